// round 1
// baseline (speedup 1.0000x reference)
#include <cuda_runtime.h>
#include <math.h>

#define B_  32
#define N_  64
#define S_  9
#define C_  128
#define CS_ 32
#define C2_ 96
#define AVGF 49.0f

// ---------------- scratch (device globals; no allocs allowed) ----------------
__device__ float g_T[B_*N_*N_*C_];     // 67 MB
__device__ float g_U[B_*N_*N_*C_];     // 67 MB
__device__ float g_y012[B_*N_*3*CS_];
__device__ float g_y34[B_*2*CS_];
__device__ float g_dvec[B_*N_*C_];
__device__ float g_rvec[B_*N_*C_];
__device__ float g_cvec[B_*N_*C_];
__device__ float g_Vrow[B_*N_*C_];
__device__ float g_Vcol[B_*N_*C_];
__device__ float g_Dd[B_*N_*C_];
__device__ float g_G[B_*C_];
__device__ float g_E[B_*C_];
__device__ float g_t[B_*C_];
__device__ float g_tr[B_*C_];
__device__ float g_dg[B_*C_];
__device__ float g_tot[B_*C_];

__device__ __forceinline__ float lrelu(float x){ return x >= 0.f ? x : 0.01f*x; }

// ---------------- eq1to2 prep: projection vectors -----------------------------
__global__ void k_prep(const float* __restrict__ scalars, const int* __restrict__ nobj,
                       const float* __restrict__ w_in) {
    int b = blockIdx.x;
    __shared__ float xs[N_][S_];
    __shared__ float ssum[S_];
    int nb = nobj[b];
    for (int idx = threadIdx.x; idx < N_*S_; idx += blockDim.x) {
        int n = idx / S_, s = idx % S_;
        xs[n][s] = (n < nb) ? scalars[(b*N_+n)*S_+s] : 0.f;
    }
    __syncthreads();
    if (threadIdx.x < S_) {
        float acc = 0.f;
        for (int n = 0; n < N_; n++) acc += xs[n][threadIdx.x];
        ssum[threadIdx.x] = acc / AVGF;
    }
    __syncthreads();
    for (int idx = threadIdx.x; idx < N_*CS_; idx += blockDim.x) {
        int n = idx / CS_, c = idx % CS_;
        float a0=0.f, a1=0.f, a2=0.f;
        #pragma unroll
        for (int s = 0; s < S_; s++) {
            float xv = xs[n][s];
            a0 += xv * w_in[(0*S_+s)*CS_+c];
            a1 += xv * w_in[(1*S_+s)*CS_+c];
            a2 += xv * w_in[(2*S_+s)*CS_+c];
        }
        g_y012[((b*N_+n)*3+0)*CS_+c] = a0;
        g_y012[((b*N_+n)*3+1)*CS_+c] = a1;
        g_y012[((b*N_+n)*3+2)*CS_+c] = a2;
    }
    if (threadIdx.x < 2*CS_) {
        int k = threadIdx.x / CS_, c = threadIdx.x % CS_;
        float a = 0.f;
        #pragma unroll
        for (int s = 0; s < S_; s++) a += ssum[s] * w_in[((3+k)*S_+s)*CS_+c];
        g_y34[(b*2+k)*CS_+c] = a;
    }
}

// ---------------- build initial T = concat(eq1to2, encoded invariants) -------
__global__ void k_init(const float* __restrict__ momenta, const int* __restrict__ nobj,
                       const float* __restrict__ w_lin, const float* __restrict__ alpha,
                       const float* __restrict__ b_in) {
    int b = blockIdx.x / N_, i = blockIdx.x % N_;
    int c = threadIdx.x; // 128
    __shared__ float pm[N_][4];
    __shared__ float dij[N_];
    __shared__ float y1s[N_][CS_];
    __shared__ float y0r[CS_], y2r[CS_], y3s[CS_], y4s[CS_];
    for (int idx = c; idx < N_*4; idx += 128) pm[idx/4][idx%4] = momenta[(b*N_)*4 + idx];
    for (int idx = c; idx < N_*CS_; idx += 128) {
        int n = idx / CS_, cs = idx % CS_;
        y1s[n][cs] = g_y012[((b*N_+n)*3+1)*CS_+cs];
    }
    if (c < CS_) {
        y0r[c] = g_y012[((b*N_+i)*3+0)*CS_+c];
        y2r[c] = g_y012[((b*N_+i)*3+2)*CS_+c];
        y3s[c] = g_y34[(b*2+0)*CS_+c];
        y4s[c] = g_y34[(b*2+1)*CS_+c];
    }
    __syncthreads();
    if (c < N_)
        dij[c] = pm[i][0]*pm[c][0] - pm[i][1]*pm[c][1] - pm[i][2]*pm[c][2] - pm[i][3]*pm[c][3];
    __syncthreads();
    int nb = nobj[b];
    float mi = (i < nb) ? 1.f : 0.f;
    float base = 0.f, wl = 0.f, al = 0.f;
    if (c < CS_) base = y0r[c] + y3s[c] + b_in[c];
    else { wl = w_lin[c-CS_]; al = alpha[c-CS_]; }
    size_t rowbase = ((size_t)(b*N_+i))*N_*C_;
    for (int j = 0; j < N_; j++) {
        float mask = mi * ((j < nb) ? 1.f : 0.f);
        float v;
        if (c < CS_) {
            v = base + y1s[j][c];
            if (j == i) v += y2r[c] + y4s[c];
            v = lrelu(v) * mask;
        } else {
            float r = dij[j] * wl;
            v = al * copysignf(log1pf(fabsf(r)), r) * mask;
        }
        g_T[rowbase + j*C_ + c] = v;
    }
}

// ---------------- MessageNet GEMM: U = lrelu(T@W + b) * mask -----------------
__global__ void k_msg(const float* __restrict__ A, const float* __restrict__ W,
                      const float* __restrict__ bias, const int* __restrict__ nobj,
                      float* __restrict__ Out) {
    extern __shared__ float sm[];
    float* As = sm;            // [64][68]
    float* Ws = sm + 64*68;    // [64][128]
    int b = blockIdx.x >> 6, i = blockIdx.x & 63;
    int tid = threadIdx.x;
    int tx = tid & 15, ty = tid >> 4;
    int r0 = ty*4, cc = tx*8;
    const float* Ablk = A + (size_t)blockIdx.x * (N_*C_);
    float acc[4][8];
    #pragma unroll
    for (int r = 0; r < 4; r++)
        #pragma unroll
        for (int u = 0; u < 8; u++) acc[r][u] = 0.f;

    for (int k0 = 0; k0 < 128; k0 += 64) {
        #pragma unroll
        for (int u = 0; u < 4; u++) {
            int f = tid + 256*u;
            int row = f >> 4, k4 = f & 15;
            *(float4*)&As[row*68 + k4*4] = *(const float4*)(Ablk + row*C_ + k0 + k4*4);
        }
        #pragma unroll
        for (int u = 0; u < 8; u++) {
            int f = tid + 256*u;
            int k = f >> 5, d4 = f & 31;
            *(float4*)&Ws[k*128 + d4*4] = *(const float4*)(W + (size_t)(k0+k)*C_ + d4*4);
        }
        __syncthreads();
        #pragma unroll 8
        for (int k = 0; k < 64; k++) {
            float a[4], bb[8];
            #pragma unroll
            for (int r = 0; r < 4; r++) a[r] = As[(r0+r)*68 + k];
            *(float4*)&bb[0] = *(float4*)&Ws[k*128 + cc];
            *(float4*)&bb[4] = *(float4*)&Ws[k*128 + cc + 4];
            #pragma unroll
            for (int r = 0; r < 4; r++)
                #pragma unroll
                for (int u = 0; u < 8; u++) acc[r][u] += a[r]*bb[u];
        }
        __syncthreads();
    }
    int nb = nobj[b];
    float mi = (i < nb) ? 1.f : 0.f;
    float bset[8];
    #pragma unroll
    for (int u = 0; u < 8; u++) bset[u] = bias[cc+u];
    float* Oblk = Out + (size_t)blockIdx.x * (N_*C_);
    #pragma unroll
    for (int r = 0; r < 4; r++) {
        int j = r0 + r;
        float mask = mi * ((j < nb) ? 1.f : 0.f);
        #pragma unroll
        for (int u = 0; u < 8; u++)
            Oblk[j*C_ + cc + u] = lrelu(acc[r][u] + bset[u]) * mask;
    }
}

// ---------------- reductions from U ------------------------------------------
__global__ void k_r1(const float* __restrict__ U) {
    int b = blockIdx.x >> 6, i = blockIdx.x & 63;
    int c = threadIdx.x;
    size_t rb = (size_t)blockIdx.x * (N_*C_);
    float rs = 0.f, cs = 0.f;
    for (int j = 0; j < N_; j++) rs += U[rb + j*C_ + c];
    for (int j = 0; j < N_; j++) cs += U[(((size_t)(b*N_+j))*N_ + i)*C_ + c];
    int o = (b*N_+i)*C_ + c;
    g_dvec[o] = U[rb + i*C_ + c];
    g_rvec[o] = rs / AVGF;
    g_cvec[o] = cs / AVGF;
}

__global__ void k_r2() {
    int b = blockIdx.x, c = threadIdx.x;
    float t = 0.f, tr = 0.f;
    for (int i = 0; i < N_; i++) {
        t  += g_rvec[(b*N_+i)*C_+c];
        tr += g_dvec[(b*N_+i)*C_+c];
    }
    g_t[b*C_+c]  = t / AVGF;
    g_tr[b*C_+c] = tr / AVGF;
}

// 9 small projections -> Vrow, Vcol, D
__global__ void k_p(const float* __restrict__ W) {
    int b = blockIdx.x >> 6, i = blockIdx.x & 63;
    int d = threadIdx.x;
    __shared__ float dv[C_], rv[C_], cv[C_];
    int o = (b*N_+i)*C_ + d;
    dv[d] = g_dvec[o]; rv[d] = g_rvec[o]; cv[d] = g_cvec[o];
    __syncthreads();
    float a = 0.f, bb = 0.f, cc = 0.f;
    for (int c = 0; c < C_; c++) {
        float dvc = dv[c], rvc = rv[c], cvc = cv[c];
        a  += dvc*W[(3*C_+c)*C_+d]  + rvc*W[(5*C_+c)*C_+d] + cvc*W[(7*C_+c)*C_+d];
        bb += dvc*W[(4*C_+c)*C_+d]  + rvc*W[(6*C_+c)*C_+d] + cvc*W[(8*C_+c)*C_+d];
        cc += dvc*W[(2*C_+c)*C_+d]  + rvc*W[(9*C_+c)*C_+d] + cvc*W[(10*C_+c)*C_+d];
    }
    g_Vrow[o] = a; g_Vcol[o] = bb; g_Dd[o] = cc;
}

// global scalar projections -> G (with eq_b), E (with eq_bd)
__global__ void k_pg(const float* __restrict__ W, const float* __restrict__ eqb,
                     const float* __restrict__ eqbd) {
    int b = blockIdx.x, d = threadIdx.x;
    __shared__ float tt[C_], tg[C_];
    tt[d] = g_t[b*C_+d]; tg[d] = g_tr[b*C_+d];
    __syncthreads();
    float g = eqb[d], e = eqbd[d];
    for (int c = 0; c < C_; c++) {
        g += tt[c]*W[(11*C_+c)*C_+d] + tg[c]*W[(13*C_+c)*C_+d];
        e += tt[c]*W[(12*C_+c)*C_+d] + tg[c]*W[(14*C_+c)*C_+d];
    }
    g_G[b*C_+d] = g; g_E[b*C_+d] = e;
}

// ---------------- Eq2to2 dual GEMM + broadcast epilogue ----------------------
__global__ void k_eq(const float* __restrict__ U, const float* __restrict__ W0,
                     const float* __restrict__ W1, const int* __restrict__ nobj,
                     float* __restrict__ Out) {
    extern __shared__ float sm[];
    float* As0 = sm;
    float* As1 = sm + 64*68;
    float* Ws0 = sm + 2*64*68;
    float* Ws1 = Ws0 + 64*128;
    int b = blockIdx.x >> 6, i = blockIdx.x & 63;
    int tid = threadIdx.x;
    int tx = tid & 15, ty = tid >> 4;
    int r0 = ty*4, cc = tx*8;
    const float* A0blk = U + (size_t)blockIdx.x * (N_*C_);
    float acc[4][8];
    #pragma unroll
    for (int r = 0; r < 4; r++)
        #pragma unroll
        for (int u = 0; u < 8; u++) acc[r][u] = 0.f;

    for (int k0 = 0; k0 < 128; k0 += 64) {
        #pragma unroll
        for (int u = 0; u < 4; u++) {
            int f = tid + 256*u;
            int row = f >> 4, k4 = f & 15;
            *(float4*)&As0[row*68 + k4*4] = *(const float4*)(A0blk + row*C_ + k0 + k4*4);
            *(float4*)&As1[row*68 + k4*4] =
                *(const float4*)(U + (((size_t)(b*N_+row))*N_ + i)*C_ + k0 + k4*4);
        }
        #pragma unroll
        for (int u = 0; u < 8; u++) {
            int f = tid + 256*u;
            int k = f >> 5, d4 = f & 31;
            *(float4*)&Ws0[k*128 + d4*4] = *(const float4*)(W0 + (size_t)(k0+k)*C_ + d4*4);
            *(float4*)&Ws1[k*128 + d4*4] = *(const float4*)(W1 + (size_t)(k0+k)*C_ + d4*4);
        }
        __syncthreads();
        #pragma unroll 4
        for (int k = 0; k < 64; k++) {
            float a0[4], a1[4], b0[8], b1[8];
            #pragma unroll
            for (int r = 0; r < 4; r++) { a0[r] = As0[(r0+r)*68 + k]; a1[r] = As1[(r0+r)*68 + k]; }
            *(float4*)&b0[0] = *(float4*)&Ws0[k*128 + cc];
            *(float4*)&b0[4] = *(float4*)&Ws0[k*128 + cc + 4];
            *(float4*)&b1[0] = *(float4*)&Ws1[k*128 + cc];
            *(float4*)&b1[4] = *(float4*)&Ws1[k*128 + cc + 4];
            #pragma unroll
            for (int r = 0; r < 4; r++)
                #pragma unroll
                for (int u = 0; u < 8; u++) acc[r][u] += a0[r]*b0[u] + a1[r]*b1[u];
        }
        __syncthreads();
    }
    int nb = nobj[b];
    float mi = (i < nb) ? 1.f : 0.f;
    float vre[8];
    #pragma unroll
    for (int u = 0; u < 8; u++)
        vre[u] = g_Vrow[(b*N_+i)*C_+cc+u] + g_G[b*C_+cc+u];
    float* Oblk = Out + (size_t)blockIdx.x * (N_*C_);
    #pragma unroll
    for (int r = 0; r < 4; r++) {
        int j = r0 + r;
        float mask = mi * ((j < nb) ? 1.f : 0.f);
        #pragma unroll
        for (int u = 0; u < 8; u++) {
            float v = acc[r][u] + vre[u] + g_Vcol[(b*N_+j)*C_+cc+u];
            if (j == i) v += g_Dd[(b*N_+i)*C_+cc+u] + g_E[b*C_+cc+u];
            Oblk[j*C_ + cc + u] = lrelu(v) * mask;
        }
    }
}

// ---------------- zero accumulators ------------------------------------------
__global__ void k_zero() {
    int idx = blockIdx.x*blockDim.x + threadIdx.x;
    if (idx < B_*C_) { g_dg[idx] = 0.f; g_tot[idx] = 0.f; }
}

// ---------------- final msg_2to0 GEMM fused with Eq2to0 reduction ------------
__global__ void k_final(const float* __restrict__ A, const float* __restrict__ W,
                        const float* __restrict__ bias, const int* __restrict__ nobj) {
    extern __shared__ float sm[];
    float* As = sm;                 // [64][68]
    float* Ws = sm + 64*68;         // [64][128]
    float* red = sm + 64*68 + 64*128;  // [16][128]
    float* dgrow = red + 16*128;       // [128]
    int b = blockIdx.x >> 6, i = blockIdx.x & 63;
    int tid = threadIdx.x;
    int tx = tid & 15, ty = tid >> 4;
    int r0 = ty*4, cc = tx*8;
    const float* Ablk = A + (size_t)blockIdx.x * (N_*C_);
    float acc[4][8];
    #pragma unroll
    for (int r = 0; r < 4; r++)
        #pragma unroll
        for (int u = 0; u < 8; u++) acc[r][u] = 0.f;

    for (int k0 = 0; k0 < 128; k0 += 64) {
        #pragma unroll
        for (int u = 0; u < 4; u++) {
            int f = tid + 256*u;
            int row = f >> 4, k4 = f & 15;
            *(float4*)&As[row*68 + k4*4] = *(const float4*)(Ablk + row*C_ + k0 + k4*4);
        }
        #pragma unroll
        for (int u = 0; u < 8; u++) {
            int f = tid + 256*u;
            int k = f >> 5, d4 = f & 31;
            *(float4*)&Ws[k*128 + d4*4] = *(const float4*)(W + (size_t)(k0+k)*C_ + d4*4);
        }
        __syncthreads();
        #pragma unroll 8
        for (int k = 0; k < 64; k++) {
            float a[4], bb[8];
            #pragma unroll
            for (int r = 0; r < 4; r++) a[r] = As[(r0+r)*68 + k];
            *(float4*)&bb[0] = *(float4*)&Ws[k*128 + cc];
            *(float4*)&bb[4] = *(float4*)&Ws[k*128 + cc + 4];
            #pragma unroll
            for (int r = 0; r < 4; r++)
                #pragma unroll
                for (int u = 0; u < 8; u++) acc[r][u] += a[r]*bb[u];
        }
        __syncthreads();
    }
    int nb = nobj[b];
    float mi = (i < nb) ? 1.f : 0.f;
    float bset[8];
    #pragma unroll
    for (int u = 0; u < 8; u++) bset[u] = bias[cc+u];
    float colsum[8];
    #pragma unroll
    for (int u = 0; u < 8; u++) colsum[u] = 0.f;
    bool hasdiag = ((i >> 2) == ty);
    float diagval[8];
    #pragma unroll
    for (int u = 0; u < 8; u++) diagval[u] = 0.f;
    #pragma unroll
    for (int r = 0; r < 4; r++) {
        int j = r0 + r;
        float mask = mi * ((j < nb) ? 1.f : 0.f);
        #pragma unroll
        for (int u = 0; u < 8; u++) {
            float v = lrelu(acc[r][u] + bset[u]) * mask;
            colsum[u] += v;
            if (hasdiag && j == i) diagval[u] = v;
        }
    }
    #pragma unroll
    for (int u = 0; u < 8; u++) red[ty*128 + cc + u] = colsum[u];
    if (hasdiag)
        #pragma unroll
        for (int u = 0; u < 8; u++) dgrow[cc + u] = diagval[u];
    __syncthreads();
    if (tid < 128) {
        float s = 0.f;
        #pragma unroll
        for (int q = 0; q < 16; q++) s += red[q*128 + tid];
        atomicAdd(&g_tot[b*C_ + tid], s);
        atomicAdd(&g_dg[b*C_ + tid], dgrow[tid]);
    }
}

// ---------------- output head ------------------------------------------------
__global__ void k_out(const float* __restrict__ w20, const float* __restrict__ b20,
                      const float* __restrict__ wmlp, const float* __restrict__ bmlp,
                      float* __restrict__ out) {
    int b = blockIdx.x, d = threadIdx.x;
    __shared__ float a0[C_], a1[C_], act[C_];
    a0[d] = lrelu(g_dg[b*C_+d] / AVGF);
    a1[d] = lrelu(g_tot[b*C_+d] / (AVGF*AVGF));
    __syncthreads();
    float a = b20[d];
    for (int c = 0; c < C_; c++)
        a += a0[c]*w20[c*C_+d] + a1[c]*w20[(C_+c)*C_+d];
    act[d] = a;
    __syncthreads();
    if (d < 2) {
        float o = bmlp[d];
        for (int k = 0; k < C_; k++) o += act[k]*wmlp[k*2+d];
        out[b*2+d] = o;
    }
}

// ---------------- host -------------------------------------------------------
extern "C" void kernel_launch(void* const* d_in, const int* in_sizes, int n_in,
                              void* d_out, int out_size) {
    const float *momenta=0, *scalars=0, *w_lin=0, *alpha=0, *w_in=0, *b_in=0;
    const int* nobj=0;
    const float *msgw[4], *msgb[4], *eqw[4], *eqb[4], *eqbd[4];
    const float *wm0=0, *bm0=0, *w20=0, *b20=0, *wmlp=0, *bmlp=0;

    if (n_in >= 33 && in_sizes[0] == 8192) {
        // insertion order (setup_inputs dict order), tuples flattened in sequence
        momenta = (const float*)d_in[0];
        scalars = (const float*)d_in[1];
        nobj    = (const int*)  d_in[2];
        w_lin   = (const float*)d_in[3];
        alpha   = (const float*)d_in[4];
        w_in    = (const float*)d_in[5];
        b_in    = (const float*)d_in[6];
        for (int l = 0; l < 4; l++) {
            msgw[l] = (const float*)d_in[7+l];
            msgb[l] = (const float*)d_in[11+l];
            eqw[l]  = (const float*)d_in[15+l];
            eqb[l]  = (const float*)d_in[19+l];
            eqbd[l] = (const float*)d_in[23+l];
        }
        wm0  = (const float*)d_in[27];
        bm0  = (const float*)d_in[28];
        w20  = (const float*)d_in[29];
        b20  = (const float*)d_in[30];
        wmlp = (const float*)d_in[31];
        bmlp = (const float*)d_in[32];
    } else if (n_in >= 33) {
        // alphabetical pytree key order
        alpha = (const float*)d_in[0];
        b20   = (const float*)d_in[1];
        b_in  = (const float*)d_in[2];
        bm0   = (const float*)d_in[3];
        bmlp  = (const float*)d_in[4];
        for (int l = 0; l < 4; l++) {
            eqb[l]  = (const float*)d_in[5+l];
            eqbd[l] = (const float*)d_in[9+l];
            eqw[l]  = (const float*)d_in[13+l];
            msgb[l] = (const float*)d_in[18+l];
            msgw[l] = (const float*)d_in[22+l];
        }
        momenta = (const float*)d_in[17];
        nobj    = (const int*)  d_in[26];
        scalars = (const float*)d_in[27];
        w20     = (const float*)d_in[28];
        w_in    = (const float*)d_in[29];
        w_lin   = (const float*)d_in[30];
        wm0     = (const float*)d_in[31];
        wmlp    = (const float*)d_in[32];
    } else {
        // insertion order with tuples concatenated into single arrays (18 inputs)
        momenta = (const float*)d_in[0];
        scalars = (const float*)d_in[1];
        nobj    = (const int*)  d_in[2];
        w_lin   = (const float*)d_in[3];
        alpha   = (const float*)d_in[4];
        w_in    = (const float*)d_in[5];
        b_in    = (const float*)d_in[6];
        for (int l = 0; l < 4; l++) {
            msgw[l] = (const float*)d_in[7]  + (size_t)l*C_*C_;
            msgb[l] = (const float*)d_in[8]  + (size_t)l*C_;
            eqw[l]  = (const float*)d_in[9]  + (size_t)l*15*C_*C_;
            eqb[l]  = (const float*)d_in[10] + (size_t)l*C_;
            eqbd[l] = (const float*)d_in[11] + (size_t)l*C_;
        }
        wm0  = (const float*)d_in[12];
        bm0  = (const float*)d_in[13];
        w20  = (const float*)d_in[14];
        b20  = (const float*)d_in[15];
        wmlp = (const float*)d_in[16];
        bmlp = (const float*)d_in[17];
    }

    const int MSG_SMEM   = (64*68 + 64*128) * 4;                    // 50176 B
    const int EQ_SMEM    = (2*64*68 + 2*64*128) * 4;                // 100352 B
    const int FINAL_SMEM = (64*68 + 64*128 + 16*128 + 128) * 4;     // 58880 B
    cudaFuncSetAttribute(k_msg,   cudaFuncAttributeMaxDynamicSharedMemorySize, MSG_SMEM);
    cudaFuncSetAttribute(k_eq,    cudaFuncAttributeMaxDynamicSharedMemorySize, EQ_SMEM);
    cudaFuncSetAttribute(k_final, cudaFuncAttributeMaxDynamicSharedMemorySize, FINAL_SMEM);

    float *Tp = 0, *Up = 0;
    cudaGetSymbolAddress((void**)&Tp, g_T);
    cudaGetSymbolAddress((void**)&Up, g_U);

    k_prep<<<B_, 256>>>(scalars, nobj, w_in);
    k_init<<<B_*N_, 128>>>(momenta, nobj, w_lin, alpha, b_in);

    for (int l = 0; l < 4; l++) {
        k_msg<<<B_*N_, 256, MSG_SMEM>>>(Tp, msgw[l], msgb[l], nobj, Up);
        k_r1<<<B_*N_, 128>>>(Up);
        k_r2<<<B_, 128>>>();
        k_p<<<B_*N_, 128>>>(eqw[l]);
        k_pg<<<B_, 128>>>(eqw[l], eqb[l], eqbd[l]);
        k_eq<<<B_*N_, 256, EQ_SMEM>>>(Up, eqw[l], eqw[l] + C_*C_, nobj, Tp);
    }

    k_zero<<<(B_*C_ + 255)/256, 256>>>();
    k_final<<<B_*N_, 256, FINAL_SMEM>>>(Tp, wm0, bm0, nobj);
    k_out<<<B_, 128>>>(w20, b20, wmlp, bmlp, (float*)d_out);
}

// round 2
// speedup vs baseline: 1.0009x; 1.0009x over previous
#include <cuda_runtime.h>
#include <math.h>

#define B_  32
#define N_  64
#define S_  9
#define C_  128
#define CS_ 32
#define C2_ 96
#define AVGF 49.0f

// ---------------- scratch (device globals; no allocs allowed) ----------------
__device__ float g_T[B_*N_*N_*C_];     // 67 MB
__device__ float g_U[B_*N_*N_*C_];     // 67 MB
__device__ float g_y012[B_*N_*3*CS_];
__device__ float g_y34[B_*2*CS_];
__device__ float g_dvec[B_*N_*C_];
__device__ float g_rvec[B_*N_*C_];
__device__ float g_cvec[B_*N_*C_];
__device__ float g_Vrow[B_*N_*C_];
__device__ float g_Vcol[B_*N_*C_];
__device__ float g_Dd[B_*N_*C_];
__device__ float g_G[B_*C_];
__device__ float g_E[B_*C_];
__device__ float g_t[B_*C_];
__device__ float g_tr[B_*C_];
__device__ float g_dg[B_*C_];
__device__ float g_tot[B_*C_];

__device__ __forceinline__ float lrelu(float x){ return x >= 0.f ? x : 0.01f*x; }

// ---------------- eq1to2 prep: projection vectors -----------------------------
__global__ void k_prep(const float* __restrict__ scalars, const int* __restrict__ nobj,
                       const float* __restrict__ w_in) {
    int b = blockIdx.x;
    __shared__ float xs[N_][S_];
    __shared__ float ssum[S_];
    int nb = nobj[b];
    for (int idx = threadIdx.x; idx < N_*S_; idx += blockDim.x) {
        int n = idx / S_, s = idx % S_;
        xs[n][s] = (n < nb) ? scalars[(b*N_+n)*S_+s] : 0.f;
    }
    __syncthreads();
    if (threadIdx.x < S_) {
        float acc = 0.f;
        for (int n = 0; n < N_; n++) acc += xs[n][threadIdx.x];
        ssum[threadIdx.x] = acc / AVGF;
    }
    __syncthreads();
    for (int idx = threadIdx.x; idx < N_*CS_; idx += blockDim.x) {
        int n = idx / CS_, c = idx % CS_;
        float a0=0.f, a1=0.f, a2=0.f;
        #pragma unroll
        for (int s = 0; s < S_; s++) {
            float xv = xs[n][s];
            a0 += xv * w_in[(0*S_+s)*CS_+c];
            a1 += xv * w_in[(1*S_+s)*CS_+c];
            a2 += xv * w_in[(2*S_+s)*CS_+c];
        }
        g_y012[((b*N_+n)*3+0)*CS_+c] = a0;
        g_y012[((b*N_+n)*3+1)*CS_+c] = a1;
        g_y012[((b*N_+n)*3+2)*CS_+c] = a2;
    }
    if (threadIdx.x < 2*CS_) {
        int k = threadIdx.x / CS_, c = threadIdx.x % CS_;
        float a = 0.f;
        #pragma unroll
        for (int s = 0; s < S_; s++) a += ssum[s] * w_in[((3+k)*S_+s)*CS_+c];
        g_y34[(b*2+k)*CS_+c] = a;
    }
}

// ---------------- build initial T = concat(eq1to2, encoded invariants) -------
__global__ void k_init(const float* __restrict__ momenta, const int* __restrict__ nobj,
                       const float* __restrict__ w_lin, const float* __restrict__ alpha,
                       const float* __restrict__ b_in) {
    int b = blockIdx.x / N_, i = blockIdx.x % N_;
    int c = threadIdx.x; // 128
    __shared__ float pm[N_][4];
    __shared__ float dij[N_];
    __shared__ float y1s[N_][CS_];
    __shared__ float y0r[CS_], y2r[CS_], y3s[CS_], y4s[CS_];
    for (int idx = c; idx < N_*4; idx += 128) pm[idx/4][idx%4] = momenta[(b*N_)*4 + idx];
    for (int idx = c; idx < N_*CS_; idx += 128) {
        int n = idx / CS_, cs = idx % CS_;
        y1s[n][cs] = g_y012[((b*N_+n)*3+1)*CS_+cs];
    }
    if (c < CS_) {
        y0r[c] = g_y012[((b*N_+i)*3+0)*CS_+c];
        y2r[c] = g_y012[((b*N_+i)*3+2)*CS_+c];
        y3s[c] = g_y34[(b*2+0)*CS_+c];
        y4s[c] = g_y34[(b*2+1)*CS_+c];
    }
    __syncthreads();
    if (c < N_)
        dij[c] = pm[i][0]*pm[c][0] - pm[i][1]*pm[c][1] - pm[i][2]*pm[c][2] - pm[i][3]*pm[c][3];
    __syncthreads();
    int nb = nobj[b];
    float mi = (i < nb) ? 1.f : 0.f;
    float base = 0.f, wl = 0.f, al = 0.f;
    if (c < CS_) base = y0r[c] + y3s[c] + b_in[c];
    else { wl = w_lin[c-CS_]; al = alpha[c-CS_]; }
    size_t rowbase = ((size_t)(b*N_+i))*N_*C_;
    for (int j = 0; j < N_; j++) {
        float mask = mi * ((j < nb) ? 1.f : 0.f);
        float v;
        if (c < CS_) {
            v = base + y1s[j][c];
            if (j == i) v += y2r[c] + y4s[c];
            v = lrelu(v) * mask;
        } else {
            float r = dij[j] * wl;
            v = al * copysignf(log1pf(fabsf(r)), r) * mask;
        }
        g_T[rowbase + j*C_ + c] = v;
    }
}

// ---------------- MessageNet GEMM: U = lrelu(T@W + b) * mask -----------------
__global__ void k_msg(const float* __restrict__ A, const float* __restrict__ W,
                      const float* __restrict__ bias, const int* __restrict__ nobj,
                      float* __restrict__ Out) {
    extern __shared__ float sm[];
    float* As = sm;            // [64][68]
    float* Ws = sm + 64*68;    // [64][128]
    int b = blockIdx.x >> 6, i = blockIdx.x & 63;
    int tid = threadIdx.x;
    int tx = tid & 15, ty = tid >> 4;
    int r0 = ty*4, cc = tx*8;
    const float* Ablk = A + (size_t)blockIdx.x * (N_*C_);
    float acc[4][8];
    #pragma unroll
    for (int r = 0; r < 4; r++)
        #pragma unroll
        for (int u = 0; u < 8; u++) acc[r][u] = 0.f;

    for (int k0 = 0; k0 < 128; k0 += 64) {
        #pragma unroll
        for (int u = 0; u < 4; u++) {
            int f = tid + 256*u;
            int row = f >> 4, k4 = f & 15;
            *(float4*)&As[row*68 + k4*4] = *(const float4*)(Ablk + row*C_ + k0 + k4*4);
        }
        #pragma unroll
        for (int u = 0; u < 8; u++) {
            int f = tid + 256*u;
            int k = f >> 5, d4 = f & 31;
            *(float4*)&Ws[k*128 + d4*4] = *(const float4*)(W + (size_t)(k0+k)*C_ + d4*4);
        }
        __syncthreads();
        #pragma unroll 8
        for (int k = 0; k < 64; k++) {
            float a[4], bb[8];
            #pragma unroll
            for (int r = 0; r < 4; r++) a[r] = As[(r0+r)*68 + k];
            *(float4*)&bb[0] = *(float4*)&Ws[k*128 + cc];
            *(float4*)&bb[4] = *(float4*)&Ws[k*128 + cc + 4];
            #pragma unroll
            for (int r = 0; r < 4; r++)
                #pragma unroll
                for (int u = 0; u < 8; u++) acc[r][u] += a[r]*bb[u];
        }
        __syncthreads();
    }
    int nb = nobj[b];
    float mi = (i < nb) ? 1.f : 0.f;
    float bset[8];
    #pragma unroll
    for (int u = 0; u < 8; u++) bset[u] = bias[cc+u];
    float* Oblk = Out + (size_t)blockIdx.x * (N_*C_);
    #pragma unroll
    for (int r = 0; r < 4; r++) {
        int j = r0 + r;
        float mask = mi * ((j < nb) ? 1.f : 0.f);
        #pragma unroll
        for (int u = 0; u < 8; u++)
            Oblk[j*C_ + cc + u] = lrelu(acc[r][u] + bset[u]) * mask;
    }
}

// ---------------- reductions from U ------------------------------------------
__global__ void k_r1(const float* __restrict__ U) {
    int b = blockIdx.x >> 6, i = blockIdx.x & 63;
    int c = threadIdx.x;
    size_t rb = (size_t)blockIdx.x * (N_*C_);
    float rs = 0.f, cs = 0.f;
    for (int j = 0; j < N_; j++) rs += U[rb + j*C_ + c];
    for (int j = 0; j < N_; j++) cs += U[(((size_t)(b*N_+j))*N_ + i)*C_ + c];
    int o = (b*N_+i)*C_ + c;
    g_dvec[o] = U[rb + i*C_ + c];
    g_rvec[o] = rs / AVGF;
    g_cvec[o] = cs / AVGF;
}

__global__ void k_r2() {
    int b = blockIdx.x, c = threadIdx.x;
    float t = 0.f, tr = 0.f;
    for (int i = 0; i < N_; i++) {
        t  += g_rvec[(b*N_+i)*C_+c];
        tr += g_dvec[(b*N_+i)*C_+c];
    }
    g_t[b*C_+c]  = t / AVGF;
    g_tr[b*C_+c] = tr / AVGF;
}

// 9 small projections -> Vrow, Vcol, D
__global__ void k_p(const float* __restrict__ W) {
    int b = blockIdx.x >> 6, i = blockIdx.x & 63;
    int d = threadIdx.x;
    __shared__ float dv[C_], rv[C_], cv[C_];
    int o = (b*N_+i)*C_ + d;
    dv[d] = g_dvec[o]; rv[d] = g_rvec[o]; cv[d] = g_cvec[o];
    __syncthreads();
    float a = 0.f, bb = 0.f, cc = 0.f;
    for (int c = 0; c < C_; c++) {
        float dvc = dv[c], rvc = rv[c], cvc = cv[c];
        a  += dvc*W[(3*C_+c)*C_+d]  + rvc*W[(5*C_+c)*C_+d] + cvc*W[(7*C_+c)*C_+d];
        bb += dvc*W[(4*C_+c)*C_+d]  + rvc*W[(6*C_+c)*C_+d] + cvc*W[(8*C_+c)*C_+d];
        cc += dvc*W[(2*C_+c)*C_+d]  + rvc*W[(9*C_+c)*C_+d] + cvc*W[(10*C_+c)*C_+d];
    }
    g_Vrow[o] = a; g_Vcol[o] = bb; g_Dd[o] = cc;
}

// global scalar projections -> G (with eq_b), E (with eq_bd)
__global__ void k_pg(const float* __restrict__ W, const float* __restrict__ eqb,
                     const float* __restrict__ eqbd) {
    int b = blockIdx.x, d = threadIdx.x;
    __shared__ float tt[C_], tg[C_];
    tt[d] = g_t[b*C_+d]; tg[d] = g_tr[b*C_+d];
    __syncthreads();
    float g = eqb[d], e = eqbd[d];
    for (int c = 0; c < C_; c++) {
        g += tt[c]*W[(11*C_+c)*C_+d] + tg[c]*W[(13*C_+c)*C_+d];
        e += tt[c]*W[(12*C_+c)*C_+d] + tg[c]*W[(14*C_+c)*C_+d];
    }
    g_G[b*C_+d] = g; g_E[b*C_+d] = e;
}

// ---------------- Eq2to2 dual GEMM + broadcast epilogue ----------------------
__global__ void k_eq(const float* __restrict__ U, const float* __restrict__ W0,
                     const float* __restrict__ W1, const int* __restrict__ nobj,
                     float* __restrict__ Out) {
    extern __shared__ float sm[];
    float* As0 = sm;
    float* As1 = sm + 64*68;
    float* Ws0 = sm + 2*64*68;
    float* Ws1 = Ws0 + 64*128;
    int b = blockIdx.x >> 6, i = blockIdx.x & 63;
    int tid = threadIdx.x;
    int tx = tid & 15, ty = tid >> 4;
    int r0 = ty*4, cc = tx*8;
    const float* A0blk = U + (size_t)blockIdx.x * (N_*C_);
    float acc[4][8];
    #pragma unroll
    for (int r = 0; r < 4; r++)
        #pragma unroll
        for (int u = 0; u < 8; u++) acc[r][u] = 0.f;

    for (int k0 = 0; k0 < 128; k0 += 64) {
        #pragma unroll
        for (int u = 0; u < 4; u++) {
            int f = tid + 256*u;
            int row = f >> 4, k4 = f & 15;
            *(float4*)&As0[row*68 + k4*4] = *(const float4*)(A0blk + row*C_ + k0 + k4*4);
            *(float4*)&As1[row*68 + k4*4] =
                *(const float4*)(U + (((size_t)(b*N_+row))*N_ + i)*C_ + k0 + k4*4);
        }
        #pragma unroll
        for (int u = 0; u < 8; u++) {
            int f = tid + 256*u;
            int k = f >> 5, d4 = f & 31;
            *(float4*)&Ws0[k*128 + d4*4] = *(const float4*)(W0 + (size_t)(k0+k)*C_ + d4*4);
            *(float4*)&Ws1[k*128 + d4*4] = *(const float4*)(W1 + (size_t)(k0+k)*C_ + d4*4);
        }
        __syncthreads();
        #pragma unroll 4
        for (int k = 0; k < 64; k++) {
            float a0[4], a1[4], b0[8], b1[8];
            #pragma unroll
            for (int r = 0; r < 4; r++) { a0[r] = As0[(r0+r)*68 + k]; a1[r] = As1[(r0+r)*68 + k]; }
            *(float4*)&b0[0] = *(float4*)&Ws0[k*128 + cc];
            *(float4*)&b0[4] = *(float4*)&Ws0[k*128 + cc + 4];
            *(float4*)&b1[0] = *(float4*)&Ws1[k*128 + cc];
            *(float4*)&b1[4] = *(float4*)&Ws1[k*128 + cc + 4];
            #pragma unroll
            for (int r = 0; r < 4; r++)
                #pragma unroll
                for (int u = 0; u < 8; u++) acc[r][u] += a0[r]*b0[u] + a1[r]*b1[u];
        }
        __syncthreads();
    }
    int nb = nobj[b];
    float mi = (i < nb) ? 1.f : 0.f;
    float vre[8];
    #pragma unroll
    for (int u = 0; u < 8; u++)
        vre[u] = g_Vrow[(b*N_+i)*C_+cc+u] + g_G[b*C_+cc+u];
    float* Oblk = Out + (size_t)blockIdx.x * (N_*C_);
    #pragma unroll
    for (int r = 0; r < 4; r++) {
        int j = r0 + r;
        float mask = mi * ((j < nb) ? 1.f : 0.f);
        #pragma unroll
        for (int u = 0; u < 8; u++) {
            float v = acc[r][u] + vre[u] + g_Vcol[(b*N_+j)*C_+cc+u];
            if (j == i) v += g_Dd[(b*N_+i)*C_+cc+u] + g_E[b*C_+cc+u];
            Oblk[j*C_ + cc + u] = lrelu(v) * mask;
        }
    }
}

// ---------------- zero accumulators ------------------------------------------
__global__ void k_zero() {
    int idx = blockIdx.x*blockDim.x + threadIdx.x;
    if (idx < B_*C_) { g_dg[idx] = 0.f; g_tot[idx] = 0.f; }
}

// ---------------- final msg_2to0 GEMM fused with Eq2to0 reduction ------------
__global__ void k_final(const float* __restrict__ A, const float* __restrict__ W,
                        const float* __restrict__ bias, const int* __restrict__ nobj) {
    extern __shared__ float sm[];
    float* As = sm;                 // [64][68]
    float* Ws = sm + 64*68;         // [64][128]
    float* red = sm + 64*68 + 64*128;  // [16][128]
    float* dgrow = red + 16*128;       // [128]
    int b = blockIdx.x >> 6, i = blockIdx.x & 63;
    int tid = threadIdx.x;
    int tx = tid & 15, ty = tid >> 4;
    int r0 = ty*4, cc = tx*8;
    const float* Ablk = A + (size_t)blockIdx.x * (N_*C_);
    float acc[4][8];
    #pragma unroll
    for (int r = 0; r < 4; r++)
        #pragma unroll
        for (int u = 0; u < 8; u++) acc[r][u] = 0.f;

    for (int k0 = 0; k0 < 128; k0 += 64) {
        #pragma unroll
        for (int u = 0; u < 4; u++) {
            int f = tid + 256*u;
            int row = f >> 4, k4 = f & 15;
            *(float4*)&As[row*68 + k4*4] = *(const float4*)(Ablk + row*C_ + k0 + k4*4);
        }
        #pragma unroll
        for (int u = 0; u < 8; u++) {
            int f = tid + 256*u;
            int k = f >> 5, d4 = f & 31;
            *(float4*)&Ws[k*128 + d4*4] = *(const float4*)(W + (size_t)(k0+k)*C_ + d4*4);
        }
        __syncthreads();
        #pragma unroll 8
        for (int k = 0; k < 64; k++) {
            float a[4], bb[8];
            #pragma unroll
            for (int r = 0; r < 4; r++) a[r] = As[(r0+r)*68 + k];
            *(float4*)&bb[0] = *(float4*)&Ws[k*128 + cc];
            *(float4*)&bb[4] = *(float4*)&Ws[k*128 + cc + 4];
            #pragma unroll
            for (int r = 0; r < 4; r++)
                #pragma unroll
                for (int u = 0; u < 8; u++) acc[r][u] += a[r]*bb[u];
        }
        __syncthreads();
    }
    int nb = nobj[b];
    float mi = (i < nb) ? 1.f : 0.f;
    float bset[8];
    #pragma unroll
    for (int u = 0; u < 8; u++) bset[u] = bias[cc+u];
    float colsum[8];
    #pragma unroll
    for (int u = 0; u < 8; u++) colsum[u] = 0.f;
    bool hasdiag = ((i >> 2) == ty);
    float diagval[8];
    #pragma unroll
    for (int u = 0; u < 8; u++) diagval[u] = 0.f;
    #pragma unroll
    for (int r = 0; r < 4; r++) {
        int j = r0 + r;
        float mask = mi * ((j < nb) ? 1.f : 0.f);
        #pragma unroll
        for (int u = 0; u < 8; u++) {
            float v = lrelu(acc[r][u] + bset[u]) * mask;
            colsum[u] += v;
            if (hasdiag && j == i) diagval[u] = v;
        }
    }
    #pragma unroll
    for (int u = 0; u < 8; u++) red[ty*128 + cc + u] = colsum[u];
    if (hasdiag)
        #pragma unroll
        for (int u = 0; u < 8; u++) dgrow[cc + u] = diagval[u];
    __syncthreads();
    if (tid < 128) {
        float s = 0.f;
        #pragma unroll
        for (int q = 0; q < 16; q++) s += red[q*128 + tid];
        atomicAdd(&g_tot[b*C_ + tid], s);
        atomicAdd(&g_dg[b*C_ + tid], dgrow[tid]);
    }
}

// ---------------- output head ------------------------------------------------
__global__ void k_out(const float* __restrict__ w20, const float* __restrict__ b20,
                      const float* __restrict__ wmlp, const float* __restrict__ bmlp,
                      float* __restrict__ out) {
    int b = blockIdx.x, d = threadIdx.x;
    __shared__ float a0[C_], a1[C_], act[C_];
    a0[d] = lrelu(g_dg[b*C_+d] / AVGF);
    a1[d] = lrelu(g_tot[b*C_+d] / (AVGF*AVGF));
    __syncthreads();
    float a = b20[d];
    for (int c = 0; c < C_; c++)
        a += a0[c]*w20[c*C_+d] + a1[c]*w20[(C_+c)*C_+d];
    act[d] = a;
    __syncthreads();
    if (d < 2) {
        float o = bmlp[d];
        for (int k = 0; k < C_; k++) o += act[k]*wmlp[k*2+d];
        out[b*2+d] = o;
    }
}

// ---------------- host -------------------------------------------------------
extern "C" void kernel_launch(void* const* d_in, const int* in_sizes, int n_in,
                              void* d_out, int out_size) {
    const float *momenta=0, *scalars=0, *w_lin=0, *alpha=0, *w_in=0, *b_in=0;
    const int* nobj=0;
    const float *msgw[4], *msgb[4], *eqw[4], *eqb[4], *eqbd[4];
    const float *wm0=0, *bm0=0, *w20=0, *b20=0, *wmlp=0, *bmlp=0;

    if (n_in >= 33 && in_sizes[0] == 8192) {
        // insertion order (setup_inputs dict order), tuples flattened in sequence
        momenta = (const float*)d_in[0];
        scalars = (const float*)d_in[1];
        nobj    = (const int*)  d_in[2];
        w_lin   = (const float*)d_in[3];
        alpha   = (const float*)d_in[4];
        w_in    = (const float*)d_in[5];
        b_in    = (const float*)d_in[6];
        for (int l = 0; l < 4; l++) {
            msgw[l] = (const float*)d_in[7+l];
            msgb[l] = (const float*)d_in[11+l];
            eqw[l]  = (const float*)d_in[15+l];
            eqb[l]  = (const float*)d_in[19+l];
            eqbd[l] = (const float*)d_in[23+l];
        }
        wm0  = (const float*)d_in[27];
        bm0  = (const float*)d_in[28];
        w20  = (const float*)d_in[29];
        b20  = (const float*)d_in[30];
        wmlp = (const float*)d_in[31];
        bmlp = (const float*)d_in[32];
    } else if (n_in >= 33) {
        // alphabetical pytree key order
        alpha = (const float*)d_in[0];
        b20   = (const float*)d_in[1];
        b_in  = (const float*)d_in[2];
        bm0   = (const float*)d_in[3];
        bmlp  = (const float*)d_in[4];
        for (int l = 0; l < 4; l++) {
            eqb[l]  = (const float*)d_in[5+l];
            eqbd[l] = (const float*)d_in[9+l];
            eqw[l]  = (const float*)d_in[13+l];
            msgb[l] = (const float*)d_in[18+l];
            msgw[l] = (const float*)d_in[22+l];
        }
        momenta = (const float*)d_in[17];
        nobj    = (const int*)  d_in[26];
        scalars = (const float*)d_in[27];
        w20     = (const float*)d_in[28];
        w_in    = (const float*)d_in[29];
        w_lin   = (const float*)d_in[30];
        wm0     = (const float*)d_in[31];
        wmlp    = (const float*)d_in[32];
    } else {
        // insertion order with tuples concatenated into single arrays (18 inputs)
        momenta = (const float*)d_in[0];
        scalars = (const float*)d_in[1];
        nobj    = (const int*)  d_in[2];
        w_lin   = (const float*)d_in[3];
        alpha   = (const float*)d_in[4];
        w_in    = (const float*)d_in[5];
        b_in    = (const float*)d_in[6];
        for (int l = 0; l < 4; l++) {
            msgw[l] = (const float*)d_in[7]  + (size_t)l*C_*C_;
            msgb[l] = (const float*)d_in[8]  + (size_t)l*C_;
            eqw[l]  = (const float*)d_in[9]  + (size_t)l*15*C_*C_;
            eqb[l]  = (const float*)d_in[10] + (size_t)l*C_;
            eqbd[l] = (const float*)d_in[11] + (size_t)l*C_;
        }
        wm0  = (const float*)d_in[12];
        bm0  = (const float*)d_in[13];
        w20  = (const float*)d_in[14];
        b20  = (const float*)d_in[15];
        wmlp = (const float*)d_in[16];
        bmlp = (const float*)d_in[17];
    }

    const int MSG_SMEM   = (64*68 + 64*128) * 4;                    // 50176 B
    const int EQ_SMEM    = (2*64*68 + 2*64*128) * 4;                // 100352 B
    const int FINAL_SMEM = (64*68 + 64*128 + 16*128 + 128) * 4;     // 58880 B
    cudaFuncSetAttribute(k_msg,   cudaFuncAttributeMaxDynamicSharedMemorySize, MSG_SMEM);
    cudaFuncSetAttribute(k_eq,    cudaFuncAttributeMaxDynamicSharedMemorySize, EQ_SMEM);
    cudaFuncSetAttribute(k_final, cudaFuncAttributeMaxDynamicSharedMemorySize, FINAL_SMEM);

    float *Tp = 0, *Up = 0;
    cudaGetSymbolAddress((void**)&Tp, g_T);
    cudaGetSymbolAddress((void**)&Up, g_U);

    k_prep<<<B_, 256>>>(scalars, nobj, w_in);
    k_init<<<B_*N_, 128>>>(momenta, nobj, w_lin, alpha, b_in);

    for (int l = 0; l < 4; l++) {
        k_msg<<<B_*N_, 256, MSG_SMEM>>>(Tp, msgw[l], msgb[l], nobj, Up);
        k_r1<<<B_*N_, 128>>>(Up);
        k_r2<<<B_, 128>>>();
        k_p<<<B_*N_, 128>>>(eqw[l]);
        k_pg<<<B_, 128>>>(eqw[l], eqb[l], eqbd[l]);
        k_eq<<<B_*N_, 256, EQ_SMEM>>>(Up, eqw[l], eqw[l] + C_*C_, nobj, Tp);
    }

    k_zero<<<(B_*C_ + 255)/256, 256>>>();
    k_final<<<B_*N_, 256, FINAL_SMEM>>>(Tp, wm0, bm0, nobj);
    k_out<<<B_, 128>>>(w20, b20, wmlp, bmlp, (float*)d_out);
}

// round 5
// speedup vs baseline: 1.8582x; 1.8564x over previous
#include <cuda_runtime.h>
#include <cuda_bf16.h>
#include <math.h>
#include <stdint.h>

#define B_  32
#define N_  64
#define S_  9
#define C_  128
#define CS_ 32
#define AVGF 49.0f
#define TILES (B_*32)   // 1024 tiles of 128 rows; tile=(b, i-pair), row=(i&1)*64+j

// ---------------- device scratch ----------------
__device__ float g_T[B_*N_*N_*C_];
__device__ float g_U[B_*N_*N_*C_];
__device__ float g_Z0[B_*N_*N_*C_];
__device__ float g_Z1[B_*N_*N_*C_];
__device__ __nv_bfloat16 g_WmsgHi[4*16384], g_WmsgLo[4*16384];
__device__ __nv_bfloat16 g_WeqHi[8*16384],  g_WeqLo[8*16384];   // [l][which][n][k]
__device__ __nv_bfloat16 g_WfinHi[16384],   g_WfinLo[16384];
__device__ float g_y012[B_*N_*3*CS_];
__device__ float g_y34[B_*2*CS_];
__device__ float g_dvec[B_*N_*C_];
__device__ float g_rvec[B_*N_*C_];
__device__ float g_cvec[B_*N_*C_];
__device__ float g_Vrow[B_*N_*C_];
__device__ float g_Vcol[B_*N_*C_];
__device__ float g_Dd[B_*N_*C_];
__device__ float g_G[B_*C_];
__device__ float g_E[B_*C_];
__device__ float g_t[B_*C_];
__device__ float g_tr[B_*C_];
__device__ float g_dg[B_*C_];
__device__ float g_tot[B_*C_];

__device__ __forceinline__ float lrelu(float x){ return x >= 0.f ? x : 0.01f*x; }
__device__ __forceinline__ uint32_t smem_u32(const void* p) {
    uint32_t a;
    asm("{ .reg .u64 t; cvta.to.shared.u64 t, %1; cvt.u32.u64 %0, t; }" : "=r"(a) : "l"(p));
    return a;
}
__device__ __forceinline__ void split2(float v, __nv_bfloat16& h, __nv_bfloat16& l) {
    h = __float2bfloat16(v);
    l = __float2bfloat16(v - __bfloat162float(h));
}
__device__ __forceinline__ void ldmx4(uint32_t a, uint32_t& r0, uint32_t& r1, uint32_t& r2, uint32_t& r3) {
    asm volatile("ldmatrix.sync.aligned.m8n8.x4.shared.b16 {%0,%1,%2,%3}, [%4];"
                 : "=r"(r0), "=r"(r1), "=r"(r2), "=r"(r3) : "r"(a));
}
__device__ __forceinline__ void mma16816(float* c, const uint32_t* a, uint32_t b0, uint32_t b1) {
    asm volatile("mma.sync.aligned.m16n8k16.row.col.f32.bf16.bf16.f32 "
                 "{%0,%1,%2,%3}, {%4,%5,%6,%7}, {%8,%9}, {%0,%1,%2,%3};"
                 : "+f"(c[0]), "+f"(c[1]), "+f"(c[2]), "+f"(c[3])
                 : "r"(a[0]), "r"(a[1]), "r"(a[2]), "r"(a[3]), "r"(b0), "r"(b1));
}

// smem geometry (bytes)
#define APAD 136   // elements; 272B row stride
#define BPAD 144   // elements; 288B n stride
#define AH_OFF 0
#define AL_OFF 34816
#define BH_OFF 69632
#define BL_OFF 106496
#define SM_GEMM 143360

// ---------------- weight split: col-major [n][k] bf16 hi/lo ----------------
__global__ void k_wsplit(const float* __restrict__ m0, const float* __restrict__ m1,
                         const float* __restrict__ m2, const float* __restrict__ m3,
                         const float* __restrict__ e0, const float* __restrict__ e1,
                         const float* __restrict__ e2, const float* __restrict__ e3,
                         const float* __restrict__ wfin) {
    int blk = blockIdx.x, tid = threadIdx.x;
    const float* W; __nv_bfloat16 *Hi, *Lo;
    if (blk < 4) {
        W = (blk==0)?m0:(blk==1)?m1:(blk==2)?m2:m3;
        Hi = g_WmsgHi + blk*16384; Lo = g_WmsgLo + blk*16384;
    } else if (blk < 12) {
        int l = (blk-4)>>1, which = (blk-4)&1;
        const float* E = (l==0)?e0:(l==1)?e1:(l==2)?e2:e3;
        W = E + which*16384;
        Hi = g_WeqHi + (l*2+which)*16384; Lo = g_WeqLo + (l*2+which)*16384;
    } else {
        W = wfin; Hi = g_WfinHi; Lo = g_WfinLo;
    }
    for (int e = tid; e < 16384; e += 256) {
        int n = e>>7, k = e&127;
        __nv_bfloat16 h, l;
        split2(W[k*C_ + n], h, l);
        Hi[e] = h; Lo[e] = l;
    }
}

// ---------------- generic 128x128x128 bf16-split MMA GEMM ----------------
// modes: 0 = U = lrelu(acc+bias)*mask ; 1 = Z0 = acc+Vrow+G ; 2 = Z1 = acc ; 3 = final reduce
__global__ void __launch_bounds__(256) k_gemm(const float* __restrict__ A,
                                              const __nv_bfloat16* __restrict__ Bhi,
                                              const __nv_bfloat16* __restrict__ Blo,
                                              const float* __restrict__ bias,
                                              const int* __restrict__ nobj, int mode) {
    extern __shared__ unsigned char sm[];
    uint32_t sb = smem_u32(sm);
    int tid = threadIdx.x, wid = tid>>5, lane = tid&31;
    int tile = blockIdx.x;
    int b = tile>>5, i0 = (tile&31)<<1;

    // stage A (fp32 -> bf16 hi/lo, pad 136)
    {
        const float4* Ag = (const float4*)(A + (size_t)tile*16384);
        #pragma unroll
        for (int u = 0; u < 16; u++) {
            int f = tid + 256*u;
            int row = f>>5, c4 = (f&31)*4;
            float4 v = Ag[f];
            __nv_bfloat16 h[4], l[4];
            split2(v.x, h[0], l[0]); split2(v.y, h[1], l[1]);
            split2(v.z, h[2], l[2]); split2(v.w, h[3], l[3]);
            uint2 hp = *(uint2*)h, lp = *(uint2*)l;
            *(uint2*)(sm + AH_OFF + (row*APAD + c4)*2) = hp;
            *(uint2*)(sm + AL_OFF + (row*APAD + c4)*2) = lp;
        }
    }
    // stage B (bf16 [n][128] -> permuted [n][BPAD])
    {
        const uint32_t* bh = (const uint32_t*)Bhi;
        const uint32_t* bl = (const uint32_t*)Blo;
        #pragma unroll
        for (int u = 0; u < 32; u++) {
            int f = tid + 256*u;          // pair index: n*64 + k/2
            int n = f>>6, k = (f&63)*2;
            int col = (k & ~15) + (((k>>1)&3)<<2) + (((k>>3)&1)<<1);
            *(uint32_t*)(sm + BH_OFF + (n*BPAD + col)*2) = bh[f];
            *(uint32_t*)(sm + BL_OFF + (n*BPAD + col)*2) = bl[f];
        }
    }
    __syncthreads();

    int wy = wid&3, wx = wid>>2;
    int rb = wy*32;                  // warp rows rb..rb+31
    int nb0 = wx*64;                 // warp cols nb0..nb0+63
    float c[2][8][4];
    #pragma unroll
    for (int mt = 0; mt < 2; mt++)
        #pragma unroll
        for (int nt = 0; nt < 8; nt++)
            #pragma unroll
            for (int q = 0; q < 4; q++) c[mt][nt][q] = 0.f;

    // ldmatrix lane address (per mt): row = rb + mt*16 + (lane&7) + ((lane>>3)&1)*8, colk byte = ((lane>>4)&1)*16
    int lrow = (lane&7) + ((lane>>3)&1)*8;
    int lcolb = ((lane>>4)&1)*16;
    int bn = nb0 + (lane>>2);
    int btid4 = (lane&3)*4;

    #pragma unroll
    for (int ks = 0; ks < 8; ks++) {
        uint32_t ah[2][4], al[2][4];
        #pragma unroll
        for (int mt = 0; mt < 2; mt++) {
            uint32_t adr = sb + AH_OFF + (rb + mt*16 + lrow)*APAD*2 + ks*32 + lcolb;
            ldmx4(adr, ah[mt][0], ah[mt][1], ah[mt][2], ah[mt][3]);
            adr = sb + AL_OFF + (rb + mt*16 + lrow)*APAD*2 + ks*32 + lcolb;
            ldmx4(adr, al[mt][0], al[mt][1], al[mt][2], al[mt][3]);
        }
        #pragma unroll
        for (int nt = 0; nt < 8; nt++) {
            uint32_t bh0, bh1, bl0, bl1;
            uint32_t badr = sb + BH_OFF + ((bn + nt*8)*BPAD + ks*16 + btid4)*2;
            asm volatile("ld.shared.v2.b32 {%0,%1}, [%2];" : "=r"(bh0), "=r"(bh1) : "r"(badr));
            badr = sb + BL_OFF + ((bn + nt*8)*BPAD + ks*16 + btid4)*2;
            asm volatile("ld.shared.v2.b32 {%0,%1}, [%2];" : "=r"(bl0), "=r"(bl1) : "r"(badr));
            #pragma unroll
            for (int mt = 0; mt < 2; mt++) {
                mma16816(c[mt][nt], ah[mt], bh0, bh1);
                mma16816(c[mt][nt], ah[mt], bl0, bl1);
                mma16816(c[mt][nt], al[mt], bh0, bh1);
            }
        }
    }

    // ---------------- epilogues ----------------
    int nb = nobj[b];
    int g = lane>>2, t2 = (lane&3)*2;
    if (mode == 0) {
        float* Out = g_U + (size_t)tile*16384;
        #pragma unroll
        for (int mt = 0; mt < 2; mt++) {
            #pragma unroll
            for (int h = 0; h < 2; h++) {
                int row = rb + mt*16 + g + h*8;
                int i = i0 + (row>>6), j = row&63;
                float mask = (i < nb && j < nb) ? 1.f : 0.f;
                #pragma unroll
                for (int nt = 0; nt < 8; nt++) {
                    int col = nb0 + nt*8 + t2;
                    float2 v;
                    v.x = lrelu(c[mt][nt][h*2+0] + bias[col])   * mask;
                    v.y = lrelu(c[mt][nt][h*2+1] + bias[col+1]) * mask;
                    *(float2*)(Out + row*128 + col) = v;
                }
            }
        }
    } else if (mode == 1 || mode == 2) {
        float* Out = (mode == 1) ? g_Z0 : g_Z1;
        #pragma unroll
        for (int mt = 0; mt < 2; mt++) {
            #pragma unroll
            for (int h = 0; h < 2; h++) {
                int row = rb + mt*16 + g + h*8;
                int i = i0 + (row>>6), j = row&63;
                size_t m = ((size_t)(b*64 + i)*64 + j);
                #pragma unroll
                for (int nt = 0; nt < 8; nt++) {
                    int col = nb0 + nt*8 + t2;
                    float2 v;
                    v.x = c[mt][nt][h*2+0];
                    v.y = c[mt][nt][h*2+1];
                    if (mode == 1) {
                        v.x += g_Vrow[(b*64+i)*C_ + col]   + g_G[b*C_ + col];
                        v.y += g_Vrow[(b*64+i)*C_ + col+1] + g_G[b*C_ + col+1];
                    }
                    *(float2*)(Out + m*128 + col) = v;
                }
            }
        }
    } else {
        // mode 3: V = lrelu(acc+bias)*mask staged in smem, then trace/total reduce
        __syncthreads();
        float* Vs = (float*)sm;   // [128][132]
        #pragma unroll
        for (int mt = 0; mt < 2; mt++) {
            #pragma unroll
            for (int h = 0; h < 2; h++) {
                int row = rb + mt*16 + g + h*8;
                int i = i0 + (row>>6), j = row&63;
                float mask = (i < nb && j < nb) ? 1.f : 0.f;
                #pragma unroll
                for (int nt = 0; nt < 8; nt++) {
                    int col = nb0 + nt*8 + t2;
                    float2 v;
                    v.x = lrelu(c[mt][nt][h*2+0] + bias[col])   * mask;
                    v.y = lrelu(c[mt][nt][h*2+1] + bias[col+1]) * mask;
                    *(float2*)(Vs + row*132 + col) = v;
                }
            }
        }
        __syncthreads();
        if (tid < 128) {
            float s = 0.f;
            #pragma unroll 8
            for (int r = 0; r < 128; r++) s += Vs[r*132 + tid];
            atomicAdd(&g_tot[b*C_ + tid], s);
            float dgv = Vs[i0*132 + tid] + Vs[(64 + i0 + 1)*132 + tid];
            atomicAdd(&g_dg[b*C_ + tid], dgv);
        }
    }
}

// ---------------- eq1to2 prep ----------------
__global__ void k_prep(const float* __restrict__ scalars, const int* __restrict__ nobj,
                       const float* __restrict__ w_in) {
    int b = blockIdx.x;
    __shared__ float xs[N_][S_];
    __shared__ float ssum[S_];
    int nb = nobj[b];
    for (int idx = threadIdx.x; idx < N_*S_; idx += blockDim.x) {
        int n = idx/S_, s = idx%S_;
        xs[n][s] = (n < nb) ? scalars[(b*N_+n)*S_+s] : 0.f;
    }
    __syncthreads();
    if (threadIdx.x < S_) {
        float a = 0.f;
        for (int n = 0; n < N_; n++) a += xs[n][threadIdx.x];
        ssum[threadIdx.x] = a / AVGF;
    }
    __syncthreads();
    for (int idx = threadIdx.x; idx < N_*CS_; idx += blockDim.x) {
        int n = idx/CS_, c = idx%CS_;
        float a0=0, a1=0, a2=0;
        #pragma unroll
        for (int s = 0; s < S_; s++) {
            float xv = xs[n][s];
            a0 += xv*w_in[(0*S_+s)*CS_+c];
            a1 += xv*w_in[(1*S_+s)*CS_+c];
            a2 += xv*w_in[(2*S_+s)*CS_+c];
        }
        g_y012[((b*N_+n)*3+0)*CS_+c] = a0;
        g_y012[((b*N_+n)*3+1)*CS_+c] = a1;
        g_y012[((b*N_+n)*3+2)*CS_+c] = a2;
    }
    if (threadIdx.x < 2*CS_) {
        int k = threadIdx.x/CS_, c = threadIdx.x%CS_;
        float a = 0.f;
        #pragma unroll
        for (int s = 0; s < S_; s++) a += ssum[s]*w_in[((3+k)*S_+s)*CS_+c];
        g_y34[(b*2+k)*CS_+c] = a;
    }
}

// ---------------- initial T (tile layout, fp32) ----------------
__global__ void k_init(const float* __restrict__ momenta, const int* __restrict__ nobj,
                       const float* __restrict__ w_lin, const float* __restrict__ alpha,
                       const float* __restrict__ b_in) {
    int b = blockIdx.x / N_, i = blockIdx.x % N_;
    int c = threadIdx.x;
    __shared__ float pm[N_][4];
    __shared__ float dij[N_];
    __shared__ float y1s[N_][CS_];
    __shared__ float y0r[CS_], y2r[CS_], y3s[CS_], y4s[CS_];
    for (int idx = c; idx < N_*4; idx += 128) pm[idx/4][idx%4] = momenta[(b*N_)*4 + idx];
    for (int idx = c; idx < N_*CS_; idx += 128) {
        int n = idx/CS_, cs = idx%CS_;
        y1s[n][cs] = g_y012[((b*N_+n)*3+1)*CS_+cs];
    }
    if (c < CS_) {
        y0r[c] = g_y012[((b*N_+i)*3+0)*CS_+c];
        y2r[c] = g_y012[((b*N_+i)*3+2)*CS_+c];
        y3s[c] = g_y34[(b*2+0)*CS_+c];
        y4s[c] = g_y34[(b*2+1)*CS_+c];
    }
    __syncthreads();
    if (c < N_)
        dij[c] = pm[i][0]*pm[c][0] - pm[i][1]*pm[c][1] - pm[i][2]*pm[c][2] - pm[i][3]*pm[c][3];
    __syncthreads();
    int nb = nobj[b];
    float mi = (i < nb) ? 1.f : 0.f;
    float base = 0.f, wl = 0.f, al = 0.f;
    if (c < CS_) base = y0r[c] + y3s[c] + b_in[c];
    else { wl = w_lin[c-CS_]; al = alpha[c-CS_]; }
    size_t rowbase = ((size_t)(b*32 + (i>>1))*128 + (i&1)*64)*128;
    for (int j = 0; j < N_; j++) {
        float mask = mi * ((j < nb) ? 1.f : 0.f);
        float v;
        if (c < CS_) {
            v = base + y1s[j][c];
            if (j == i) v += y2r[c] + y4s[c];
            v = lrelu(v) * mask;
        } else {
            float r = dij[j] * wl;
            v = al * copysignf(log1pf(fabsf(r)), r) * mask;
        }
        g_T[rowbase + j*128 + c] = v;
    }
}

// ---------------- reductions from U (tile layout) ----------------
__global__ void k_r1() {
    int b = blockIdx.x >> 6, i = blockIdx.x & 63;
    int c = threadIdx.x;
    size_t rbase = ((size_t)(b*32 + (i>>1))*128 + (i&1)*64)*128 + c;
    float rs = 0.f, cs = 0.f;
    for (int j = 0; j < N_; j++) rs += g_U[rbase + j*128];
    for (int ii = 0; ii < N_; ii++)
        cs += g_U[((size_t)(b*32 + (ii>>1))*128 + (ii&1)*64 + i)*128 + c];
    int o = (b*N_+i)*C_ + c;
    g_dvec[o] = g_U[rbase + i*128];
    g_rvec[o] = rs / AVGF;
    g_cvec[o] = cs / AVGF;
}

__global__ void k_r2() {
    int b = blockIdx.x, c = threadIdx.x;
    float t = 0.f, tr = 0.f;
    for (int i = 0; i < N_; i++) { t += g_rvec[(b*N_+i)*C_+c]; tr += g_dvec[(b*N_+i)*C_+c]; }
    g_t[b*C_+c] = t/AVGF; g_tr[b*C_+c] = tr/AVGF;
}

__global__ void k_p(const float* __restrict__ W) {
    int b = blockIdx.x>>6, i = blockIdx.x&63;
    int d = threadIdx.x;
    __shared__ float dv[C_], rv[C_], cv[C_];
    int o = (b*N_+i)*C_ + d;
    dv[d] = g_dvec[o]; rv[d] = g_rvec[o]; cv[d] = g_cvec[o];
    __syncthreads();
    float a = 0.f, bb = 0.f, cc = 0.f;
    for (int c = 0; c < C_; c++) {
        float dvc = dv[c], rvc = rv[c], cvc = cv[c];
        a  += dvc*W[(3*C_+c)*C_+d] + rvc*W[(5*C_+c)*C_+d] + cvc*W[(7*C_+c)*C_+d];
        bb += dvc*W[(4*C_+c)*C_+d] + rvc*W[(6*C_+c)*C_+d] + cvc*W[(8*C_+c)*C_+d];
        cc += dvc*W[(2*C_+c)*C_+d] + rvc*W[(9*C_+c)*C_+d] + cvc*W[(10*C_+c)*C_+d];
    }
    g_Vrow[o] = a; g_Vcol[o] = bb; g_Dd[o] = cc;
}

__global__ void k_pg(const float* __restrict__ W, const float* __restrict__ eqb,
                     const float* __restrict__ eqbd) {
    int b = blockIdx.x, d = threadIdx.x;
    __shared__ float tt[C_], tg[C_];
    tt[d] = g_t[b*C_+d]; tg[d] = g_tr[b*C_+d];
    __syncthreads();
    float g = eqb[d], e = eqbd[d];
    for (int c = 0; c < C_; c++) {
        g += tt[c]*W[(11*C_+c)*C_+d] + tg[c]*W[(13*C_+c)*C_+d];
        e += tt[c]*W[(12*C_+c)*C_+d] + tg[c]*W[(14*C_+c)*C_+d];
    }
    g_G[b*C_+d] = g; g_E[b*C_+d] = e;
}

// ---------------- combine: T = lrelu(Z0 + Z1^T + Vcol (+diag))*mask ----------------
__global__ void k_combine(const int* __restrict__ nobj) {
    int gid = blockIdx.x*256 + threadIdx.x;
    int m = gid>>4, gc = (gid&15)<<3;
    int b = m>>12, i = (m>>6)&63, j = m&63;
    int nb = nobj[b];
    float mask = (i < nb && j < nb) ? 1.f : 0.f;
    size_t mt = (size_t)((b<<12) | (j<<6) | i);
    float4 z0a = *(const float4*)(g_Z0 + (size_t)m*C_ + gc);
    float4 z0b = *(const float4*)(g_Z0 + (size_t)m*C_ + gc + 4);
    float4 z1a = *(const float4*)(g_Z1 + mt*C_ + gc);
    float4 z1b = *(const float4*)(g_Z1 + mt*C_ + gc + 4);
    float4 vca = *(const float4*)(g_Vcol + (b*N_+j)*C_ + gc);
    float4 vcb = *(const float4*)(g_Vcol + (b*N_+j)*C_ + gc + 4);
    float v[8];
    v[0]=z0a.x+z1a.x+vca.x; v[1]=z0a.y+z1a.y+vca.y; v[2]=z0a.z+z1a.z+vca.z; v[3]=z0a.w+z1a.w+vca.w;
    v[4]=z0b.x+z1b.x+vcb.x; v[5]=z0b.y+z1b.y+vcb.y; v[6]=z0b.z+z1b.z+vcb.z; v[7]=z0b.w+z1b.w+vcb.w;
    if (i == j) {
        float4 da = *(const float4*)(g_Dd + (b*N_+i)*C_ + gc);
        float4 db = *(const float4*)(g_Dd + (b*N_+i)*C_ + gc + 4);
        float4 ea = *(const float4*)(g_E + b*C_ + gc);
        float4 eb = *(const float4*)(g_E + b*C_ + gc + 4);
        v[0]+=da.x+ea.x; v[1]+=da.y+ea.y; v[2]+=da.z+ea.z; v[3]+=da.w+ea.w;
        v[4]+=db.x+eb.x; v[5]+=db.y+eb.y; v[6]+=db.z+eb.z; v[7]+=db.w+eb.w;
    }
    float4 oa, ob;
    oa.x = lrelu(v[0])*mask; oa.y = lrelu(v[1])*mask; oa.z = lrelu(v[2])*mask; oa.w = lrelu(v[3])*mask;
    ob.x = lrelu(v[4])*mask; ob.y = lrelu(v[5])*mask; ob.z = lrelu(v[6])*mask; ob.w = lrelu(v[7])*mask;
    size_t tadr = ((size_t)(b*32 + (i>>1))*128 + (i&1)*64 + j)*128 + gc;
    *(float4*)(g_T + tadr)     = oa;
    *(float4*)(g_T + tadr + 4) = ob;
}

__global__ void k_zero() {
    int idx = blockIdx.x*blockDim.x + threadIdx.x;
    if (idx < B_*C_) { g_dg[idx] = 0.f; g_tot[idx] = 0.f; }
}

__global__ void k_out(const float* __restrict__ w20, const float* __restrict__ b20,
                      const float* __restrict__ wmlp, const float* __restrict__ bmlp,
                      float* __restrict__ out) {
    int b = blockIdx.x, d = threadIdx.x;
    __shared__ float a0[C_], a1[C_], act[C_];
    a0[d] = lrelu(g_dg[b*C_+d] / AVGF);
    a1[d] = lrelu(g_tot[b*C_+d] / (AVGF*AVGF));
    __syncthreads();
    float a = b20[d];
    for (int c = 0; c < C_; c++) a += a0[c]*w20[c*C_+d] + a1[c]*w20[(C_+c)*C_+d];
    act[d] = a;
    __syncthreads();
    if (d < 2) {
        float o = bmlp[d];
        for (int k = 0; k < C_; k++) o += act[k]*wmlp[k*2+d];
        out[b*2+d] = o;
    }
}

// ---------------- host ----------------
extern "C" void kernel_launch(void* const* d_in, const int* in_sizes, int n_in,
                              void* d_out, int out_size) {
    const float *momenta=0, *scalars=0, *w_lin=0, *alpha=0, *w_in=0, *b_in=0;
    const int* nobj=0;
    const float *msgw[4], *msgb[4], *eqw[4], *eqb[4], *eqbd[4];
    const float *wm0=0, *bm0=0, *w20=0, *b20=0, *wmlp=0, *bmlp=0;

    if (n_in >= 33 && in_sizes[0] == 8192) {
        momenta=(const float*)d_in[0]; scalars=(const float*)d_in[1]; nobj=(const int*)d_in[2];
        w_lin=(const float*)d_in[3]; alpha=(const float*)d_in[4]; w_in=(const float*)d_in[5];
        b_in=(const float*)d_in[6];
        for (int l = 0; l < 4; l++) {
            msgw[l]=(const float*)d_in[7+l];  msgb[l]=(const float*)d_in[11+l];
            eqw[l] =(const float*)d_in[15+l]; eqb[l] =(const float*)d_in[19+l];
            eqbd[l]=(const float*)d_in[23+l];
        }
        wm0=(const float*)d_in[27]; bm0=(const float*)d_in[28]; w20=(const float*)d_in[29];
        b20=(const float*)d_in[30]; wmlp=(const float*)d_in[31]; bmlp=(const float*)d_in[32];
    } else if (n_in >= 33) {
        alpha=(const float*)d_in[0]; b20=(const float*)d_in[1]; b_in=(const float*)d_in[2];
        bm0=(const float*)d_in[3]; bmlp=(const float*)d_in[4];
        for (int l = 0; l < 4; l++) {
            eqb[l] =(const float*)d_in[5+l];  eqbd[l]=(const float*)d_in[9+l];
            eqw[l] =(const float*)d_in[13+l]; msgb[l]=(const float*)d_in[18+l];
            msgw[l]=(const float*)d_in[22+l];
        }
        momenta=(const float*)d_in[17]; nobj=(const int*)d_in[26]; scalars=(const float*)d_in[27];
        w20=(const float*)d_in[28]; w_in=(const float*)d_in[29]; w_lin=(const float*)d_in[30];
        wm0=(const float*)d_in[31]; wmlp=(const float*)d_in[32];
    } else {
        momenta=(const float*)d_in[0]; scalars=(const float*)d_in[1]; nobj=(const int*)d_in[2];
        w_lin=(const float*)d_in[3]; alpha=(const float*)d_in[4]; w_in=(const float*)d_in[5];
        b_in=(const float*)d_in[6];
        for (int l = 0; l < 4; l++) {
            msgw[l]=(const float*)d_in[7]+(size_t)l*C_*C_;     msgb[l]=(const float*)d_in[8]+(size_t)l*C_;
            eqw[l] =(const float*)d_in[9]+(size_t)l*15*C_*C_;  eqb[l] =(const float*)d_in[10]+(size_t)l*C_;
            eqbd[l]=(const float*)d_in[11]+(size_t)l*C_;
        }
        wm0=(const float*)d_in[12]; bm0=(const float*)d_in[13]; w20=(const float*)d_in[14];
        b20=(const float*)d_in[15]; wmlp=(const float*)d_in[16]; bmlp=(const float*)d_in[17];
    }

    cudaFuncSetAttribute(k_gemm, cudaFuncAttributeMaxDynamicSharedMemorySize, SM_GEMM);

    float *Tp=0, *Up=0;
    cudaGetSymbolAddress((void**)&Tp, g_T);
    cudaGetSymbolAddress((void**)&Up, g_U);
    __nv_bfloat16 *WmH=0, *WmL=0, *WeH=0, *WeL=0, *WfH=0, *WfL=0;
    cudaGetSymbolAddress((void**)&WmH, g_WmsgHi);
    cudaGetSymbolAddress((void**)&WmL, g_WmsgLo);
    cudaGetSymbolAddress((void**)&WeH, g_WeqHi);
    cudaGetSymbolAddress((void**)&WeL, g_WeqLo);
    cudaGetSymbolAddress((void**)&WfH, g_WfinHi);
    cudaGetSymbolAddress((void**)&WfL, g_WfinLo);

    k_wsplit<<<13, 256>>>(msgw[0], msgw[1], msgw[2], msgw[3],
                          eqw[0], eqw[1], eqw[2], eqw[3], wm0);
    k_prep<<<B_, 256>>>(scalars, nobj, w_in);
    k_init<<<B_*N_, 128>>>(momenta, nobj, w_lin, alpha, b_in);

    for (int l = 0; l < 4; l++) {
        k_gemm<<<TILES, 256, SM_GEMM>>>(Tp, WmH + l*16384, WmL + l*16384, msgb[l], nobj, 0);
        k_r1<<<B_*N_, 128>>>();
        k_r2<<<B_, 128>>>();
        k_p<<<B_*N_, 128>>>(eqw[l]);
        k_pg<<<B_, 128>>>(eqw[l], eqb[l], eqbd[l]);
        k_gemm<<<TILES, 256, SM_GEMM>>>(Up, WeH + (l*2+0)*16384, WeL + (l*2+0)*16384, msgb[l], nobj, 1);
        k_gemm<<<TILES, 256, SM_GEMM>>>(Up, WeH + (l*2+1)*16384, WeL + (l*2+1)*16384, msgb[l], nobj, 2);
        k_combine<<<8192, 256>>>(nobj);
    }

    k_zero<<<(B_*C_ + 255)/256, 256>>>();
    k_gemm<<<TILES, 256, SM_GEMM>>>(Tp, WfH, WfL, bm0, nobj, 3);
    k_out<<<B_, 128>>>(w20, b20, wmlp, bmlp, (float*)d_out);
}

// round 6
// speedup vs baseline: 1.9929x; 1.0725x over previous
#include <cuda_runtime.h>
#include <cuda_bf16.h>
#include <math.h>
#include <stdint.h>

#define B_  32
#define N_  64
#define S_  9
#define C_  128
#define CS_ 32
#define AVGF 49.0f
#define TILES (B_*32)   // 1024 tiles of 128 rows; tile=(b, i-pair), row=(i&1)*64+j

// ---------------- device scratch ----------------
__device__ float g_T[B_*N_*N_*C_];
__device__ float g_U[B_*N_*N_*C_];
__device__ float g_Z1[B_*N_*N_*C_];      // stored TRANSPOSED: index (b, i, j) holds (U@W1)[b,j,i]
__device__ __nv_bfloat16 g_WmsgHi[4*16384], g_WmsgLo[4*16384];
__device__ __nv_bfloat16 g_WeqHi[8*16384],  g_WeqLo[8*16384];   // [l][which][n][k]
__device__ __nv_bfloat16 g_WfinHi[16384],   g_WfinLo[16384];
__device__ float g_y012[B_*N_*3*CS_];
__device__ float g_y34[B_*2*CS_];
__device__ float g_dvec[B_*N_*C_];
__device__ float g_rvec[B_*N_*C_];
__device__ float g_cvec[B_*N_*C_];
__device__ float g_Vrow[B_*N_*C_];
__device__ float g_Vcol[B_*N_*C_];
__device__ float g_Dd[B_*N_*C_];
__device__ float g_G[B_*C_];
__device__ float g_E[B_*C_];
__device__ float g_t[B_*C_];
__device__ float g_tr[B_*C_];
__device__ float g_dg[B_*C_];
__device__ float g_tot[B_*C_];

__device__ __forceinline__ float lrelu(float x){ return x >= 0.f ? x : 0.01f*x; }
__device__ __forceinline__ uint32_t smem_u32(const void* p) {
    uint32_t a;
    asm("{ .reg .u64 t; cvta.to.shared.u64 t, %1; cvt.u32.u64 %0, t; }" : "=r"(a) : "l"(p));
    return a;
}
__device__ __forceinline__ void split2(float v, __nv_bfloat16& h, __nv_bfloat16& l) {
    h = __float2bfloat16(v);
    l = __float2bfloat16(v - __bfloat162float(h));
}
__device__ __forceinline__ void ldmx4(uint32_t a, uint32_t& r0, uint32_t& r1, uint32_t& r2, uint32_t& r3) {
    asm volatile("ldmatrix.sync.aligned.m8n8.x4.shared.b16 {%0,%1,%2,%3}, [%4];"
                 : "=r"(r0), "=r"(r1), "=r"(r2), "=r"(r3) : "r"(a));
}
__device__ __forceinline__ void mma16816(float* c, const uint32_t* a, uint32_t b0, uint32_t b1) {
    asm volatile("mma.sync.aligned.m16n8k16.row.col.f32.bf16.bf16.f32 "
                 "{%0,%1,%2,%3}, {%4,%5,%6,%7}, {%8,%9}, {%0,%1,%2,%3};"
                 : "+f"(c[0]), "+f"(c[1]), "+f"(c[2]), "+f"(c[3])
                 : "r"(a[0]), "r"(a[1]), "r"(a[2]), "r"(a[3]), "r"(b0), "r"(b1));
}

// smem geometry (half-K staging: K=64 per phase)
#define APAD 72    // elements; 144B row stride
#define BPAD 80    // elements; 160B n stride
#define AH_OFF 0
#define AL_OFF 18432
#define BH_OFF 36864
#define BL_OFF 57344
#define SM_GEMM 77824

// ---------------- weight split: col-major [n][k] bf16 hi/lo ----------------
__global__ void k_wsplit(const float* __restrict__ m0, const float* __restrict__ m1,
                         const float* __restrict__ m2, const float* __restrict__ m3,
                         const float* __restrict__ e0, const float* __restrict__ e1,
                         const float* __restrict__ e2, const float* __restrict__ e3,
                         const float* __restrict__ wfin) {
    int blk = blockIdx.x, tid = threadIdx.x;
    const float* W; __nv_bfloat16 *Hi, *Lo;
    if (blk < 4) {
        W = (blk==0)?m0:(blk==1)?m1:(blk==2)?m2:m3;
        Hi = g_WmsgHi + blk*16384; Lo = g_WmsgLo + blk*16384;
    } else if (blk < 12) {
        int l = (blk-4)>>1, which = (blk-4)&1;
        const float* E = (l==0)?e0:(l==1)?e1:(l==2)?e2:e3;
        W = E + which*16384;
        Hi = g_WeqHi + (l*2+which)*16384; Lo = g_WeqLo + (l*2+which)*16384;
    } else {
        W = wfin; Hi = g_WfinHi; Lo = g_WfinLo;
    }
    for (int e = tid; e < 16384; e += 256) {
        int n = e>>7, k = e&127;
        __nv_bfloat16 h, l;
        split2(W[k*C_ + n], h, l);
        Hi[e] = h; Lo[e] = l;
    }
}

// ---------------- generic 128x128x128 bf16-split MMA GEMM, 2-phase K ----------------
// modes: 0 = U = lrelu(acc+bias)*mask
//        1 = T = lrelu(acc + Vrow + G + Vcol + Z1t (+Dd+E diag))*mask   [fused Eq2to2 combine]
//        2 = Z1t(b,j,i) = acc(b,i,j)   [transposed store]
//        3 = final: lrelu(acc+bias)*mask -> trace/total reduction
__global__ void __launch_bounds__(256, 2) k_gemm(const float* __restrict__ A,
                                                 const __nv_bfloat16* __restrict__ Bhi,
                                                 const __nv_bfloat16* __restrict__ Blo,
                                                 const float* __restrict__ bias,
                                                 const int* __restrict__ nobj, int mode) {
    extern __shared__ unsigned char sm[];
    uint32_t sb = smem_u32(sm);
    int tid = threadIdx.x, wid = tid>>5, lane = tid&31;
    int tile = blockIdx.x;
    int b = tile>>5, i0 = (tile&31)<<1;

    int wy = wid&3, wx = wid>>2;
    int rb = wy*32;
    int nb0 = wx*64;
    float c[2][8][4];
    #pragma unroll
    for (int mt = 0; mt < 2; mt++)
        #pragma unroll
        for (int nt = 0; nt < 8; nt++)
            #pragma unroll
            for (int q = 0; q < 4; q++) c[mt][nt][q] = 0.f;

    int lrow = (lane&7) + ((lane>>3)&1)*8;
    int lcolb = ((lane>>4)&1)*16;
    int bn = nb0 + (lane>>2);
    int btid4 = (lane&3)*4;

    for (int ph = 0; ph < 2; ph++) {
        if (ph) __syncthreads();
        // stage A half (fp32 -> bf16 hi/lo)
        {
            const float4* Ag = (const float4*)(A + (size_t)tile*16384);
            #pragma unroll
            for (int u = 0; u < 8; u++) {
                int f = tid + 256*u;
                int row = f>>4, c4 = (f&15)*4;
                float4 v = Ag[row*32 + ph*16 + (f&15)];
                __nv_bfloat16 h[4], l[4];
                split2(v.x, h[0], l[0]); split2(v.y, h[1], l[1]);
                split2(v.z, h[2], l[2]); split2(v.w, h[3], l[3]);
                *(uint2*)(sm + AH_OFF + (row*APAD + c4)*2) = *(uint2*)h;
                *(uint2*)(sm + AL_OFF + (row*APAD + c4)*2) = *(uint2*)l;
            }
        }
        // stage B half (bf16 [n][128] -> permuted [n][BPAD])
        {
            const uint32_t* bh = (const uint32_t*)Bhi;
            const uint32_t* bl = (const uint32_t*)Blo;
            #pragma unroll
            for (int u = 0; u < 16; u++) {
                int f = tid + 256*u;
                int n = f>>5, kp = f&31;
                int k = kp*2;
                int col = (k & ~15) + (((k>>1)&3)<<2) + (((k>>3)&1)<<1);
                *(uint32_t*)(sm + BH_OFF + (n*BPAD + col)*2) = bh[n*64 + ph*32 + kp];
                *(uint32_t*)(sm + BL_OFF + (n*BPAD + col)*2) = bl[n*64 + ph*32 + kp];
            }
        }
        __syncthreads();
        #pragma unroll
        for (int ks = 0; ks < 4; ks++) {
            uint32_t ah[2][4], al[2][4];
            #pragma unroll
            for (int mt = 0; mt < 2; mt++) {
                uint32_t adr = sb + AH_OFF + (rb + mt*16 + lrow)*APAD*2 + ks*32 + lcolb;
                ldmx4(adr, ah[mt][0], ah[mt][1], ah[mt][2], ah[mt][3]);
                adr = sb + AL_OFF + (rb + mt*16 + lrow)*APAD*2 + ks*32 + lcolb;
                ldmx4(adr, al[mt][0], al[mt][1], al[mt][2], al[mt][3]);
            }
            #pragma unroll
            for (int nt = 0; nt < 8; nt++) {
                uint32_t bh0, bh1, bl0, bl1;
                uint32_t badr = sb + BH_OFF + ((bn + nt*8)*BPAD + ks*16 + btid4)*2;
                asm volatile("ld.shared.v2.b32 {%0,%1}, [%2];" : "=r"(bh0), "=r"(bh1) : "r"(badr));
                badr = sb + BL_OFF + ((bn + nt*8)*BPAD + ks*16 + btid4)*2;
                asm volatile("ld.shared.v2.b32 {%0,%1}, [%2];" : "=r"(bl0), "=r"(bl1) : "r"(badr));
                #pragma unroll
                for (int mt = 0; mt < 2; mt++) {
                    mma16816(c[mt][nt], ah[mt], bh0, bh1);
                    mma16816(c[mt][nt], ah[mt], bl0, bl1);
                    mma16816(c[mt][nt], al[mt], bh0, bh1);
                }
            }
        }
    }

    // ---------------- epilogues ----------------
    int nb = nobj[b];
    int g = lane>>2, t2 = (lane&3)*2;
    if (mode == 0) {
        float* Out = g_U + (size_t)tile*16384;
        #pragma unroll
        for (int mt = 0; mt < 2; mt++) {
            #pragma unroll
            for (int h = 0; h < 2; h++) {
                int row = rb + mt*16 + g + h*8;
                int i = i0 + (row>>6), j = row&63;
                float mask = (i < nb && j < nb) ? 1.f : 0.f;
                #pragma unroll
                for (int nt = 0; nt < 8; nt++) {
                    int col = nb0 + nt*8 + t2;
                    float2 v;
                    v.x = lrelu(c[mt][nt][h*2+0] + bias[col])   * mask;
                    v.y = lrelu(c[mt][nt][h*2+1] + bias[col+1]) * mask;
                    *(float2*)(Out + row*128 + col) = v;
                }
            }
        }
    } else if (mode == 2) {
        // transposed store: acc for (b,i,j) goes to linear index (b, j, i)
        #pragma unroll
        for (int mt = 0; mt < 2; mt++) {
            #pragma unroll
            for (int h = 0; h < 2; h++) {
                int row = rb + mt*16 + g + h*8;
                int i = i0 + (row>>6), j = row&63;
                size_t m = ((size_t)(b*64 + j)*64 + i);
                #pragma unroll
                for (int nt = 0; nt < 8; nt++) {
                    int col = nb0 + nt*8 + t2;
                    float2 v;
                    v.x = c[mt][nt][h*2+0];
                    v.y = c[mt][nt][h*2+1];
                    *(float2*)(g_Z1 + m*128 + col) = v;
                }
            }
        }
    } else if (mode == 1) {
        // fused Eq2to2 combine -> T (tile layout; Z1t read is linear at same offset)
        float* Out = g_T + (size_t)tile*16384;
        const float* Zt = g_Z1 + (size_t)tile*16384;
        #pragma unroll
        for (int mt = 0; mt < 2; mt++) {
            #pragma unroll
            for (int h = 0; h < 2; h++) {
                int row = rb + mt*16 + g + h*8;
                int i = i0 + (row>>6), j = row&63;
                float mask = (i < nb && j < nb) ? 1.f : 0.f;
                bool diag = (i == j);
                const float* vr = g_Vrow + (b*64+i)*C_;
                const float* vc = g_Vcol + (b*64+j)*C_;
                const float* gg = g_G + b*C_;
                const float* dd = g_Dd + (b*64+i)*C_;
                const float* ee = g_E + b*C_;
                #pragma unroll
                for (int nt = 0; nt < 8; nt++) {
                    int col = nb0 + nt*8 + t2;
                    float2 z = *(const float2*)(Zt + row*128 + col);
                    float vx = c[mt][nt][h*2+0] + z.x + vr[col]   + gg[col]   + vc[col];
                    float vy = c[mt][nt][h*2+1] + z.y + vr[col+1] + gg[col+1] + vc[col+1];
                    if (diag) {
                        vx += dd[col]   + ee[col];
                        vy += dd[col+1] + ee[col+1];
                    }
                    float2 o;
                    o.x = lrelu(vx) * mask;
                    o.y = lrelu(vy) * mask;
                    *(float2*)(Out + row*128 + col) = o;
                }
            }
        }
    } else {
        // mode 3: V = lrelu(acc+bias)*mask staged in smem, then trace/total reduce
        __syncthreads();
        float* Vs = (float*)sm;   // [128][132] floats = 67584 B < SM_GEMM
        #pragma unroll
        for (int mt = 0; mt < 2; mt++) {
            #pragma unroll
            for (int h = 0; h < 2; h++) {
                int row = rb + mt*16 + g + h*8;
                int i = i0 + (row>>6), j = row&63;
                float mask = (i < nb && j < nb) ? 1.f : 0.f;
                #pragma unroll
                for (int nt = 0; nt < 8; nt++) {
                    int col = nb0 + nt*8 + t2;
                    float2 v;
                    v.x = lrelu(c[mt][nt][h*2+0] + bias[col])   * mask;
                    v.y = lrelu(c[mt][nt][h*2+1] + bias[col+1]) * mask;
                    *(float2*)(Vs + row*132 + col) = v;
                }
            }
        }
        __syncthreads();
        if (tid < 128) {
            float s = 0.f;
            #pragma unroll 8
            for (int r = 0; r < 128; r++) s += Vs[r*132 + tid];
            atomicAdd(&g_tot[b*C_ + tid], s);
            float dgv = Vs[i0*132 + tid] + Vs[(64 + i0 + 1)*132 + tid];
            atomicAdd(&g_dg[b*C_ + tid], dgv);
        }
    }
}

// ---------------- eq1to2 prep ----------------
__global__ void k_prep(const float* __restrict__ scalars, const int* __restrict__ nobj,
                       const float* __restrict__ w_in) {
    int b = blockIdx.x;
    __shared__ float xs[N_][S_];
    __shared__ float ssum[S_];
    int nb = nobj[b];
    for (int idx = threadIdx.x; idx < N_*S_; idx += blockDim.x) {
        int n = idx/S_, s = idx%S_;
        xs[n][s] = (n < nb) ? scalars[(b*N_+n)*S_+s] : 0.f;
    }
    __syncthreads();
    if (threadIdx.x < S_) {
        float a = 0.f;
        for (int n = 0; n < N_; n++) a += xs[n][threadIdx.x];
        ssum[threadIdx.x] = a / AVGF;
    }
    __syncthreads();
    for (int idx = threadIdx.x; idx < N_*CS_; idx += blockDim.x) {
        int n = idx/CS_, c = idx%CS_;
        float a0=0, a1=0, a2=0;
        #pragma unroll
        for (int s = 0; s < S_; s++) {
            float xv = xs[n][s];
            a0 += xv*w_in[(0*S_+s)*CS_+c];
            a1 += xv*w_in[(1*S_+s)*CS_+c];
            a2 += xv*w_in[(2*S_+s)*CS_+c];
        }
        g_y012[((b*N_+n)*3+0)*CS_+c] = a0;
        g_y012[((b*N_+n)*3+1)*CS_+c] = a1;
        g_y012[((b*N_+n)*3+2)*CS_+c] = a2;
    }
    if (threadIdx.x < 2*CS_) {
        int k = threadIdx.x/CS_, c = threadIdx.x%CS_;
        float a = 0.f;
        #pragma unroll
        for (int s = 0; s < S_; s++) a += ssum[s]*w_in[((3+k)*S_+s)*CS_+c];
        g_y34[(b*2+k)*CS_+c] = a;
    }
}

// ---------------- initial T (tile layout, fp32) ----------------
__global__ void k_init(const float* __restrict__ momenta, const int* __restrict__ nobj,
                       const float* __restrict__ w_lin, const float* __restrict__ alpha,
                       const float* __restrict__ b_in) {
    int b = blockIdx.x / N_, i = blockIdx.x % N_;
    int c = threadIdx.x;
    __shared__ float pm[N_][4];
    __shared__ float dij[N_];
    __shared__ float y1s[N_][CS_];
    __shared__ float y0r[CS_], y2r[CS_], y3s[CS_], y4s[CS_];
    for (int idx = c; idx < N_*4; idx += 128) pm[idx/4][idx%4] = momenta[(b*N_)*4 + idx];
    for (int idx = c; idx < N_*CS_; idx += 128) {
        int n = idx/CS_, cs = idx%CS_;
        y1s[n][cs] = g_y012[((b*N_+n)*3+1)*CS_+cs];
    }
    if (c < CS_) {
        y0r[c] = g_y012[((b*N_+i)*3+0)*CS_+c];
        y2r[c] = g_y012[((b*N_+i)*3+2)*CS_+c];
        y3s[c] = g_y34[(b*2+0)*CS_+c];
        y4s[c] = g_y34[(b*2+1)*CS_+c];
    }
    __syncthreads();
    if (c < N_)
        dij[c] = pm[i][0]*pm[c][0] - pm[i][1]*pm[c][1] - pm[i][2]*pm[c][2] - pm[i][3]*pm[c][3];
    __syncthreads();
    int nb = nobj[b];
    float mi = (i < nb) ? 1.f : 0.f;
    float base = 0.f, wl = 0.f, al = 0.f;
    if (c < CS_) base = y0r[c] + y3s[c] + b_in[c];
    else { wl = w_lin[c-CS_]; al = alpha[c-CS_]; }
    size_t rowbase = ((size_t)(b*32 + (i>>1))*128 + (i&1)*64)*128;
    for (int j = 0; j < N_; j++) {
        float mask = mi * ((j < nb) ? 1.f : 0.f);
        float v;
        if (c < CS_) {
            v = base + y1s[j][c];
            if (j == i) v += y2r[c] + y4s[c];
            v = lrelu(v) * mask;
        } else {
            float r = dij[j] * wl;
            v = al * copysignf(log1pf(fabsf(r)), r) * mask;
        }
        g_T[rowbase + j*128 + c] = v;
    }
}

// ---------------- reductions from U (tile layout) ----------------
__global__ void k_r1() {
    int b = blockIdx.x >> 6, i = blockIdx.x & 63;
    int c = threadIdx.x;
    size_t rbase = ((size_t)(b*32 + (i>>1))*128 + (i&1)*64)*128 + c;
    float rs = 0.f, cs = 0.f;
    for (int j = 0; j < N_; j++) rs += g_U[rbase + j*128];
    for (int ii = 0; ii < N_; ii++)
        cs += g_U[((size_t)(b*32 + (ii>>1))*128 + (ii&1)*64 + i)*128 + c];
    int o = (b*N_+i)*C_ + c;
    g_dvec[o] = g_U[rbase + i*128];
    g_rvec[o] = rs / AVGF;
    g_cvec[o] = cs / AVGF;
}

__global__ void k_r2() {
    int b = blockIdx.x, c = threadIdx.x;
    float t = 0.f, tr = 0.f;
    for (int i = 0; i < N_; i++) { t += g_rvec[(b*N_+i)*C_+c]; tr += g_dvec[(b*N_+i)*C_+c]; }
    g_t[b*C_+c] = t/AVGF; g_tr[b*C_+c] = tr/AVGF;
}

__global__ void k_p(const float* __restrict__ W) {
    int b = blockIdx.x>>6, i = blockIdx.x&63;
    int d = threadIdx.x;
    __shared__ float dv[C_], rv[C_], cv[C_];
    int o = (b*N_+i)*C_ + d;
    dv[d] = g_dvec[o]; rv[d] = g_rvec[o]; cv[d] = g_cvec[o];
    __syncthreads();
    float a = 0.f, bb = 0.f, cc = 0.f;
    for (int c = 0; c < C_; c++) {
        float dvc = dv[c], rvc = rv[c], cvc = cv[c];
        a  += dvc*W[(3*C_+c)*C_+d] + rvc*W[(5*C_+c)*C_+d] + cvc*W[(7*C_+c)*C_+d];
        bb += dvc*W[(4*C_+c)*C_+d] + rvc*W[(6*C_+c)*C_+d] + cvc*W[(8*C_+c)*C_+d];
        cc += dvc*W[(2*C_+c)*C_+d] + rvc*W[(9*C_+c)*C_+d] + cvc*W[(10*C_+c)*C_+d];
    }
    g_Vrow[o] = a; g_Vcol[o] = bb; g_Dd[o] = cc;
}

__global__ void k_pg(const float* __restrict__ W, const float* __restrict__ eqb,
                     const float* __restrict__ eqbd) {
    int b = blockIdx.x, d = threadIdx.x;
    __shared__ float tt[C_], tg[C_];
    tt[d] = g_t[b*C_+d]; tg[d] = g_tr[b*C_+d];
    __syncthreads();
    float g = eqb[d], e = eqbd[d];
    for (int c = 0; c < C_; c++) {
        g += tt[c]*W[(11*C_+c)*C_+d] + tg[c]*W[(13*C_+c)*C_+d];
        e += tt[c]*W[(12*C_+c)*C_+d] + tg[c]*W[(14*C_+c)*C_+d];
    }
    g_G[b*C_+d] = g; g_E[b*C_+d] = e;
}

__global__ void k_zero() {
    int idx = blockIdx.x*blockDim.x + threadIdx.x;
    if (idx < B_*C_) { g_dg[idx] = 0.f; g_tot[idx] = 0.f; }
}

__global__ void k_out(const float* __restrict__ w20, const float* __restrict__ b20,
                      const float* __restrict__ wmlp, const float* __restrict__ bmlp,
                      float* __restrict__ out) {
    int b = blockIdx.x, d = threadIdx.x;
    __shared__ float a0[C_], a1[C_], act[C_];
    a0[d] = lrelu(g_dg[b*C_+d] / AVGF);
    a1[d] = lrelu(g_tot[b*C_+d] / (AVGF*AVGF));
    __syncthreads();
    float a = b20[d];
    for (int c = 0; c < C_; c++) a += a0[c]*w20[c*C_+d] + a1[c]*w20[(C_+c)*C_+d];
    act[d] = a;
    __syncthreads();
    if (d < 2) {
        float o = bmlp[d];
        for (int k = 0; k < C_; k++) o += act[k]*wmlp[k*2+d];
        out[b*2+d] = o;
    }
}

// ---------------- host ----------------
extern "C" void kernel_launch(void* const* d_in, const int* in_sizes, int n_in,
                              void* d_out, int out_size) {
    const float *momenta=0, *scalars=0, *w_lin=0, *alpha=0, *w_in=0, *b_in=0;
    const int* nobj=0;
    const float *msgw[4], *msgb[4], *eqw[4], *eqb[4], *eqbd[4];
    const float *wm0=0, *bm0=0, *w20=0, *b20=0, *wmlp=0, *bmlp=0;

    if (n_in >= 33 && in_sizes[0] == 8192) {
        momenta=(const float*)d_in[0]; scalars=(const float*)d_in[1]; nobj=(const int*)d_in[2];
        w_lin=(const float*)d_in[3]; alpha=(const float*)d_in[4]; w_in=(const float*)d_in[5];
        b_in=(const float*)d_in[6];
        for (int l = 0; l < 4; l++) {
            msgw[l]=(const float*)d_in[7+l];  msgb[l]=(const float*)d_in[11+l];
            eqw[l] =(const float*)d_in[15+l]; eqb[l] =(const float*)d_in[19+l];
            eqbd[l]=(const float*)d_in[23+l];
        }
        wm0=(const float*)d_in[27]; bm0=(const float*)d_in[28]; w20=(const float*)d_in[29];
        b20=(const float*)d_in[30]; wmlp=(const float*)d_in[31]; bmlp=(const float*)d_in[32];
    } else if (n_in >= 33) {
        alpha=(const float*)d_in[0]; b20=(const float*)d_in[1]; b_in=(const float*)d_in[2];
        bm0=(const float*)d_in[3]; bmlp=(const float*)d_in[4];
        for (int l = 0; l < 4; l++) {
            eqb[l] =(const float*)d_in[5+l];  eqbd[l]=(const float*)d_in[9+l];
            eqw[l] =(const float*)d_in[13+l]; msgb[l]=(const float*)d_in[18+l];
            msgw[l]=(const float*)d_in[22+l];
        }
        momenta=(const float*)d_in[17]; nobj=(const int*)d_in[26]; scalars=(const float*)d_in[27];
        w20=(const float*)d_in[28]; w_in=(const float*)d_in[29]; w_lin=(const float*)d_in[30];
        wm0=(const float*)d_in[31]; wmlp=(const float*)d_in[32];
    } else {
        momenta=(const float*)d_in[0]; scalars=(const float*)d_in[1]; nobj=(const int*)d_in[2];
        w_lin=(const float*)d_in[3]; alpha=(const float*)d_in[4]; w_in=(const float*)d_in[5];
        b_in=(const float*)d_in[6];
        for (int l = 0; l < 4; l++) {
            msgw[l]=(const float*)d_in[7]+(size_t)l*C_*C_;     msgb[l]=(const float*)d_in[8]+(size_t)l*C_;
            eqw[l] =(const float*)d_in[9]+(size_t)l*15*C_*C_;  eqb[l] =(const float*)d_in[10]+(size_t)l*C_;
            eqbd[l]=(const float*)d_in[11]+(size_t)l*C_;
        }
        wm0=(const float*)d_in[12]; bm0=(const float*)d_in[13]; w20=(const float*)d_in[14];
        b20=(const float*)d_in[15]; wmlp=(const float*)d_in[16]; bmlp=(const float*)d_in[17];
    }

    cudaFuncSetAttribute(k_gemm, cudaFuncAttributeMaxDynamicSharedMemorySize, SM_GEMM);

    float *Tp=0, *Up=0;
    cudaGetSymbolAddress((void**)&Tp, g_T);
    cudaGetSymbolAddress((void**)&Up, g_U);
    __nv_bfloat16 *WmH=0, *WmL=0, *WeH=0, *WeL=0, *WfH=0, *WfL=0;
    cudaGetSymbolAddress((void**)&WmH, g_WmsgHi);
    cudaGetSymbolAddress((void**)&WmL, g_WmsgLo);
    cudaGetSymbolAddress((void**)&WeH, g_WeqHi);
    cudaGetSymbolAddress((void**)&WeL, g_WeqLo);
    cudaGetSymbolAddress((void**)&WfH, g_WfinHi);
    cudaGetSymbolAddress((void**)&WfL, g_WfinLo);

    k_wsplit<<<13, 256>>>(msgw[0], msgw[1], msgw[2], msgw[3],
                          eqw[0], eqw[1], eqw[2], eqw[3], wm0);
    k_prep<<<B_, 256>>>(scalars, nobj, w_in);
    k_init<<<B_*N_, 128>>>(momenta, nobj, w_lin, alpha, b_in);

    for (int l = 0; l < 4; l++) {
        k_gemm<<<TILES, 256, SM_GEMM>>>(Tp, WmH + l*16384, WmL + l*16384, msgb[l], nobj, 0);
        k_r1<<<B_*N_, 128>>>();
        k_r2<<<B_, 128>>>();
        k_p<<<B_*N_, 128>>>(eqw[l]);
        k_pg<<<B_, 128>>>(eqw[l], eqb[l], eqbd[l]);
        k_gemm<<<TILES, 256, SM_GEMM>>>(Up, WeH + (l*2+1)*16384, WeL + (l*2+1)*16384, msgb[l], nobj, 2);
        k_gemm<<<TILES, 256, SM_GEMM>>>(Up, WeH + (l*2+0)*16384, WeL + (l*2+0)*16384, msgb[l], nobj, 1);
    }

    k_zero<<<(B_*C_ + 255)/256, 256>>>();
    k_gemm<<<TILES, 256, SM_GEMM>>>(Tp, WfH, WfL, bm0, nobj, 3);
    k_out<<<B_, 128>>>(w20, b20, wmlp, bmlp, (float*)d_out);
}

// round 7
// speedup vs baseline: 2.3162x; 1.1622x over previous
#include <cuda_runtime.h>
#include <cuda_bf16.h>
#include <math.h>
#include <stdint.h>

#define B_  32
#define N_  64
#define S_  9
#define C_  128
#define CS_ 32
#define AVGF 49.0f
#define TILES (B_*32)   // 1024 tiles of 128 rows; tile=(b, i-pair), row=(i&1)*64+j

// ---------------- device scratch ----------------
__device__ float g_T[B_*N_*N_*C_];
__device__ float g_U[B_*N_*N_*C_];
__device__ float g_X[B_*N_*384];          // [m=b*64+i][dvec|rvec|cvec]
__device__ __nv_bfloat16 g_WmsgHi[4*16384], g_WmsgLo[4*16384];
__device__ __nv_bfloat16 g_WeqHi[8*16384],  g_WeqLo[8*16384];   // [l][which][n][k]
__device__ __nv_bfloat16 g_WfinHi[16384],   g_WfinLo[16384];
__device__ __nv_bfloat16 g_WpHi[4*147456],  g_WpLo[4*147456];   // [l][p][n][384k]
__device__ float g_y012[B_*N_*3*CS_];
__device__ float g_y34[B_*2*CS_];
__device__ float g_Vrow[B_*N_*C_];
__device__ float g_Vcol[B_*N_*C_];
__device__ float g_Dd[B_*N_*C_];
__device__ float g_G[B_*C_];
__device__ float g_E[B_*C_];
__device__ float g_t[B_*C_];
__device__ float g_tr[B_*C_];
__device__ float g_dg[B_*C_];
__device__ float g_tot[B_*C_];

__device__ __forceinline__ float lrelu(float x){ return x >= 0.f ? x : 0.01f*x; }
__device__ __forceinline__ uint32_t smem_u32(const void* p) {
    uint32_t a;
    asm("{ .reg .u64 t; cvta.to.shared.u64 t, %1; cvt.u32.u64 %0, t; }" : "=r"(a) : "l"(p));
    return a;
}
__device__ __forceinline__ void split2(float v, __nv_bfloat16& h, __nv_bfloat16& l) {
    h = __float2bfloat16(v);
    l = __float2bfloat16(v - __bfloat162float(h));
}
__device__ __forceinline__ void ldmx4(uint32_t a, uint32_t& r0, uint32_t& r1, uint32_t& r2, uint32_t& r3) {
    asm volatile("ldmatrix.sync.aligned.m8n8.x4.shared.b16 {%0,%1,%2,%3}, [%4];"
                 : "=r"(r0), "=r"(r1), "=r"(r2), "=r"(r3) : "r"(a));
}
__device__ __forceinline__ void mma16816(float* c, const uint32_t* a, uint32_t b0, uint32_t b1) {
    asm volatile("mma.sync.aligned.m16n8k16.row.col.f32.bf16.bf16.f32 "
                 "{%0,%1,%2,%3}, {%4,%5,%6,%7}, {%8,%9}, {%0,%1,%2,%3};"
                 : "+f"(c[0]), "+f"(c[1]), "+f"(c[2]), "+f"(c[3])
                 : "r"(a[0]), "r"(a[1]), "r"(a[2]), "r"(a[3]), "r"(b0), "r"(b1));
}

// smem geometry (K=64 per staged phase)
#define APAD 72
#define BPAD 80
#define AH_OFF 0
#define AL_OFF 18432
#define BH_OFF 36864
#define BL_OFF 57344
#define SM_GEMM 77824

// ---------------- weight split: col-major [n][k] bf16 hi/lo ----------------
__global__ void k_wsplit(const float* __restrict__ m0, const float* __restrict__ m1,
                         const float* __restrict__ m2, const float* __restrict__ m3,
                         const float* __restrict__ e0, const float* __restrict__ e1,
                         const float* __restrict__ e2, const float* __restrict__ e3,
                         const float* __restrict__ wfin) {
    int blk = blockIdx.x, tid = threadIdx.x;
    const float* W; __nv_bfloat16 *Hi, *Lo;
    if (blk < 4) {
        W = (blk==0)?m0:(blk==1)?m1:(blk==2)?m2:m3;
        Hi = g_WmsgHi + blk*16384; Lo = g_WmsgLo + blk*16384;
    } else if (blk < 12) {
        int l = (blk-4)>>1, which = (blk-4)&1;
        const float* E = (l==0)?e0:(l==1)?e1:(l==2)?e2:e3;
        W = E + which*16384;
        Hi = g_WeqHi + (l*2+which)*16384; Lo = g_WeqLo + (l*2+which)*16384;
    } else {
        W = wfin; Hi = g_WfinHi; Lo = g_WfinLo;
    }
    for (int e = tid; e < 16384; e += 256) {
        int n = e>>7, k = e&127;
        __nv_bfloat16 h, l;
        split2(W[k*C_ + n], h, l);
        Hi[e] = h; Lo[e] = l;
    }
}

// proj weights: [l][p][n][384] with k-chunks mapping to eq mats
__global__ void k_wsplit2(const float* __restrict__ e0, const float* __restrict__ e1,
                          const float* __restrict__ e2, const float* __restrict__ e3) {
    int l = blockIdx.x / 3, p = blockIdx.x % 3, tid = threadIdx.x;
    const int tbl[3][3] = {{3,5,7},{4,6,8},{2,9,10}};
    const float* E = (l==0)?e0:(l==1)?e1:(l==2)?e2:e3;
    __nv_bfloat16* Hi = g_WpHi + (size_t)l*147456 + p*49152;
    __nv_bfloat16* Lo = g_WpLo + (size_t)l*147456 + p*49152;
    for (int e = tid; e < 49152; e += 256) {
        int n = e / 384, k = e % 384;
        int mat = tbl[p][k>>7], kk = k&127;
        __nv_bfloat16 h, lo;
        split2(E[(mat*C_ + kk)*C_ + n], h, lo);
        Hi[n*384 + k] = h; Lo[n*384 + k] = lo;
    }
}

// ---------------- main GEMM ----------------
// modes: 0 = U = lrelu(T@W + b)*mask
//        1 = T = lrelu(U@W0 + UT@W1 + Vrow+G+Vcol (+Dd+E diag))*mask  [dual-source accumulate]
//        3 = final: lrelu(acc+bias)*mask -> trace/total reduction
__global__ void __launch_bounds__(256, 2) k_gemm(const float* __restrict__ A,
                                                 const __nv_bfloat16* __restrict__ Bhi,
                                                 const __nv_bfloat16* __restrict__ Blo,
                                                 const __nv_bfloat16* __restrict__ Bhi2,
                                                 const __nv_bfloat16* __restrict__ Blo2,
                                                 const float* __restrict__ bias,
                                                 const int* __restrict__ nobj, int mode) {
    extern __shared__ unsigned char sm[];
    uint32_t sb = smem_u32(sm);
    int tid = threadIdx.x, wid = tid>>5, lane = tid&31;
    int tile = blockIdx.x;
    int b = tile>>5, i0 = (tile&31)<<1;

    int wy = wid&3, wx = wid>>2;
    int rb = wy*32, nb0 = wx*64;
    float c[2][8][4];
    #pragma unroll
    for (int mt = 0; mt < 2; mt++)
        #pragma unroll
        for (int nt = 0; nt < 8; nt++)
            #pragma unroll
            for (int q = 0; q < 4; q++) c[mt][nt][q] = 0.f;

    int lrow = (lane&7) + ((lane>>3)&1)*8;
    int lcolb = ((lane>>4)&1)*16;
    int bn = nb0 + (lane>>2);
    int btid4 = (lane&3)*4;

    int nsrc = (mode == 1) ? 2 : 1;
    for (int src = 0; src < nsrc; src++) {
        const uint32_t* bhp = (const uint32_t*)(src ? Bhi2 : Bhi);
        const uint32_t* blp = (const uint32_t*)(src ? Blo2 : Blo);
        for (int ph = 0; ph < 2; ph++) {
            if (src | ph) __syncthreads();
            // stage A half
            {
                #pragma unroll
                for (int u = 0; u < 8; u++) {
                    int f = tid + 256*u;
                    int row = f>>4, q = f&15, c4 = q*4;
                    float4 v;
                    if (src == 0) {
                        v = ((const float4*)(A + (size_t)tile*16384))[row*32 + ph*16 + q];
                    } else {
                        int jj = row & 63, hh = row >> 6;
                        const float4* s4 = (const float4*)(g_U +
                            ((size_t)(b*32 + (jj>>1))*128 + (jj&1)*64 + (i0+hh))*128);
                        v = s4[ph*16 + q];
                    }
                    __nv_bfloat16 h[4], l[4];
                    split2(v.x, h[0], l[0]); split2(v.y, h[1], l[1]);
                    split2(v.z, h[2], l[2]); split2(v.w, h[3], l[3]);
                    *(uint2*)(sm + AH_OFF + (row*APAD + c4)*2) = *(uint2*)h;
                    *(uint2*)(sm + AL_OFF + (row*APAD + c4)*2) = *(uint2*)l;
                }
            }
            // stage B half
            {
                #pragma unroll
                for (int u = 0; u < 16; u++) {
                    int f = tid + 256*u;
                    int n = f>>5, kp = f&31;
                    int k = kp*2;
                    int col = (k & ~15) + (((k>>1)&3)<<2) + (((k>>3)&1)<<1);
                    *(uint32_t*)(sm + BH_OFF + (n*BPAD + col)*2) = bhp[n*64 + ph*32 + kp];
                    *(uint32_t*)(sm + BL_OFF + (n*BPAD + col)*2) = blp[n*64 + ph*32 + kp];
                }
            }
            __syncthreads();
            #pragma unroll
            for (int ks = 0; ks < 4; ks++) {
                uint32_t ah[2][4], al[2][4];
                #pragma unroll
                for (int mt = 0; mt < 2; mt++) {
                    uint32_t adr = sb + AH_OFF + (rb + mt*16 + lrow)*APAD*2 + ks*32 + lcolb;
                    ldmx4(adr, ah[mt][0], ah[mt][1], ah[mt][2], ah[mt][3]);
                    adr = sb + AL_OFF + (rb + mt*16 + lrow)*APAD*2 + ks*32 + lcolb;
                    ldmx4(adr, al[mt][0], al[mt][1], al[mt][2], al[mt][3]);
                }
                #pragma unroll
                for (int nt = 0; nt < 8; nt++) {
                    uint32_t bh0, bh1, bl0, bl1;
                    uint32_t badr = sb + BH_OFF + ((bn + nt*8)*BPAD + ks*16 + btid4)*2;
                    asm volatile("ld.shared.v2.b32 {%0,%1}, [%2];" : "=r"(bh0), "=r"(bh1) : "r"(badr));
                    badr = sb + BL_OFF + ((bn + nt*8)*BPAD + ks*16 + btid4)*2;
                    asm volatile("ld.shared.v2.b32 {%0,%1}, [%2];" : "=r"(bl0), "=r"(bl1) : "r"(badr));
                    #pragma unroll
                    for (int mt = 0; mt < 2; mt++) {
                        mma16816(c[mt][nt], ah[mt], bh0, bh1);
                        mma16816(c[mt][nt], ah[mt], bl0, bl1);
                        mma16816(c[mt][nt], al[mt], bh0, bh1);
                    }
                }
            }
        }
    }

    // ---------------- epilogues ----------------
    int nb = nobj[b];
    int g = lane>>2, t2 = (lane&3)*2;
    if (mode == 0) {
        float* Out = g_U + (size_t)tile*16384;
        #pragma unroll
        for (int mt = 0; mt < 2; mt++) {
            #pragma unroll
            for (int h = 0; h < 2; h++) {
                int row = rb + mt*16 + g + h*8;
                int i = i0 + (row>>6), j = row&63;
                float mask = (i < nb && j < nb) ? 1.f : 0.f;
                #pragma unroll
                for (int nt = 0; nt < 8; nt++) {
                    int col = nb0 + nt*8 + t2;
                    float2 v;
                    v.x = lrelu(c[mt][nt][h*2+0] + bias[col])   * mask;
                    v.y = lrelu(c[mt][nt][h*2+1] + bias[col+1]) * mask;
                    *(float2*)(Out + row*128 + col) = v;
                }
            }
        }
    } else if (mode == 1) {
        float* Out = g_T + (size_t)tile*16384;
        #pragma unroll
        for (int mt = 0; mt < 2; mt++) {
            #pragma unroll
            for (int h = 0; h < 2; h++) {
                int row = rb + mt*16 + g + h*8;
                int i = i0 + (row>>6), j = row&63;
                float mask = (i < nb && j < nb) ? 1.f : 0.f;
                bool diag = (i == j);
                const float* vr = g_Vrow + (b*64+i)*C_;
                const float* vc = g_Vcol + (b*64+j)*C_;
                const float* gg = g_G + b*C_;
                const float* dd = g_Dd + (b*64+i)*C_;
                const float* ee = g_E + b*C_;
                #pragma unroll
                for (int nt = 0; nt < 8; nt++) {
                    int col = nb0 + nt*8 + t2;
                    float vx = c[mt][nt][h*2+0] + vr[col]   + gg[col]   + vc[col];
                    float vy = c[mt][nt][h*2+1] + vr[col+1] + gg[col+1] + vc[col+1];
                    if (diag) {
                        vx += dd[col]   + ee[col];
                        vy += dd[col+1] + ee[col+1];
                    }
                    float2 o;
                    o.x = lrelu(vx) * mask;
                    o.y = lrelu(vy) * mask;
                    *(float2*)(Out + row*128 + col) = o;
                }
            }
        }
    } else {
        __syncthreads();
        float* Vs = (float*)sm;   // [128][132]
        #pragma unroll
        for (int mt = 0; mt < 2; mt++) {
            #pragma unroll
            for (int h = 0; h < 2; h++) {
                int row = rb + mt*16 + g + h*8;
                int i = i0 + (row>>6), j = row&63;
                float mask = (i < nb && j < nb) ? 1.f : 0.f;
                #pragma unroll
                for (int nt = 0; nt < 8; nt++) {
                    int col = nb0 + nt*8 + t2;
                    float2 v;
                    v.x = lrelu(c[mt][nt][h*2+0] + bias[col])   * mask;
                    v.y = lrelu(c[mt][nt][h*2+1] + bias[col+1]) * mask;
                    *(float2*)(Vs + row*132 + col) = v;
                }
            }
        }
        __syncthreads();
        if (tid < 128) {
            float s = 0.f;
            #pragma unroll 8
            for (int r = 0; r < 128; r++) s += Vs[r*132 + tid];
            atomicAdd(&g_tot[b*C_ + tid], s);
            float dgv = Vs[i0*132 + tid] + Vs[(64 + i0 + 1)*132 + tid];
            atomicAdd(&g_dg[b*C_ + tid], dgv);
        }
    }
}

// ---------------- projection GEMM: [Vrow|Vcol|Dd] = X @ Wp ----------------
__global__ void __launch_bounds__(256, 2) k_proj(const __nv_bfloat16* __restrict__ Bhi,
                                                 const __nv_bfloat16* __restrict__ Blo) {
    extern __shared__ unsigned char sm[];
    uint32_t sb = smem_u32(sm);
    int tid = threadIdx.x, wid = tid>>5, lane = tid&31;
    int p = blockIdx.x >> 4, tile = blockIdx.x & 15;

    int wy = wid&3, wx = wid>>2;
    int rb = wy*32, nb0 = wx*64;
    float c[2][8][4];
    #pragma unroll
    for (int mt = 0; mt < 2; mt++)
        #pragma unroll
        for (int nt = 0; nt < 8; nt++)
            #pragma unroll
            for (int q = 0; q < 4; q++) c[mt][nt][q] = 0.f;

    int lrow = (lane&7) + ((lane>>3)&1)*8;
    int lcolb = ((lane>>4)&1)*16;
    int bn = nb0 + (lane>>2);
    int btid4 = (lane&3)*4;
    const uint32_t* bhp = (const uint32_t*)(Bhi + p*49152);
    const uint32_t* blp = (const uint32_t*)(Blo + p*49152);
    const float4* Ag = (const float4*)(g_X + (size_t)tile*128*384);

    for (int ph = 0; ph < 6; ph++) {
        if (ph) __syncthreads();
        #pragma unroll
        for (int u = 0; u < 8; u++) {
            int f = tid + 256*u;
            int row = f>>4, q = f&15, c4 = q*4;
            float4 v = Ag[row*96 + ph*16 + q];
            __nv_bfloat16 h[4], l[4];
            split2(v.x, h[0], l[0]); split2(v.y, h[1], l[1]);
            split2(v.z, h[2], l[2]); split2(v.w, h[3], l[3]);
            *(uint2*)(sm + AH_OFF + (row*APAD + c4)*2) = *(uint2*)h;
            *(uint2*)(sm + AL_OFF + (row*APAD + c4)*2) = *(uint2*)l;
        }
        #pragma unroll
        for (int u = 0; u < 16; u++) {
            int f = tid + 256*u;
            int n = f>>5, kp = f&31;
            int k = kp*2;
            int col = (k & ~15) + (((k>>1)&3)<<2) + (((k>>3)&1)<<1);
            *(uint32_t*)(sm + BH_OFF + (n*BPAD + col)*2) = bhp[n*192 + ph*32 + kp];
            *(uint32_t*)(sm + BL_OFF + (n*BPAD + col)*2) = blp[n*192 + ph*32 + kp];
        }
        __syncthreads();
        #pragma unroll
        for (int ks = 0; ks < 4; ks++) {
            uint32_t ah[2][4], al[2][4];
            #pragma unroll
            for (int mt = 0; mt < 2; mt++) {
                uint32_t adr = sb + AH_OFF + (rb + mt*16 + lrow)*APAD*2 + ks*32 + lcolb;
                ldmx4(adr, ah[mt][0], ah[mt][1], ah[mt][2], ah[mt][3]);
                adr = sb + AL_OFF + (rb + mt*16 + lrow)*APAD*2 + ks*32 + lcolb;
                ldmx4(adr, al[mt][0], al[mt][1], al[mt][2], al[mt][3]);
            }
            #pragma unroll
            for (int nt = 0; nt < 8; nt++) {
                uint32_t bh0, bh1, bl0, bl1;
                uint32_t badr = sb + BH_OFF + ((bn + nt*8)*BPAD + ks*16 + btid4)*2;
                asm volatile("ld.shared.v2.b32 {%0,%1}, [%2];" : "=r"(bh0), "=r"(bh1) : "r"(badr));
                badr = sb + BL_OFF + ((bn + nt*8)*BPAD + ks*16 + btid4)*2;
                asm volatile("ld.shared.v2.b32 {%0,%1}, [%2];" : "=r"(bl0), "=r"(bl1) : "r"(badr));
                #pragma unroll
                for (int mt = 0; mt < 2; mt++) {
                    mma16816(c[mt][nt], ah[mt], bh0, bh1);
                    mma16816(c[mt][nt], ah[mt], bl0, bl1);
                    mma16816(c[mt][nt], al[mt], bh0, bh1);
                }
            }
        }
    }
    float* Out = (p==0) ? g_Vrow : (p==1) ? g_Vcol : g_Dd;
    int g = lane>>2, t2 = (lane&3)*2;
    #pragma unroll
    for (int mt = 0; mt < 2; mt++) {
        #pragma unroll
        for (int h = 0; h < 2; h++) {
            int row = rb + mt*16 + g + h*8;
            int m = tile*128 + row;
            #pragma unroll
            for (int nt = 0; nt < 8; nt++) {
                int col = nb0 + nt*8 + t2;
                float2 v;
                v.x = c[mt][nt][h*2+0];
                v.y = c[mt][nt][h*2+1];
                *(float2*)(Out + (size_t)m*128 + col) = v;
            }
        }
    }
}

// ---------------- eq1to2 prep ----------------
__global__ void k_prep(const float* __restrict__ scalars, const int* __restrict__ nobj,
                       const float* __restrict__ w_in) {
    int b = blockIdx.x;
    __shared__ float xs[N_][S_];
    __shared__ float ssum[S_];
    int nb = nobj[b];
    for (int idx = threadIdx.x; idx < N_*S_; idx += blockDim.x) {
        int n = idx/S_, s = idx%S_;
        xs[n][s] = (n < nb) ? scalars[(b*N_+n)*S_+s] : 0.f;
    }
    __syncthreads();
    if (threadIdx.x < S_) {
        float a = 0.f;
        for (int n = 0; n < N_; n++) a += xs[n][threadIdx.x];
        ssum[threadIdx.x] = a / AVGF;
    }
    __syncthreads();
    for (int idx = threadIdx.x; idx < N_*CS_; idx += blockDim.x) {
        int n = idx/CS_, c = idx%CS_;
        float a0=0, a1=0, a2=0;
        #pragma unroll
        for (int s = 0; s < S_; s++) {
            float xv = xs[n][s];
            a0 += xv*w_in[(0*S_+s)*CS_+c];
            a1 += xv*w_in[(1*S_+s)*CS_+c];
            a2 += xv*w_in[(2*S_+s)*CS_+c];
        }
        g_y012[((b*N_+n)*3+0)*CS_+c] = a0;
        g_y012[((b*N_+n)*3+1)*CS_+c] = a1;
        g_y012[((b*N_+n)*3+2)*CS_+c] = a2;
    }
    if (threadIdx.x < 2*CS_) {
        int k = threadIdx.x/CS_, c = threadIdx.x%CS_;
        float a = 0.f;
        #pragma unroll
        for (int s = 0; s < S_; s++) a += ssum[s]*w_in[((3+k)*S_+s)*CS_+c];
        g_y34[(b*2+k)*CS_+c] = a;
    }
}

// ---------------- initial T (tile layout, fp32) ----------------
__global__ void k_init(const float* __restrict__ momenta, const int* __restrict__ nobj,
                       const float* __restrict__ w_lin, const float* __restrict__ alpha,
                       const float* __restrict__ b_in) {
    int b = blockIdx.x / N_, i = blockIdx.x % N_;
    int c = threadIdx.x;
    __shared__ float pm[N_][4];
    __shared__ float dij[N_];
    __shared__ float y1s[N_][CS_];
    __shared__ float y0r[CS_], y2r[CS_], y3s[CS_], y4s[CS_];
    for (int idx = c; idx < N_*4; idx += 128) pm[idx/4][idx%4] = momenta[(b*N_)*4 + idx];
    for (int idx = c; idx < N_*CS_; idx += 128) {
        int n = idx/CS_, cs = idx%CS_;
        y1s[n][cs] = g_y012[((b*N_+n)*3+1)*CS_+cs];
    }
    if (c < CS_) {
        y0r[c] = g_y012[((b*N_+i)*3+0)*CS_+c];
        y2r[c] = g_y012[((b*N_+i)*3+2)*CS_+c];
        y3s[c] = g_y34[(b*2+0)*CS_+c];
        y4s[c] = g_y34[(b*2+1)*CS_+c];
    }
    __syncthreads();
    if (c < N_)
        dij[c] = pm[i][0]*pm[c][0] - pm[i][1]*pm[c][1] - pm[i][2]*pm[c][2] - pm[i][3]*pm[c][3];
    __syncthreads();
    int nb = nobj[b];
    float mi = (i < nb) ? 1.f : 0.f;
    float base = 0.f, wl = 0.f, al = 0.f;
    if (c < CS_) base = y0r[c] + y3s[c] + b_in[c];
    else { wl = w_lin[c-CS_]; al = alpha[c-CS_]; }
    size_t rowbase = ((size_t)(b*32 + (i>>1))*128 + (i&1)*64)*128;
    for (int j = 0; j < N_; j++) {
        float mask = mi * ((j < nb) ? 1.f : 0.f);
        float v;
        if (c < CS_) {
            v = base + y1s[j][c];
            if (j == i) v += y2r[c] + y4s[c];
            v = lrelu(v) * mask;
        } else {
            float r = dij[j] * wl;
            v = al * copysignf(log1pf(fabsf(r)), r) * mask;
        }
        g_T[rowbase + j*128 + c] = v;
    }
}

// ---------------- reductions from U -> X ----------------
__global__ void k_r1() {
    int b = blockIdx.x >> 6, i = blockIdx.x & 63;
    int c = threadIdx.x;
    size_t rbase = ((size_t)(b*32 + (i>>1))*128 + (i&1)*64)*128 + c;
    float rs = 0.f, cs = 0.f;
    for (int j = 0; j < N_; j++) rs += g_U[rbase + j*128];
    for (int ii = 0; ii < N_; ii++)
        cs += g_U[((size_t)(b*32 + (ii>>1))*128 + (ii&1)*64 + i)*128 + c];
    size_t m = (size_t)(b*N_+i);
    g_X[m*384 + c]       = g_U[rbase + i*128];
    g_X[m*384 + 128 + c] = rs / AVGF;
    g_X[m*384 + 256 + c] = cs / AVGF;
}

__global__ void k_r2() {
    int b = blockIdx.x, c = threadIdx.x;
    float t = 0.f, tr = 0.f;
    for (int i = 0; i < N_; i++) {
        size_t m = (size_t)(b*N_+i);
        t  += g_X[m*384 + 128 + c];
        tr += g_X[m*384 + c];
    }
    g_t[b*C_+c] = t/AVGF; g_tr[b*C_+c] = tr/AVGF;
}

__global__ void k_pg(const float* __restrict__ W, const float* __restrict__ eqb,
                     const float* __restrict__ eqbd) {
    int b = blockIdx.x, d = threadIdx.x;
    __shared__ float tt[C_], tg[C_];
    tt[d] = g_t[b*C_+d]; tg[d] = g_tr[b*C_+d];
    __syncthreads();
    float g = eqb[d], e = eqbd[d];
    for (int c = 0; c < C_; c++) {
        g += tt[c]*W[(11*C_+c)*C_+d] + tg[c]*W[(13*C_+c)*C_+d];
        e += tt[c]*W[(12*C_+c)*C_+d] + tg[c]*W[(14*C_+c)*C_+d];
    }
    g_G[b*C_+d] = g; g_E[b*C_+d] = e;
}

__global__ void k_zero() {
    int idx = blockIdx.x*blockDim.x + threadIdx.x;
    if (idx < B_*C_) { g_dg[idx] = 0.f; g_tot[idx] = 0.f; }
}

__global__ void k_out(const float* __restrict__ w20, const float* __restrict__ b20,
                      const float* __restrict__ wmlp, const float* __restrict__ bmlp,
                      float* __restrict__ out) {
    int b = blockIdx.x, d = threadIdx.x;
    __shared__ float a0[C_], a1[C_], act[C_];
    a0[d] = lrelu(g_dg[b*C_+d] / AVGF);
    a1[d] = lrelu(g_tot[b*C_+d] / (AVGF*AVGF));
    __syncthreads();
    float a = b20[d];
    for (int c = 0; c < C_; c++) a += a0[c]*w20[c*C_+d] + a1[c]*w20[(C_+c)*C_+d];
    act[d] = a;
    __syncthreads();
    if (d < 2) {
        float o = bmlp[d];
        for (int k = 0; k < C_; k++) o += act[k]*wmlp[k*2+d];
        out[b*2+d] = o;
    }
}

// ---------------- host ----------------
extern "C" void kernel_launch(void* const* d_in, const int* in_sizes, int n_in,
                              void* d_out, int out_size) {
    const float *momenta=0, *scalars=0, *w_lin=0, *alpha=0, *w_in=0, *b_in=0;
    const int* nobj=0;
    const float *msgw[4], *msgb[4], *eqw[4], *eqb[4], *eqbd[4];
    const float *wm0=0, *bm0=0, *w20=0, *b20=0, *wmlp=0, *bmlp=0;

    if (n_in >= 33 && in_sizes[0] == 8192) {
        momenta=(const float*)d_in[0]; scalars=(const float*)d_in[1]; nobj=(const int*)d_in[2];
        w_lin=(const float*)d_in[3]; alpha=(const float*)d_in[4]; w_in=(const float*)d_in[5];
        b_in=(const float*)d_in[6];
        for (int l = 0; l < 4; l++) {
            msgw[l]=(const float*)d_in[7+l];  msgb[l]=(const float*)d_in[11+l];
            eqw[l] =(const float*)d_in[15+l]; eqb[l] =(const float*)d_in[19+l];
            eqbd[l]=(const float*)d_in[23+l];
        }
        wm0=(const float*)d_in[27]; bm0=(const float*)d_in[28]; w20=(const float*)d_in[29];
        b20=(const float*)d_in[30]; wmlp=(const float*)d_in[31]; bmlp=(const float*)d_in[32];
    } else if (n_in >= 33) {
        alpha=(const float*)d_in[0]; b20=(const float*)d_in[1]; b_in=(const float*)d_in[2];
        bm0=(const float*)d_in[3]; bmlp=(const float*)d_in[4];
        for (int l = 0; l < 4; l++) {
            eqb[l] =(const float*)d_in[5+l];  eqbd[l]=(const float*)d_in[9+l];
            eqw[l] =(const float*)d_in[13+l]; msgb[l]=(const float*)d_in[18+l];
            msgw[l]=(const float*)d_in[22+l];
        }
        momenta=(const float*)d_in[17]; nobj=(const int*)d_in[26]; scalars=(const float*)d_in[27];
        w20=(const float*)d_in[28]; w_in=(const float*)d_in[29]; w_lin=(const float*)d_in[30];
        wm0=(const float*)d_in[31]; wmlp=(const float*)d_in[32];
    } else {
        momenta=(const float*)d_in[0]; scalars=(const float*)d_in[1]; nobj=(const int*)d_in[2];
        w_lin=(const float*)d_in[3]; alpha=(const float*)d_in[4]; w_in=(const float*)d_in[5];
        b_in=(const float*)d_in[6];
        for (int l = 0; l < 4; l++) {
            msgw[l]=(const float*)d_in[7]+(size_t)l*C_*C_;     msgb[l]=(const float*)d_in[8]+(size_t)l*C_;
            eqw[l] =(const float*)d_in[9]+(size_t)l*15*C_*C_;  eqb[l] =(const float*)d_in[10]+(size_t)l*C_;
            eqbd[l]=(const float*)d_in[11]+(size_t)l*C_;
        }
        wm0=(const float*)d_in[12]; bm0=(const float*)d_in[13]; w20=(const float*)d_in[14];
        b20=(const float*)d_in[15]; wmlp=(const float*)d_in[16]; bmlp=(const float*)d_in[17];
    }

    cudaFuncSetAttribute(k_gemm, cudaFuncAttributeMaxDynamicSharedMemorySize, SM_GEMM);
    cudaFuncSetAttribute(k_proj, cudaFuncAttributeMaxDynamicSharedMemorySize, SM_GEMM);

    float *Tp=0, *Up=0;
    cudaGetSymbolAddress((void**)&Tp, g_T);
    cudaGetSymbolAddress((void**)&Up, g_U);
    __nv_bfloat16 *WmH=0, *WmL=0, *WeH=0, *WeL=0, *WfH=0, *WfL=0, *WpH=0, *WpL=0;
    cudaGetSymbolAddress((void**)&WmH, g_WmsgHi);
    cudaGetSymbolAddress((void**)&WmL, g_WmsgLo);
    cudaGetSymbolAddress((void**)&WeH, g_WeqHi);
    cudaGetSymbolAddress((void**)&WeL, g_WeqLo);
    cudaGetSymbolAddress((void**)&WfH, g_WfinHi);
    cudaGetSymbolAddress((void**)&WfL, g_WfinLo);
    cudaGetSymbolAddress((void**)&WpH, g_WpHi);
    cudaGetSymbolAddress((void**)&WpL, g_WpLo);

    k_wsplit<<<13, 256>>>(msgw[0], msgw[1], msgw[2], msgw[3],
                          eqw[0], eqw[1], eqw[2], eqw[3], wm0);
    k_wsplit2<<<12, 256>>>(eqw[0], eqw[1], eqw[2], eqw[3]);
    k_prep<<<B_, 256>>>(scalars, nobj, w_in);
    k_init<<<B_*N_, 128>>>(momenta, nobj, w_lin, alpha, b_in);

    for (int l = 0; l < 4; l++) {
        k_gemm<<<TILES, 256, SM_GEMM>>>(Tp, WmH + l*16384, WmL + l*16384,
                                        (const __nv_bfloat16*)0, (const __nv_bfloat16*)0,
                                        msgb[l], nobj, 0);
        k_r1<<<B_*N_, 128>>>();
        k_r2<<<B_, 128>>>();
        k_proj<<<48, 256, SM_GEMM>>>(WpH + (size_t)l*147456, WpL + (size_t)l*147456);
        k_pg<<<B_, 128>>>(eqw[l], eqb[l], eqbd[l]);
        k_gemm<<<TILES, 256, SM_GEMM>>>(Up, WeH + (l*2+0)*16384, WeL + (l*2+0)*16384,
                                        WeH + (l*2+1)*16384, WeL + (l*2+1)*16384,
                                        msgb[l], nobj, 1);
    }

    k_zero<<<(B_*C_ + 255)/256, 256>>>();
    k_gemm<<<TILES, 256, SM_GEMM>>>(Tp, WfH, WfL,
                                    (const __nv_bfloat16*)0, (const __nv_bfloat16*)0,
                                    bm0, nobj, 3);
    k_out<<<B_, 128>>>(w20, b20, wmlp, bmlp, (float*)d_out);
}

// round 8
// speedup vs baseline: 2.5102x; 1.0838x over previous
#include <cuda_runtime.h>
#include <cuda_bf16.h>
#include <math.h>
#include <stdint.h>

#define B_  32
#define N_  64
#define S_  9
#define C_  128
#define CS_ 32
#define AVGF 49.0f
#define TILES (B_*32)   // 1024 tiles of 128 rows; tile=(b, i-pair), row=(i&1)*64+j

// ---------------- device scratch ----------------
__device__ __nv_bfloat16 g_Thi[TILES*16384], g_Tlo[TILES*16384];
__device__ __nv_bfloat16 g_Uhi[TILES*16384], g_Ulo[TILES*16384];
__device__ float g_X[B_*N_*384];          // [m=b*64+i][dvec|rvec|cvec]
__device__ uint4 g_Bf[13*4096];           // B fragments: [mat][wx][ks][nt][lane] = {b0h,b1h,b0l,b1l}
__device__ __nv_bfloat16 g_WpHi[4*147456], g_WpLo[4*147456];   // proj weights [l][p][n][384k]
__device__ float g_y012[B_*N_*3*CS_];
__device__ float g_y34[B_*2*CS_];
__device__ float g_Vrow[B_*N_*C_];
__device__ float g_Vcol[B_*N_*C_];
__device__ float g_Dd[B_*N_*C_];
__device__ float g_G[B_*C_];
__device__ float g_E[B_*C_];
__device__ float g_t[B_*C_];
__device__ float g_tr[B_*C_];
__device__ float g_dg[B_*C_];
__device__ float g_tot[B_*C_];

__device__ __forceinline__ float lrelu(float x){ return x >= 0.f ? x : 0.01f*x; }
__device__ __forceinline__ uint32_t smem_u32(const void* p) {
    uint32_t a;
    asm("{ .reg .u64 t; cvta.to.shared.u64 t, %1; cvt.u32.u64 %0, t; }" : "=r"(a) : "l"(p));
    return a;
}
__device__ __forceinline__ void split2(float v, __nv_bfloat16& h, __nv_bfloat16& l) {
    h = __float2bfloat16(v);
    l = __float2bfloat16(v - __bfloat162float(h));
}
__device__ __forceinline__ uint32_t packbf(__nv_bfloat16 a, __nv_bfloat16 b) {
    __nv_bfloat162 p; p.x = a; p.y = b;
    return *(uint32_t*)&p;
}
__device__ __forceinline__ void ldmx4(uint32_t a, uint32_t& r0, uint32_t& r1, uint32_t& r2, uint32_t& r3) {
    asm volatile("ldmatrix.sync.aligned.m8n8.x4.shared.b16 {%0,%1,%2,%3}, [%4];"
                 : "=r"(r0), "=r"(r1), "=r"(r2), "=r"(r3) : "r"(a));
}
__device__ __forceinline__ void mma16816(float* c, const uint32_t* a, uint32_t b0, uint32_t b1) {
    asm volatile("mma.sync.aligned.m16n8k16.row.col.f32.bf16.bf16.f32 "
                 "{%0,%1,%2,%3}, {%4,%5,%6,%7}, {%8,%9}, {%0,%1,%2,%3};"
                 : "+f"(c[0]), "+f"(c[1]), "+f"(c[2]), "+f"(c[3])
                 : "r"(a[0]), "r"(a[1]), "r"(a[2]), "r"(a[3]), "r"(b0), "r"(b1));
}
#define CPA16(dst, src) asm volatile("cp.async.ca.shared.global [%0], [%1], 16;" :: "r"(dst), "l"(src))
#define CPCOMMIT() asm volatile("cp.async.commit_group;" ::: "memory")
#define CPWAIT()   asm volatile("cp.async.wait_group 0;"  ::: "memory")

// k_gemm smem: A hi [128][136] bf16 + A lo [128][136] bf16 = 69632 B
#define AROW2 136          // elements; 272B row stride (16B-multiple, conflict-free)
#define ALO2  34816
#define SM_G  69632
// k_proj smem (old layout)
#define APAD 72
#define BPAD 80
#define AH_OFF 0
#define AL_OFF 18432
#define BH_OFF 36864
#define BL_OFF 57344
#define SM_P 77824

// ---------------- B fragment pack: [mat][wx][ks][nt][lane] ----------------
__global__ void k_wsplitF(const float* __restrict__ m0, const float* __restrict__ m1,
                          const float* __restrict__ m2, const float* __restrict__ m3,
                          const float* __restrict__ e0, const float* __restrict__ e1,
                          const float* __restrict__ e2, const float* __restrict__ e3,
                          const float* __restrict__ wfin) {
    int mat = blockIdx.x, tid = threadIdx.x;
    const float* W;
    if (mat < 4)       W = (mat==0)?m0:(mat==1)?m1:(mat==2)?m2:m3;
    else if (mat < 12) {
        int l = (mat-4)>>1, wh = (mat-4)&1;
        const float* E = (l==0)?e0:(l==1)?e1:(l==2)?e2:e3;
        W = E + wh*16384;
    } else W = wfin;
    uint4* dst = g_Bf + mat*4096;
    for (int e = tid; e < 4096; e += 256) {
        int lane = e&31, nt = (e>>5)&7, ks = (e>>8)&7, wx = e>>11;
        int n = wx*64 + nt*8 + (lane>>2);
        int k0 = ks*16 + (lane&3)*2;
        __nv_bfloat16 h00,l00,h01,l01,h10,l10,h11,l11;
        split2(W[k0*128+n],     h00, l00);
        split2(W[(k0+1)*128+n], h01, l01);
        split2(W[(k0+8)*128+n], h10, l10);
        split2(W[(k0+9)*128+n], h11, l11);
        uint4 o;
        o.x = packbf(h00,h01); o.y = packbf(h10,h11);
        o.z = packbf(l00,l01); o.w = packbf(l10,l11);
        dst[e] = o;
    }
}

// proj weights: [l][p][n][384] with k-chunks mapping to eq mats
__global__ void k_wsplit2(const float* __restrict__ e0, const float* __restrict__ e1,
                          const float* __restrict__ e2, const float* __restrict__ e3) {
    int l = blockIdx.x / 3, p = blockIdx.x % 3, tid = threadIdx.x;
    const int tbl[3][3] = {{3,5,7},{4,6,8},{2,9,10}};
    const float* E = (l==0)?e0:(l==1)?e1:(l==2)?e2:e3;
    __nv_bfloat16* Hi = g_WpHi + (size_t)l*147456 + p*49152;
    __nv_bfloat16* Lo = g_WpLo + (size_t)l*147456 + p*49152;
    for (int e = tid; e < 49152; e += 256) {
        int n = e / 384, k = e % 384;
        int mat = tbl[p][k>>7], kk = k&127;
        __nv_bfloat16 h, lo;
        split2(E[(mat*C_ + kk)*C_ + n], h, lo);
        Hi[n*384 + k] = h; Lo[n*384 + k] = lo;
    }
}

// ---------------- main GEMM: A bf16 hi/lo via cp.async, B fragments from global --------
// modes: 0 = U = lrelu(acc+bias)*mask (bf16 split store)
//        1 = T = lrelu(U@W0 + UT@W1 + Vrow+G+Vcol (+Dd+E diag))*mask (bf16 split store)
//        3 = final: lrelu(acc+bias)*mask -> trace/total reduction
__global__ void __launch_bounds__(256, 2) k_gemm(const __nv_bfloat16* __restrict__ Ahi,
                                                 const __nv_bfloat16* __restrict__ Alo,
                                                 const uint4* __restrict__ F0,
                                                 const uint4* __restrict__ F1,
                                                 const float* __restrict__ bias,
                                                 const int* __restrict__ nobj, int mode) {
    extern __shared__ unsigned char sm[];
    uint32_t sb = smem_u32(sm);
    int tid = threadIdx.x, wid = tid>>5, lane = tid&31;
    int tile = blockIdx.x;
    int b = tile>>5, i0 = (tile&31)<<1;

    int wy = wid&3, wx = wid>>2;
    int rb = wy*32, nb0 = wx*64;
    float c[2][8][4];
    #pragma unroll
    for (int mt = 0; mt < 2; mt++)
        #pragma unroll
        for (int nt = 0; nt < 8; nt++)
            #pragma unroll
            for (int q = 0; q < 4; q++) c[mt][nt][q] = 0.f;

    int lrow = (lane&7) + ((lane>>3)&1)*8;
    int lcolb = ((lane>>4)&1)*16;

    int nsrc = (mode == 1) ? 2 : 1;
    for (int src = 0; src < nsrc; src++) {
        if (src) __syncthreads();   // prior compute must finish before restage
        #pragma unroll
        for (int u = 0; u < 16; u++) {
            int f = tid + 256*u;
            int comp = f>>11, rem = f&2047, row = rem>>4, c16 = rem&15;
            const __nv_bfloat16* basep = comp ? Alo : Ahi;
            size_t goff;
            if (src == 0) {
                goff = (size_t)tile*16384 + row*128 + c16*8;
            } else {
                int jj = row&63, hh = row>>6;
                goff = ((size_t)(b*32 + (jj>>1))*128 + (jj&1)*64 + i0 + hh)*128 + c16*8;
            }
            uint32_t dst = sb + comp*ALO2 + row*272 + c16*16;
            CPA16(dst, basep + goff);
        }
        CPCOMMIT(); CPWAIT();
        __syncthreads();
        const uint4* Fw = (src ? F1 : F0) + wx*2048;
        #pragma unroll
        for (int ks = 0; ks < 8; ks++) {
            uint32_t ah[2][4], al[2][4];
            #pragma unroll
            for (int mt = 0; mt < 2; mt++) {
                uint32_t adr = sb + (rb + mt*16 + lrow)*272 + ks*32 + lcolb;
                ldmx4(adr, ah[mt][0], ah[mt][1], ah[mt][2], ah[mt][3]);
                adr += ALO2;
                ldmx4(adr, al[mt][0], al[mt][1], al[mt][2], al[mt][3]);
            }
            #pragma unroll
            for (int nt = 0; nt < 8; nt++) {
                uint4 f4 = Fw[(ks*8 + nt)*32 + lane];
                #pragma unroll
                for (int mt = 0; mt < 2; mt++) {
                    mma16816(c[mt][nt], ah[mt], f4.x, f4.y);
                    mma16816(c[mt][nt], ah[mt], f4.z, f4.w);
                    mma16816(c[mt][nt], al[mt], f4.x, f4.y);
                }
            }
        }
    }

    // ---------------- epilogues ----------------
    int nb = nobj[b];
    int g = lane>>2, t2 = (lane&3)*2;
    if (mode == 0 || mode == 1) {
        __nv_bfloat16* Hi = (mode==0 ? g_Uhi : g_Thi) + (size_t)tile*16384;
        __nv_bfloat16* Lo = (mode==0 ? g_Ulo : g_Tlo) + (size_t)tile*16384;
        #pragma unroll
        for (int mt = 0; mt < 2; mt++) {
            #pragma unroll
            for (int h = 0; h < 2; h++) {
                int row = rb + mt*16 + g + h*8;
                int i = i0 + (row>>6), j = row&63;
                float mask = (i < nb && j < nb) ? 1.f : 0.f;
                bool diag = (i == j);
                const float* vr = g_Vrow + (b*64+i)*C_;
                const float* vc = g_Vcol + (b*64+j)*C_;
                const float* gg = g_G + b*C_;
                const float* dd = g_Dd + (b*64+i)*C_;
                const float* ee = g_E + b*C_;
                #pragma unroll
                for (int nt = 0; nt < 8; nt++) {
                    int col = nb0 + nt*8 + t2;
                    float vx, vy;
                    if (mode == 0) {
                        vx = lrelu(c[mt][nt][h*2+0] + bias[col])   * mask;
                        vy = lrelu(c[mt][nt][h*2+1] + bias[col+1]) * mask;
                    } else {
                        vx = c[mt][nt][h*2+0] + vr[col]   + gg[col]   + vc[col];
                        vy = c[mt][nt][h*2+1] + vr[col+1] + gg[col+1] + vc[col+1];
                        if (diag) { vx += dd[col] + ee[col]; vy += dd[col+1] + ee[col+1]; }
                        vx = lrelu(vx) * mask;
                        vy = lrelu(vy) * mask;
                    }
                    __nv_bfloat16 hx,lx,hy,ly;
                    split2(vx, hx, lx); split2(vy, hy, ly);
                    *(uint32_t*)(Hi + row*128 + col) = packbf(hx, hy);
                    *(uint32_t*)(Lo + row*128 + col) = packbf(lx, ly);
                }
            }
        }
    } else {
        __syncthreads();
        float* Vs = (float*)sm;   // [128][132] = 67584 B <= SM_G
        #pragma unroll
        for (int mt = 0; mt < 2; mt++) {
            #pragma unroll
            for (int h = 0; h < 2; h++) {
                int row = rb + mt*16 + g + h*8;
                int i = i0 + (row>>6), j = row&63;
                float mask = (i < nb && j < nb) ? 1.f : 0.f;
                #pragma unroll
                for (int nt = 0; nt < 8; nt++) {
                    int col = nb0 + nt*8 + t2;
                    float2 v;
                    v.x = lrelu(c[mt][nt][h*2+0] + bias[col])   * mask;
                    v.y = lrelu(c[mt][nt][h*2+1] + bias[col+1]) * mask;
                    *(float2*)(Vs + row*132 + col) = v;
                }
            }
        }
        __syncthreads();
        if (tid < 128) {
            float s = 0.f;
            #pragma unroll 8
            for (int r = 0; r < 128; r++) s += Vs[r*132 + tid];
            atomicAdd(&g_tot[b*C_ + tid], s);
            float dgv = Vs[i0*132 + tid] + Vs[(64 + i0 + 1)*132 + tid];
            atomicAdd(&g_dg[b*C_ + tid], dgv);
        }
    }
}

// ---------------- projection GEMM: [Vrow|Vcol|Dd] = X @ Wp (old staging path) ----------
__global__ void __launch_bounds__(256, 2) k_proj(const __nv_bfloat16* __restrict__ Bhi,
                                                 const __nv_bfloat16* __restrict__ Blo) {
    extern __shared__ unsigned char sm[];
    uint32_t sb = smem_u32(sm);
    int tid = threadIdx.x, wid = tid>>5, lane = tid&31;
    int p = blockIdx.x >> 4, tile = blockIdx.x & 15;

    int wy = wid&3, wx = wid>>2;
    int rb = wy*32, nb0 = wx*64;
    float c[2][8][4];
    #pragma unroll
    for (int mt = 0; mt < 2; mt++)
        #pragma unroll
        for (int nt = 0; nt < 8; nt++)
            #pragma unroll
            for (int q = 0; q < 4; q++) c[mt][nt][q] = 0.f;

    int lrow = (lane&7) + ((lane>>3)&1)*8;
    int lcolb = ((lane>>4)&1)*16;
    int bn = nb0 + (lane>>2);
    int btid4 = (lane&3)*4;
    const uint32_t* bhp = (const uint32_t*)(Bhi + p*49152);
    const uint32_t* blp = (const uint32_t*)(Blo + p*49152);
    const float4* Ag = (const float4*)(g_X + (size_t)tile*128*384);

    for (int ph = 0; ph < 6; ph++) {
        if (ph) __syncthreads();
        #pragma unroll
        for (int u = 0; u < 8; u++) {
            int f = tid + 256*u;
            int row = f>>4, q = f&15, c4 = q*4;
            float4 v = Ag[row*96 + ph*16 + q];
            __nv_bfloat16 h[4], l[4];
            split2(v.x, h[0], l[0]); split2(v.y, h[1], l[1]);
            split2(v.z, h[2], l[2]); split2(v.w, h[3], l[3]);
            *(uint2*)(sm + AH_OFF + (row*APAD + c4)*2) = *(uint2*)h;
            *(uint2*)(sm + AL_OFF + (row*APAD + c4)*2) = *(uint2*)l;
        }
        #pragma unroll
        for (int u = 0; u < 16; u++) {
            int f = tid + 256*u;
            int n = f>>5, kp = f&31;
            int k = kp*2;
            int col = (k & ~15) + (((k>>1)&3)<<2) + (((k>>3)&1)<<1);
            *(uint32_t*)(sm + BH_OFF + (n*BPAD + col)*2) = bhp[n*192 + ph*32 + kp];
            *(uint32_t*)(sm + BL_OFF + (n*BPAD + col)*2) = blp[n*192 + ph*32 + kp];
        }
        __syncthreads();
        #pragma unroll
        for (int ks = 0; ks < 4; ks++) {
            uint32_t ah[2][4], al[2][4];
            #pragma unroll
            for (int mt = 0; mt < 2; mt++) {
                uint32_t adr = sb + AH_OFF + (rb + mt*16 + lrow)*APAD*2 + ks*32 + lcolb;
                ldmx4(adr, ah[mt][0], ah[mt][1], ah[mt][2], ah[mt][3]);
                adr = sb + AL_OFF + (rb + mt*16 + lrow)*APAD*2 + ks*32 + lcolb;
                ldmx4(adr, al[mt][0], al[mt][1], al[mt][2], al[mt][3]);
            }
            #pragma unroll
            for (int nt = 0; nt < 8; nt++) {
                uint32_t bh0, bh1, bl0, bl1;
                uint32_t badr = sb + BH_OFF + ((bn + nt*8)*BPAD + ks*16 + btid4)*2;
                asm volatile("ld.shared.v2.b32 {%0,%1}, [%2];" : "=r"(bh0), "=r"(bh1) : "r"(badr));
                badr = sb + BL_OFF + ((bn + nt*8)*BPAD + ks*16 + btid4)*2;
                asm volatile("ld.shared.v2.b32 {%0,%1}, [%2];" : "=r"(bl0), "=r"(bl1) : "r"(badr));
                #pragma unroll
                for (int mt = 0; mt < 2; mt++) {
                    mma16816(c[mt][nt], ah[mt], bh0, bh1);
                    mma16816(c[mt][nt], ah[mt], bl0, bl1);
                    mma16816(c[mt][nt], al[mt], bh0, bh1);
                }
            }
        }
    }
    float* Out = (p==0) ? g_Vrow : (p==1) ? g_Vcol : g_Dd;
    int g = lane>>2, t2 = (lane&3)*2;
    #pragma unroll
    for (int mt = 0; mt < 2; mt++) {
        #pragma unroll
        for (int h = 0; h < 2; h++) {
            int row = rb + mt*16 + g + h*8;
            int m = tile*128 + row;
            #pragma unroll
            for (int nt = 0; nt < 8; nt++) {
                int col = nb0 + nt*8 + t2;
                float2 v;
                v.x = c[mt][nt][h*2+0];
                v.y = c[mt][nt][h*2+1];
                *(float2*)(Out + (size_t)m*128 + col) = v;
            }
        }
    }
}

// ---------------- eq1to2 prep ----------------
__global__ void k_prep(const float* __restrict__ scalars, const int* __restrict__ nobj,
                       const float* __restrict__ w_in) {
    int b = blockIdx.x;
    __shared__ float xs[N_][S_];
    __shared__ float ssum[S_];
    int nb = nobj[b];
    for (int idx = threadIdx.x; idx < N_*S_; idx += blockDim.x) {
        int n = idx/S_, s = idx%S_;
        xs[n][s] = (n < nb) ? scalars[(b*N_+n)*S_+s] : 0.f;
    }
    __syncthreads();
    if (threadIdx.x < S_) {
        float a = 0.f;
        for (int n = 0; n < N_; n++) a += xs[n][threadIdx.x];
        ssum[threadIdx.x] = a / AVGF;
    }
    __syncthreads();
    for (int idx = threadIdx.x; idx < N_*CS_; idx += blockDim.x) {
        int n = idx/CS_, c = idx%CS_;
        float a0=0, a1=0, a2=0;
        #pragma unroll
        for (int s = 0; s < S_; s++) {
            float xv = xs[n][s];
            a0 += xv*w_in[(0*S_+s)*CS_+c];
            a1 += xv*w_in[(1*S_+s)*CS_+c];
            a2 += xv*w_in[(2*S_+s)*CS_+c];
        }
        g_y012[((b*N_+n)*3+0)*CS_+c] = a0;
        g_y012[((b*N_+n)*3+1)*CS_+c] = a1;
        g_y012[((b*N_+n)*3+2)*CS_+c] = a2;
    }
    if (threadIdx.x < 2*CS_) {
        int k = threadIdx.x/CS_, c = threadIdx.x%CS_;
        float a = 0.f;
        #pragma unroll
        for (int s = 0; s < S_; s++) a += ssum[s]*w_in[((3+k)*S_+s)*CS_+c];
        g_y34[(b*2+k)*CS_+c] = a;
    }
}

// ---------------- initial T (bf16 hi/lo, tile layout) ----------------
__global__ void k_init(const float* __restrict__ momenta, const int* __restrict__ nobj,
                       const float* __restrict__ w_lin, const float* __restrict__ alpha,
                       const float* __restrict__ b_in) {
    int b = blockIdx.x / N_, i = blockIdx.x % N_;
    int c = threadIdx.x;
    __shared__ float pm[N_][4];
    __shared__ float dij[N_];
    __shared__ float y1s[N_][CS_];
    __shared__ float y0r[CS_], y2r[CS_], y3s[CS_], y4s[CS_];
    for (int idx = c; idx < N_*4; idx += 128) pm[idx/4][idx%4] = momenta[(b*N_)*4 + idx];
    for (int idx = c; idx < N_*CS_; idx += 128) {
        int n = idx/CS_, cs = idx%CS_;
        y1s[n][cs] = g_y012[((b*N_+n)*3+1)*CS_+cs];
    }
    if (c < CS_) {
        y0r[c] = g_y012[((b*N_+i)*3+0)*CS_+c];
        y2r[c] = g_y012[((b*N_+i)*3+2)*CS_+c];
        y3s[c] = g_y34[(b*2+0)*CS_+c];
        y4s[c] = g_y34[(b*2+1)*CS_+c];
    }
    __syncthreads();
    if (c < N_)
        dij[c] = pm[i][0]*pm[c][0] - pm[i][1]*pm[c][1] - pm[i][2]*pm[c][2] - pm[i][3]*pm[c][3];
    __syncthreads();
    int nb = nobj[b];
    float mi = (i < nb) ? 1.f : 0.f;
    float base = 0.f, wl = 0.f, al = 0.f;
    if (c < CS_) base = y0r[c] + y3s[c] + b_in[c];
    else { wl = w_lin[c-CS_]; al = alpha[c-CS_]; }
    size_t rowbase = ((size_t)(b*32 + (i>>1))*128 + (i&1)*64)*128;
    for (int j = 0; j < N_; j++) {
        float mask = mi * ((j < nb) ? 1.f : 0.f);
        float v;
        if (c < CS_) {
            v = base + y1s[j][c];
            if (j == i) v += y2r[c] + y4s[c];
            v = lrelu(v) * mask;
        } else {
            float r = dij[j] * wl;
            v = al * copysignf(log1pf(fabsf(r)), r) * mask;
        }
        __nv_bfloat16 h, l;
        split2(v, h, l);
        g_Thi[rowbase + j*128 + c] = h;
        g_Tlo[rowbase + j*128 + c] = l;
    }
}

// ---------------- reductions from U (bf16 hi/lo) -> X ----------------
__global__ void k_r1() {
    int b = blockIdx.x >> 6, i = blockIdx.x & 63;
    int t = threadIdx.x;
    int g = t&15, jg = t>>4;
    __shared__ float red[8][128];
    float aR[8] = {0,0,0,0,0,0,0,0}, aC[8] = {0,0,0,0,0,0,0,0};
    #pragma unroll
    for (int jj = 0; jj < 8; jj++) {
        int j = jg*8 + jj;
        {
            size_t off = ((size_t)(b*32 + (i>>1))*128 + (i&1)*64 + j)*128 + g*8;
            uint4 h4 = *(const uint4*)(g_Uhi + off);
            uint4 l4 = *(const uint4*)(g_Ulo + off);
            const __nv_bfloat16 *hp = (const __nv_bfloat16*)&h4, *lp = (const __nv_bfloat16*)&l4;
            #pragma unroll
            for (int q = 0; q < 8; q++) aR[q] += __bfloat162float(hp[q]) + __bfloat162float(lp[q]);
        }
        {
            size_t off = ((size_t)(b*32 + (j>>1))*128 + (j&1)*64 + i)*128 + g*8;
            uint4 h4 = *(const uint4*)(g_Uhi + off);
            uint4 l4 = *(const uint4*)(g_Ulo + off);
            const __nv_bfloat16 *hp = (const __nv_bfloat16*)&h4, *lp = (const __nv_bfloat16*)&l4;
            #pragma unroll
            for (int q = 0; q < 8; q++) aC[q] += __bfloat162float(hp[q]) + __bfloat162float(lp[q]);
        }
    }
    size_t m = (size_t)(b*N_+i);
    #pragma unroll
    for (int q = 0; q < 8; q++) red[jg][g*8+q] = aR[q];
    __syncthreads();
    { float s = 0.f; for (int r = 0; r < 8; r++) s += red[r][t]; g_X[m*384 + 128 + t] = s/AVGF; }
    __syncthreads();
    #pragma unroll
    for (int q = 0; q < 8; q++) red[jg][g*8+q] = aC[q];
    __syncthreads();
    { float s = 0.f; for (int r = 0; r < 8; r++) s += red[r][t]; g_X[m*384 + 256 + t] = s/AVGF; }
    if (t < 16) {
        size_t off = ((size_t)(b*32 + (i>>1))*128 + (i&1)*64 + i)*128 + t*8;
        uint4 h4 = *(const uint4*)(g_Uhi + off);
        uint4 l4 = *(const uint4*)(g_Ulo + off);
        const __nv_bfloat16 *hp = (const __nv_bfloat16*)&h4, *lp = (const __nv_bfloat16*)&l4;
        #pragma unroll
        for (int q = 0; q < 8; q++)
            g_X[m*384 + t*8 + q] = __bfloat162float(hp[q]) + __bfloat162float(lp[q]);
    }
}

__global__ void k_r2() {
    int b = blockIdx.x, c = threadIdx.x;
    float t = 0.f, tr = 0.f;
    for (int i = 0; i < N_; i++) {
        size_t m = (size_t)(b*N_+i);
        t  += g_X[m*384 + 128 + c];
        tr += g_X[m*384 + c];
    }
    g_t[b*C_+c] = t/AVGF; g_tr[b*C_+c] = tr/AVGF;
}

__global__ void k_pg(const float* __restrict__ W, const float* __restrict__ eqb,
                     const float* __restrict__ eqbd) {
    int b = blockIdx.x, d = threadIdx.x;
    __shared__ float tt[C_], tg[C_];
    tt[d] = g_t[b*C_+d]; tg[d] = g_tr[b*C_+d];
    __syncthreads();
    float g = eqb[d], e = eqbd[d];
    for (int c = 0; c < C_; c++) {
        g += tt[c]*W[(11*C_+c)*C_+d] + tg[c]*W[(13*C_+c)*C_+d];
        e += tt[c]*W[(12*C_+c)*C_+d] + tg[c]*W[(14*C_+c)*C_+d];
    }
    g_G[b*C_+d] = g; g_E[b*C_+d] = e;
}

__global__ void k_zero() {
    int idx = blockIdx.x*blockDim.x + threadIdx.x;
    if (idx < B_*C_) { g_dg[idx] = 0.f; g_tot[idx] = 0.f; }
}

__global__ void k_out(const float* __restrict__ w20, const float* __restrict__ b20,
                      const float* __restrict__ wmlp, const float* __restrict__ bmlp,
                      float* __restrict__ out) {
    int b = blockIdx.x, d = threadIdx.x;
    __shared__ float a0[C_], a1[C_], act[C_];
    a0[d] = lrelu(g_dg[b*C_+d] / AVGF);
    a1[d] = lrelu(g_tot[b*C_+d] / (AVGF*AVGF));
    __syncthreads();
    float a = b20[d];
    for (int c = 0; c < C_; c++) a += a0[c]*w20[c*C_+d] + a1[c]*w20[(C_+c)*C_+d];
    act[d] = a;
    __syncthreads();
    if (d < 2) {
        float o = bmlp[d];
        for (int k = 0; k < C_; k++) o += act[k]*wmlp[k*2+d];
        out[b*2+d] = o;
    }
}

// ---------------- host ----------------
extern "C" void kernel_launch(void* const* d_in, const int* in_sizes, int n_in,
                              void* d_out, int out_size) {
    const float *momenta=0, *scalars=0, *w_lin=0, *alpha=0, *w_in=0, *b_in=0;
    const int* nobj=0;
    const float *msgw[4], *msgb[4], *eqw[4], *eqb[4], *eqbd[4];
    const float *wm0=0, *bm0=0, *w20=0, *b20=0, *wmlp=0, *bmlp=0;

    if (n_in >= 33 && in_sizes[0] == 8192) {
        momenta=(const float*)d_in[0]; scalars=(const float*)d_in[1]; nobj=(const int*)d_in[2];
        w_lin=(const float*)d_in[3]; alpha=(const float*)d_in[4]; w_in=(const float*)d_in[5];
        b_in=(const float*)d_in[6];
        for (int l = 0; l < 4; l++) {
            msgw[l]=(const float*)d_in[7+l];  msgb[l]=(const float*)d_in[11+l];
            eqw[l] =(const float*)d_in[15+l]; eqb[l] =(const float*)d_in[19+l];
            eqbd[l]=(const float*)d_in[23+l];
        }
        wm0=(const float*)d_in[27]; bm0=(const float*)d_in[28]; w20=(const float*)d_in[29];
        b20=(const float*)d_in[30]; wmlp=(const float*)d_in[31]; bmlp=(const float*)d_in[32];
    } else if (n_in >= 33) {
        alpha=(const float*)d_in[0]; b20=(const float*)d_in[1]; b_in=(const float*)d_in[2];
        bm0=(const float*)d_in[3]; bmlp=(const float*)d_in[4];
        for (int l = 0; l < 4; l++) {
            eqb[l] =(const float*)d_in[5+l];  eqbd[l]=(const float*)d_in[9+l];
            eqw[l] =(const float*)d_in[13+l]; msgb[l]=(const float*)d_in[18+l];
            msgw[l]=(const float*)d_in[22+l];
        }
        momenta=(const float*)d_in[17]; nobj=(const int*)d_in[26]; scalars=(const float*)d_in[27];
        w20=(const float*)d_in[28]; w_in=(const float*)d_in[29]; w_lin=(const float*)d_in[30];
        wm0=(const float*)d_in[31]; wmlp=(const float*)d_in[32];
    } else {
        momenta=(const float*)d_in[0]; scalars=(const float*)d_in[1]; nobj=(const int*)d_in[2];
        w_lin=(const float*)d_in[3]; alpha=(const float*)d_in[4]; w_in=(const float*)d_in[5];
        b_in=(const float*)d_in[6];
        for (int l = 0; l < 4; l++) {
            msgw[l]=(const float*)d_in[7]+(size_t)l*C_*C_;     msgb[l]=(const float*)d_in[8]+(size_t)l*C_;
            eqw[l] =(const float*)d_in[9]+(size_t)l*15*C_*C_;  eqb[l] =(const float*)d_in[10]+(size_t)l*C_;
            eqbd[l]=(const float*)d_in[11]+(size_t)l*C_;
        }
        wm0=(const float*)d_in[12]; bm0=(const float*)d_in[13]; w20=(const float*)d_in[14];
        b20=(const float*)d_in[15]; wmlp=(const float*)d_in[16]; bmlp=(const float*)d_in[17];
    }

    cudaFuncSetAttribute(k_gemm, cudaFuncAttributeMaxDynamicSharedMemorySize, SM_G);
    cudaFuncSetAttribute(k_proj, cudaFuncAttributeMaxDynamicSharedMemorySize, SM_P);

    __nv_bfloat16 *Thi=0, *Tlo=0, *Uhi=0, *Ulo=0, *WpH=0, *WpL=0;
    uint4* Bf=0;
    cudaGetSymbolAddress((void**)&Thi, g_Thi);
    cudaGetSymbolAddress((void**)&Tlo, g_Tlo);
    cudaGetSymbolAddress((void**)&Uhi, g_Uhi);
    cudaGetSymbolAddress((void**)&Ulo, g_Ulo);
    cudaGetSymbolAddress((void**)&Bf,  g_Bf);
    cudaGetSymbolAddress((void**)&WpH, g_WpHi);
    cudaGetSymbolAddress((void**)&WpL, g_WpLo);

    k_wsplitF<<<13, 256>>>(msgw[0], msgw[1], msgw[2], msgw[3],
                           eqw[0], eqw[1], eqw[2], eqw[3], wm0);
    k_wsplit2<<<12, 256>>>(eqw[0], eqw[1], eqw[2], eqw[3]);
    k_prep<<<B_, 256>>>(scalars, nobj, w_in);
    k_init<<<B_*N_, 128>>>(momenta, nobj, w_lin, alpha, b_in);

    for (int l = 0; l < 4; l++) {
        k_gemm<<<TILES, 256, SM_G>>>(Thi, Tlo, Bf + l*4096, (const uint4*)0,
                                     msgb[l], nobj, 0);
        k_r1<<<B_*N_, 128>>>();
        k_r2<<<B_, 128>>>();
        k_proj<<<48, 256, SM_P>>>(WpH + (size_t)l*147456, WpL + (size_t)l*147456);
        k_pg<<<B_, 128>>>(eqw[l], eqb[l], eqbd[l]);
        k_gemm<<<TILES, 256, SM_G>>>(Uhi, Ulo, Bf + (4 + l*2)*4096, Bf + (5 + l*2)*4096,
                                     msgb[l], nobj, 1);
    }

    k_zero<<<(B_*C_ + 255)/256, 256>>>();
    k_gemm<<<TILES, 256, SM_G>>>(Thi, Tlo, Bf + 12*4096, (const uint4*)0,
                                 bm0, nobj, 3);
    k_out<<<B_, 128>>>(w20, b20, wmlp, bmlp, (float*)d_out);
}

// round 9
// speedup vs baseline: 3.6405x; 1.4503x over previous
#include <cuda_runtime.h>
#include <cuda_bf16.h>
#include <math.h>
#include <stdint.h>

#define B_  32
#define N_  64
#define S_  9
#define C_  128
#define CS_ 32
#define AVGF 49.0f
#define TILES (B_*32)   // 1024 tiles of 128 rows; tile=(b, i-pair), row=(i&1)*64+j

// ---------------- device scratch ----------------
__device__ __nv_bfloat16 g_Thi[TILES*16384], g_Tlo[TILES*16384];
__device__ __nv_bfloat16 g_Uhi[TILES*16384], g_Ulo[TILES*16384];
__device__ float g_X[B_*N_*384];          // [m=b*64+i][dvec|rvec|cvec]
__device__ uint4 g_Bf[13*4096];           // B fragments: [mat][wx][ks][nt][lane] = {b0h,b1h,b0l,b1l}
__device__ __nv_bfloat16 g_WpHi[4*147456], g_WpLo[4*147456];   // proj weights [l][p][n][384k]
__device__ float g_y012[B_*N_*3*CS_];
__device__ float g_y34[B_*2*CS_];
__device__ float g_Vrow[B_*N_*C_];
__device__ float g_Vcol[B_*N_*C_];
__device__ float g_Dd[B_*N_*C_];
__device__ float g_G[B_*C_];
__device__ float g_E[B_*C_];
__device__ float g_dg[B_*C_];
__device__ float g_tot[B_*C_];

__device__ __forceinline__ float lrelu(float x){ return x >= 0.f ? x : 0.01f*x; }
__device__ __forceinline__ uint32_t smem_u32(const void* p) {
    uint32_t a;
    asm("{ .reg .u64 t; cvta.to.shared.u64 t, %1; cvt.u32.u64 %0, t; }" : "=r"(a) : "l"(p));
    return a;
}
__device__ __forceinline__ void split2(float v, __nv_bfloat16& h, __nv_bfloat16& l) {
    h = __float2bfloat16(v);
    l = __float2bfloat16(v - __bfloat162float(h));
}
__device__ __forceinline__ uint32_t packbf(__nv_bfloat16 a, __nv_bfloat16 b) {
    __nv_bfloat162 p; p.x = a; p.y = b;
    return *(uint32_t*)&p;
}
__device__ __forceinline__ void ldmx4(uint32_t a, uint32_t& r0, uint32_t& r1, uint32_t& r2, uint32_t& r3) {
    asm volatile("ldmatrix.sync.aligned.m8n8.x4.shared.b16 {%0,%1,%2,%3}, [%4];"
                 : "=r"(r0), "=r"(r1), "=r"(r2), "=r"(r3) : "r"(a));
}
__device__ __forceinline__ void mma16816(float* c, const uint32_t* a, uint32_t b0, uint32_t b1) {
    asm volatile("mma.sync.aligned.m16n8k16.row.col.f32.bf16.bf16.f32 "
                 "{%0,%1,%2,%3}, {%4,%5,%6,%7}, {%8,%9}, {%0,%1,%2,%3};"
                 : "+f"(c[0]), "+f"(c[1]), "+f"(c[2]), "+f"(c[3])
                 : "r"(a[0]), "r"(a[1]), "r"(a[2]), "r"(a[3]), "r"(b0), "r"(b1));
}
#define CPA16(dst, src) asm volatile("cp.async.ca.shared.global [%0], [%1], 16;" :: "r"(dst), "l"(src))
#define CPCOMMIT() asm volatile("cp.async.commit_group;" ::: "memory")
#define CPWAIT()   asm volatile("cp.async.wait_group 0;"  ::: "memory")

#define AROW2 136
#define ALO2  34816
#define SM_G  69632
#define APAD 72
#define BPAD 80
#define AH_OFF 0
#define AL_OFF 18432
#define BH_OFF 36864
#define BL_OFF 57344
#define SM_P 77824

// ---------------- B fragment pack: [mat][wx][ks][nt][lane] ----------------
__global__ void k_wsplitF(const float* __restrict__ m0, const float* __restrict__ m1,
                          const float* __restrict__ m2, const float* __restrict__ m3,
                          const float* __restrict__ e0, const float* __restrict__ e1,
                          const float* __restrict__ e2, const float* __restrict__ e3,
                          const float* __restrict__ wfin) {
    int mat = blockIdx.x, tid = threadIdx.x;
    const float* W;
    if (mat < 4)       W = (mat==0)?m0:(mat==1)?m1:(mat==2)?m2:m3;
    else if (mat < 12) {
        int l = (mat-4)>>1, wh = (mat-4)&1;
        const float* E = (l==0)?e0:(l==1)?e1:(l==2)?e2:e3;
        W = E + wh*16384;
    } else W = wfin;
    uint4* dst = g_Bf + mat*4096;
    for (int e = tid; e < 4096; e += 256) {
        int lane = e&31, nt = (e>>5)&7, ks = (e>>8)&7, wx = e>>11;
        int n = wx*64 + nt*8 + (lane>>2);
        int k0 = ks*16 + (lane&3)*2;
        __nv_bfloat16 h00,l00,h01,l01,h10,l10,h11,l11;
        split2(W[k0*128+n],     h00, l00);
        split2(W[(k0+1)*128+n], h01, l01);
        split2(W[(k0+8)*128+n], h10, l10);
        split2(W[(k0+9)*128+n], h11, l11);
        uint4 o;
        o.x = packbf(h00,h01); o.y = packbf(h10,h11);
        o.z = packbf(l00,l01); o.w = packbf(l10,l11);
        dst[e] = o;
    }
}

// proj weights: [l][p][n][384] with k-chunks mapping to eq mats
__global__ void k_wsplit2(const float* __restrict__ e0, const float* __restrict__ e1,
                          const float* __restrict__ e2, const float* __restrict__ e3) {
    int l = blockIdx.x / 3, p = blockIdx.x % 3, tid = threadIdx.x;
    const int tbl[3][3] = {{3,5,7},{4,6,8},{2,9,10}};
    const float* E = (l==0)?e0:(l==1)?e1:(l==2)?e2:e3;
    __nv_bfloat16* Hi = g_WpHi + (size_t)l*147456 + p*49152;
    __nv_bfloat16* Lo = g_WpLo + (size_t)l*147456 + p*49152;
    for (int e = tid; e < 49152; e += 256) {
        int n = e / 384, k = e % 384;
        int mat = tbl[p][k>>7], kk = k&127;
        __nv_bfloat16 h, lo;
        split2(E[(mat*C_ + kk)*C_ + n], h, lo);
        Hi[n*384 + k] = h; Lo[n*384 + k] = lo;
    }
}

// ---------------- main GEMM (masked-tile early exit) ----------------
// modes: 0 = U = lrelu(acc+bias)*mask
//        1 = T = lrelu(U@W0 + UT@W1 + Vrow+G+Vcol (+Dd+E diag))*mask
//        3 = final: lrelu(acc+bias)*mask -> trace/total reduction
__global__ void __launch_bounds__(256, 2) k_gemm(const __nv_bfloat16* __restrict__ Ahi,
                                                 const __nv_bfloat16* __restrict__ Alo,
                                                 const uint4* __restrict__ F0,
                                                 const uint4* __restrict__ F1,
                                                 const float* __restrict__ bias,
                                                 const int* __restrict__ nobj, int mode) {
    extern __shared__ unsigned char sm[];
    uint32_t sb = smem_u32(sm);
    int tid = threadIdx.x, wid = tid>>5, lane = tid&31;
    int tile = blockIdx.x;
    int b = tile>>5, i0 = (tile&31)<<1;
    int nb = nobj[b];
    if (i0 >= nb) return;   // whole tile masked: outputs are permanently zero

    int wy = wid&3, wx = wid>>2;
    int rb = wy*32, nb0 = wx*64;
    float c[2][8][4];
    #pragma unroll
    for (int mt = 0; mt < 2; mt++)
        #pragma unroll
        for (int nt = 0; nt < 8; nt++)
            #pragma unroll
            for (int q = 0; q < 4; q++) c[mt][nt][q] = 0.f;

    int lrow = (lane&7) + ((lane>>3)&1)*8;
    int lcolb = ((lane>>4)&1)*16;

    int nsrc = (mode == 1) ? 2 : 1;
    for (int src = 0; src < nsrc; src++) {
        if (src) __syncthreads();
        #pragma unroll
        for (int u = 0; u < 16; u++) {
            int f = tid + 256*u;
            int comp = f>>11, rem = f&2047, row = rem>>4, c16 = rem&15;
            const __nv_bfloat16* basep = comp ? Alo : Ahi;
            size_t goff;
            if (src == 0) {
                goff = (size_t)tile*16384 + row*128 + c16*8;
            } else {
                int jj = row&63, hh = row>>6;
                goff = ((size_t)(b*32 + (jj>>1))*128 + (jj&1)*64 + i0 + hh)*128 + c16*8;
            }
            uint32_t dst = sb + comp*ALO2 + row*272 + c16*16;
            CPA16(dst, basep + goff);
        }
        CPCOMMIT(); CPWAIT();
        __syncthreads();
        const uint4* Fw = (src ? F1 : F0) + wx*2048;
        #pragma unroll
        for (int ks = 0; ks < 8; ks++) {
            uint32_t ah[2][4], al[2][4];
            #pragma unroll
            for (int mt = 0; mt < 2; mt++) {
                uint32_t adr = sb + (rb + mt*16 + lrow)*272 + ks*32 + lcolb;
                ldmx4(adr, ah[mt][0], ah[mt][1], ah[mt][2], ah[mt][3]);
                adr += ALO2;
                ldmx4(adr, al[mt][0], al[mt][1], al[mt][2], al[mt][3]);
            }
            #pragma unroll
            for (int nt = 0; nt < 8; nt++) {
                uint4 f4 = Fw[(ks*8 + nt)*32 + lane];
                #pragma unroll
                for (int mt = 0; mt < 2; mt++) {
                    mma16816(c[mt][nt], ah[mt], f4.x, f4.y);
                    mma16816(c[mt][nt], ah[mt], f4.z, f4.w);
                    mma16816(c[mt][nt], al[mt], f4.x, f4.y);
                }
            }
        }
    }

    // ---------------- epilogues ----------------
    int g = lane>>2, t2 = (lane&3)*2;
    if (mode == 0 || mode == 1) {
        __nv_bfloat16* Hi = (mode==0 ? g_Uhi : g_Thi) + (size_t)tile*16384;
        __nv_bfloat16* Lo = (mode==0 ? g_Ulo : g_Tlo) + (size_t)tile*16384;
        #pragma unroll
        for (int mt = 0; mt < 2; mt++) {
            #pragma unroll
            for (int h = 0; h < 2; h++) {
                int row = rb + mt*16 + g + h*8;
                int i = i0 + (row>>6), j = row&63;
                float mask = (i < nb && j < nb) ? 1.f : 0.f;
                bool diag = (i == j);
                const float* vr = g_Vrow + (b*64+i)*C_;
                const float* vc = g_Vcol + (b*64+j)*C_;
                const float* gg = g_G + b*C_;
                const float* dd = g_Dd + (b*64+i)*C_;
                const float* ee = g_E + b*C_;
                #pragma unroll
                for (int nt = 0; nt < 8; nt++) {
                    int col = nb0 + nt*8 + t2;
                    float vx, vy;
                    if (mode == 0) {
                        vx = lrelu(c[mt][nt][h*2+0] + bias[col])   * mask;
                        vy = lrelu(c[mt][nt][h*2+1] + bias[col+1]) * mask;
                    } else {
                        vx = c[mt][nt][h*2+0] + vr[col]   + gg[col]   + vc[col];
                        vy = c[mt][nt][h*2+1] + vr[col+1] + gg[col+1] + vc[col+1];
                        if (diag) { vx += dd[col] + ee[col]; vy += dd[col+1] + ee[col+1]; }
                        vx = lrelu(vx) * mask;
                        vy = lrelu(vy) * mask;
                    }
                    __nv_bfloat16 hx,lx,hy,ly;
                    split2(vx, hx, lx); split2(vy, hy, ly);
                    *(uint32_t*)(Hi + row*128 + col) = packbf(hx, hy);
                    *(uint32_t*)(Lo + row*128 + col) = packbf(lx, ly);
                }
            }
        }
    } else {
        __syncthreads();
        float* Vs = (float*)sm;   // [128][132]
        #pragma unroll
        for (int mt = 0; mt < 2; mt++) {
            #pragma unroll
            for (int h = 0; h < 2; h++) {
                int row = rb + mt*16 + g + h*8;
                int i = i0 + (row>>6), j = row&63;
                float mask = (i < nb && j < nb) ? 1.f : 0.f;
                #pragma unroll
                for (int nt = 0; nt < 8; nt++) {
                    int col = nb0 + nt*8 + t2;
                    float2 v;
                    v.x = lrelu(c[mt][nt][h*2+0] + bias[col])   * mask;
                    v.y = lrelu(c[mt][nt][h*2+1] + bias[col+1]) * mask;
                    *(float2*)(Vs + row*132 + col) = v;
                }
            }
        }
        __syncthreads();
        if (tid < 128) {
            float s = 0.f;
            #pragma unroll 8
            for (int r = 0; r < 128; r++) s += Vs[r*132 + tid];
            atomicAdd(&g_tot[b*C_ + tid], s);
            float dgv = Vs[i0*132 + tid] + Vs[(64 + i0 + 1)*132 + tid];
            atomicAdd(&g_dg[b*C_ + tid], dgv);
        }
    }
}

// ---------------- projection GEMM: [Vrow|Vcol|Dd] = X @ Wp ----------------
__global__ void __launch_bounds__(256, 2) k_proj(const __nv_bfloat16* __restrict__ Bhi,
                                                 const __nv_bfloat16* __restrict__ Blo) {
    extern __shared__ unsigned char sm[];
    uint32_t sb = smem_u32(sm);
    int tid = threadIdx.x, wid = tid>>5, lane = tid&31;
    int p = blockIdx.x >> 4, tile = blockIdx.x & 15;

    int wy = wid&3, wx = wid>>2;
    int rb = wy*32, nb0 = wx*64;
    float c[2][8][4];
    #pragma unroll
    for (int mt = 0; mt < 2; mt++)
        #pragma unroll
        for (int nt = 0; nt < 8; nt++)
            #pragma unroll
            for (int q = 0; q < 4; q++) c[mt][nt][q] = 0.f;

    int lrow = (lane&7) + ((lane>>3)&1)*8;
    int lcolb = ((lane>>4)&1)*16;
    int bn = nb0 + (lane>>2);
    int btid4 = (lane&3)*4;
    const uint32_t* bhp = (const uint32_t*)(Bhi + p*49152);
    const uint32_t* blp = (const uint32_t*)(Blo + p*49152);
    const float4* Ag = (const float4*)(g_X + (size_t)tile*128*384);

    for (int ph = 0; ph < 6; ph++) {
        if (ph) __syncthreads();
        #pragma unroll
        for (int u = 0; u < 8; u++) {
            int f = tid + 256*u;
            int row = f>>4, q = f&15, c4 = q*4;
            float4 v = Ag[row*96 + ph*16 + q];
            __nv_bfloat16 h[4], l[4];
            split2(v.x, h[0], l[0]); split2(v.y, h[1], l[1]);
            split2(v.z, h[2], l[2]); split2(v.w, h[3], l[3]);
            *(uint2*)(sm + AH_OFF + (row*APAD + c4)*2) = *(uint2*)h;
            *(uint2*)(sm + AL_OFF + (row*APAD + c4)*2) = *(uint2*)l;
        }
        #pragma unroll
        for (int u = 0; u < 16; u++) {
            int f = tid + 256*u;
            int n = f>>5, kp = f&31;
            int k = kp*2;
            int col = (k & ~15) + (((k>>1)&3)<<2) + (((k>>3)&1)<<1);
            *(uint32_t*)(sm + BH_OFF + (n*BPAD + col)*2) = bhp[n*192 + ph*32 + kp];
            *(uint32_t*)(sm + BL_OFF + (n*BPAD + col)*2) = blp[n*192 + ph*32 + kp];
        }
        __syncthreads();
        #pragma unroll
        for (int ks = 0; ks < 4; ks++) {
            uint32_t ah[2][4], al[2][4];
            #pragma unroll
            for (int mt = 0; mt < 2; mt++) {
                uint32_t adr = sb + AH_OFF + (rb + mt*16 + lrow)*APAD*2 + ks*32 + lcolb;
                ldmx4(adr, ah[mt][0], ah[mt][1], ah[mt][2], ah[mt][3]);
                adr = sb + AL_OFF + (rb + mt*16 + lrow)*APAD*2 + ks*32 + lcolb;
                ldmx4(adr, al[mt][0], al[mt][1], al[mt][2], al[mt][3]);
            }
            #pragma unroll
            for (int nt = 0; nt < 8; nt++) {
                uint32_t bh0, bh1, bl0, bl1;
                uint32_t badr = sb + BH_OFF + ((bn + nt*8)*BPAD + ks*16 + btid4)*2;
                asm volatile("ld.shared.v2.b32 {%0,%1}, [%2];" : "=r"(bh0), "=r"(bh1) : "r"(badr));
                badr = sb + BL_OFF + ((bn + nt*8)*BPAD + ks*16 + btid4)*2;
                asm volatile("ld.shared.v2.b32 {%0,%1}, [%2];" : "=r"(bl0), "=r"(bl1) : "r"(badr));
                #pragma unroll
                for (int mt = 0; mt < 2; mt++) {
                    mma16816(c[mt][nt], ah[mt], bh0, bh1);
                    mma16816(c[mt][nt], ah[mt], bl0, bl1);
                    mma16816(c[mt][nt], al[mt], bh0, bh1);
                }
            }
        }
    }
    float* Out = (p==0) ? g_Vrow : (p==1) ? g_Vcol : g_Dd;
    int g = lane>>2, t2 = (lane&3)*2;
    #pragma unroll
    for (int mt = 0; mt < 2; mt++) {
        #pragma unroll
        for (int h = 0; h < 2; h++) {
            int row = rb + mt*16 + g + h*8;
            int m = tile*128 + row;
            #pragma unroll
            for (int nt = 0; nt < 8; nt++) {
                int col = nb0 + nt*8 + t2;
                float2 v;
                v.x = c[mt][nt][h*2+0];
                v.y = c[mt][nt][h*2+1];
                *(float2*)(Out + (size_t)m*128 + col) = v;
            }
        }
    }
}

// ---------------- eq1to2 prep ----------------
__global__ void k_prep(const float* __restrict__ scalars, const int* __restrict__ nobj,
                       const float* __restrict__ w_in) {
    int b = blockIdx.x;
    __shared__ float xs[N_][S_];
    __shared__ float ssum[S_];
    int nb = nobj[b];
    for (int idx = threadIdx.x; idx < N_*S_; idx += blockDim.x) {
        int n = idx/S_, s = idx%S_;
        xs[n][s] = (n < nb) ? scalars[(b*N_+n)*S_+s] : 0.f;
    }
    __syncthreads();
    if (threadIdx.x < S_) {
        float a = 0.f;
        for (int n = 0; n < N_; n++) a += xs[n][threadIdx.x];
        ssum[threadIdx.x] = a / AVGF;
    }
    __syncthreads();
    for (int idx = threadIdx.x; idx < N_*CS_; idx += blockDim.x) {
        int n = idx/CS_, c = idx%CS_;
        float a0=0, a1=0, a2=0;
        #pragma unroll
        for (int s = 0; s < S_; s++) {
            float xv = xs[n][s];
            a0 += xv*w_in[(0*S_+s)*CS_+c];
            a1 += xv*w_in[(1*S_+s)*CS_+c];
            a2 += xv*w_in[(2*S_+s)*CS_+c];
        }
        g_y012[((b*N_+n)*3+0)*CS_+c] = a0;
        g_y012[((b*N_+n)*3+1)*CS_+c] = a1;
        g_y012[((b*N_+n)*3+2)*CS_+c] = a2;
    }
    if (threadIdx.x < 2*CS_) {
        int k = threadIdx.x/CS_, c = threadIdx.x%CS_;
        float a = 0.f;
        #pragma unroll
        for (int s = 0; s < S_; s++) a += ssum[s]*w_in[((3+k)*S_+s)*CS_+c];
        g_y34[(b*2+k)*CS_+c] = a;
    }
}

// ---------------- initial T (bf16 hi/lo, masked rows skipped) ----------------
__global__ void k_init(const float* __restrict__ momenta, const int* __restrict__ nobj,
                       const float* __restrict__ w_lin, const float* __restrict__ alpha,
                       const float* __restrict__ b_in) {
    int b = blockIdx.x / N_, i = blockIdx.x % N_;
    int nb = nobj[b];
    if (i >= nb) return;   // masked row: stays zero forever
    int c = threadIdx.x;
    __shared__ float pm[N_][4];
    __shared__ float dij[N_];
    __shared__ float y1s[N_][CS_];
    __shared__ float y0r[CS_], y2r[CS_], y3s[CS_], y4s[CS_];
    for (int idx = c; idx < N_*4; idx += 128) pm[idx/4][idx%4] = momenta[(b*N_)*4 + idx];
    for (int idx = c; idx < N_*CS_; idx += 128) {
        int n = idx/CS_, cs = idx%CS_;
        y1s[n][cs] = g_y012[((b*N_+n)*3+1)*CS_+cs];
    }
    if (c < CS_) {
        y0r[c] = g_y012[((b*N_+i)*3+0)*CS_+c];
        y2r[c] = g_y012[((b*N_+i)*3+2)*CS_+c];
        y3s[c] = g_y34[(b*2+0)*CS_+c];
        y4s[c] = g_y34[(b*2+1)*CS_+c];
    }
    __syncthreads();
    if (c < N_)
        dij[c] = pm[i][0]*pm[c][0] - pm[i][1]*pm[c][1] - pm[i][2]*pm[c][2] - pm[i][3]*pm[c][3];
    __syncthreads();
    float base = 0.f, wl = 0.f, al = 0.f;
    if (c < CS_) base = y0r[c] + y3s[c] + b_in[c];
    else { wl = w_lin[c-CS_]; al = alpha[c-CS_]; }
    size_t rowbase = ((size_t)(b*32 + (i>>1))*128 + (i&1)*64)*128;
    for (int j = 0; j < N_; j++) {
        float mask = (j < nb) ? 1.f : 0.f;
        float v;
        if (c < CS_) {
            v = base + y1s[j][c];
            if (j == i) v += y2r[c] + y4s[c];
            v = lrelu(v) * mask;
        } else {
            float r = dij[j] * wl;
            v = al * copysignf(log1pf(fabsf(r)), r) * mask;
        }
        __nv_bfloat16 h, l;
        split2(v, h, l);
        g_Thi[rowbase + j*128 + c] = h;
        g_Tlo[rowbase + j*128 + c] = l;
    }
}

// ---------------- reductions from U (bf16 hi/lo) -> X (masked rows skipped) ----------------
__global__ void k_r1(const int* __restrict__ nobj) {
    int b = blockIdx.x >> 6, i = blockIdx.x & 63;
    if (i >= nobj[b]) return;  // X row stays zero -> proj outputs zero -> masked epilogue OK
    int t = threadIdx.x;
    int g = t&15, jg = t>>4;
    __shared__ float red[8][128];
    float aR[8] = {0,0,0,0,0,0,0,0}, aC[8] = {0,0,0,0,0,0,0,0};
    #pragma unroll
    for (int jj = 0; jj < 8; jj++) {
        int j = jg*8 + jj;
        {
            size_t off = ((size_t)(b*32 + (i>>1))*128 + (i&1)*64 + j)*128 + g*8;
            uint4 h4 = *(const uint4*)(g_Uhi + off);
            uint4 l4 = *(const uint4*)(g_Ulo + off);
            const __nv_bfloat16 *hp = (const __nv_bfloat16*)&h4, *lp = (const __nv_bfloat16*)&l4;
            #pragma unroll
            for (int q = 0; q < 8; q++) aR[q] += __bfloat162float(hp[q]) + __bfloat162float(lp[q]);
        }
        {
            size_t off = ((size_t)(b*32 + (j>>1))*128 + (j&1)*64 + i)*128 + g*8;
            uint4 h4 = *(const uint4*)(g_Uhi + off);
            uint4 l4 = *(const uint4*)(g_Ulo + off);
            const __nv_bfloat16 *hp = (const __nv_bfloat16*)&h4, *lp = (const __nv_bfloat16*)&l4;
            #pragma unroll
            for (int q = 0; q < 8; q++) aC[q] += __bfloat162float(hp[q]) + __bfloat162float(lp[q]);
        }
    }
    size_t m = (size_t)(b*N_+i);
    #pragma unroll
    for (int q = 0; q < 8; q++) red[jg][g*8+q] = aR[q];
    __syncthreads();
    { float s = 0.f; for (int r = 0; r < 8; r++) s += red[r][t]; g_X[m*384 + 128 + t] = s/AVGF; }
    __syncthreads();
    #pragma unroll
    for (int q = 0; q < 8; q++) red[jg][g*8+q] = aC[q];
    __syncthreads();
    { float s = 0.f; for (int r = 0; r < 8; r++) s += red[r][t]; g_X[m*384 + 256 + t] = s/AVGF; }
    if (t < 16) {
        size_t off = ((size_t)(b*32 + (i>>1))*128 + (i&1)*64 + i)*128 + t*8;
        uint4 h4 = *(const uint4*)(g_Uhi + off);
        uint4 l4 = *(const uint4*)(g_Ulo + off);
        const __nv_bfloat16 *hp = (const __nv_bfloat16*)&h4, *lp = (const __nv_bfloat16*)&l4;
        #pragma unroll
        for (int q = 0; q < 8; q++)
            g_X[m*384 + t*8 + q] = __bfloat162float(hp[q]) + __bfloat162float(lp[q]);
    }
}

// ---------------- fused r2 + pg: totals then G/E projections ----------------
__global__ void k_rpg(const float* __restrict__ W, const float* __restrict__ eqb,
                      const float* __restrict__ eqbd, const int* __restrict__ nobj) {
    int b = blockIdx.x, d = threadIdx.x;
    __shared__ float tt[C_], tg[C_];
    int nb = nobj[b];
    float t = 0.f, tr = 0.f;
    for (int i = 0; i < nb; i++) {
        size_t m = (size_t)(b*N_+i);
        t  += g_X[m*384 + 128 + d];
        tr += g_X[m*384 + d];
    }
    tt[d] = t / AVGF; tg[d] = tr / AVGF;
    __syncthreads();
    float g = eqb[d], e = eqbd[d];
    for (int c = 0; c < C_; c++) {
        g += tt[c]*W[(11*C_+c)*C_+d] + tg[c]*W[(13*C_+c)*C_+d];
        e += tt[c]*W[(12*C_+c)*C_+d] + tg[c]*W[(14*C_+c)*C_+d];
    }
    g_G[b*C_+d] = g; g_E[b*C_+d] = e;
}

__global__ void k_zero() {
    int idx = blockIdx.x*blockDim.x + threadIdx.x;
    if (idx < B_*C_) { g_dg[idx] = 0.f; g_tot[idx] = 0.f; }
}

__global__ void k_out(const float* __restrict__ w20, const float* __restrict__ b20,
                      const float* __restrict__ wmlp, const float* __restrict__ bmlp,
                      float* __restrict__ out) {
    int b = blockIdx.x, d = threadIdx.x;
    __shared__ float a0[C_], a1[C_], act[C_];
    a0[d] = lrelu(g_dg[b*C_+d] / AVGF);
    a1[d] = lrelu(g_tot[b*C_+d] / (AVGF*AVGF));
    __syncthreads();
    float a = b20[d];
    for (int c = 0; c < C_; c++) a += a0[c]*w20[c*C_+d] + a1[c]*w20[(C_+c)*C_+d];
    act[d] = a;
    __syncthreads();
    if (d < 2) {
        float o = bmlp[d];
        for (int k = 0; k < C_; k++) o += act[k]*wmlp[k*2+d];
        out[b*2+d] = o;
    }
}

// ---------------- host ----------------
extern "C" void kernel_launch(void* const* d_in, const int* in_sizes, int n_in,
                              void* d_out, int out_size) {
    const float *momenta=0, *scalars=0, *w_lin=0, *alpha=0, *w_in=0, *b_in=0;
    const int* nobj=0;
    const float *msgw[4], *msgb[4], *eqw[4], *eqb[4], *eqbd[4];
    const float *wm0=0, *bm0=0, *w20=0, *b20=0, *wmlp=0, *bmlp=0;

    if (n_in >= 33 && in_sizes[0] == 8192) {
        momenta=(const float*)d_in[0]; scalars=(const float*)d_in[1]; nobj=(const int*)d_in[2];
        w_lin=(const float*)d_in[3]; alpha=(const float*)d_in[4]; w_in=(const float*)d_in[5];
        b_in=(const float*)d_in[6];
        for (int l = 0; l < 4; l++) {
            msgw[l]=(const float*)d_in[7+l];  msgb[l]=(const float*)d_in[11+l];
            eqw[l] =(const float*)d_in[15+l]; eqb[l] =(const float*)d_in[19+l];
            eqbd[l]=(const float*)d_in[23+l];
        }
        wm0=(const float*)d_in[27]; bm0=(const float*)d_in[28]; w20=(const float*)d_in[29];
        b20=(const float*)d_in[30]; wmlp=(const float*)d_in[31]; bmlp=(const float*)d_in[32];
    } else if (n_in >= 33) {
        alpha=(const float*)d_in[0]; b20=(const float*)d_in[1]; b_in=(const float*)d_in[2];
        bm0=(const float*)d_in[3]; bmlp=(const float*)d_in[4];
        for (int l = 0; l < 4; l++) {
            eqb[l] =(const float*)d_in[5+l];  eqbd[l]=(const float*)d_in[9+l];
            eqw[l] =(const float*)d_in[13+l]; msgb[l]=(const float*)d_in[18+l];
            msgw[l]=(const float*)d_in[22+l];
        }
        momenta=(const float*)d_in[17]; nobj=(const int*)d_in[26]; scalars=(const float*)d_in[27];
        w20=(const float*)d_in[28]; w_in=(const float*)d_in[29]; w_lin=(const float*)d_in[30];
        wm0=(const float*)d_in[31]; wmlp=(const float*)d_in[32];
    } else {
        momenta=(const float*)d_in[0]; scalars=(const float*)d_in[1]; nobj=(const int*)d_in[2];
        w_lin=(const float*)d_in[3]; alpha=(const float*)d_in[4]; w_in=(const float*)d_in[5];
        b_in=(const float*)d_in[6];
        for (int l = 0; l < 4; l++) {
            msgw[l]=(const float*)d_in[7]+(size_t)l*C_*C_;     msgb[l]=(const float*)d_in[8]+(size_t)l*C_;
            eqw[l] =(const float*)d_in[9]+(size_t)l*15*C_*C_;  eqb[l] =(const float*)d_in[10]+(size_t)l*C_;
            eqbd[l]=(const float*)d_in[11]+(size_t)l*C_;
        }
        wm0=(const float*)d_in[12]; bm0=(const float*)d_in[13]; w20=(const float*)d_in[14];
        b20=(const float*)d_in[15]; wmlp=(const float*)d_in[16]; bmlp=(const float*)d_in[17];
    }

    cudaFuncSetAttribute(k_gemm, cudaFuncAttributeMaxDynamicSharedMemorySize, SM_G);
    cudaFuncSetAttribute(k_proj, cudaFuncAttributeMaxDynamicSharedMemorySize, SM_P);

    __nv_bfloat16 *Thi=0, *Tlo=0, *Uhi=0, *Ulo=0, *WpH=0, *WpL=0;
    uint4* Bf=0;
    cudaGetSymbolAddress((void**)&Thi, g_Thi);
    cudaGetSymbolAddress((void**)&Tlo, g_Tlo);
    cudaGetSymbolAddress((void**)&Uhi, g_Uhi);
    cudaGetSymbolAddress((void**)&Ulo, g_Ulo);
    cudaGetSymbolAddress((void**)&Bf,  g_Bf);
    cudaGetSymbolAddress((void**)&WpH, g_WpHi);
    cudaGetSymbolAddress((void**)&WpL, g_WpLo);

    k_wsplitF<<<13, 256>>>(msgw[0], msgw[1], msgw[2], msgw[3],
                           eqw[0], eqw[1], eqw[2], eqw[3], wm0);
    k_wsplit2<<<12, 256>>>(eqw[0], eqw[1], eqw[2], eqw[3]);
    k_prep<<<B_, 256>>>(scalars, nobj, w_in);
    k_init<<<B_*N_, 128>>>(momenta, nobj, w_lin, alpha, b_in);

    for (int l = 0; l < 4; l++) {
        k_gemm<<<TILES, 256, SM_G>>>(Thi, Tlo, Bf + l*4096, (const uint4*)0,
                                     msgb[l], nobj, 0);
        k_r1<<<B_*N_, 128>>>(nobj);
        k_proj<<<48, 256, SM_P>>>(WpH + (size_t)l*147456, WpL + (size_t)l*147456);
        k_rpg<<<B_, 128>>>(eqw[l], eqb[l], eqbd[l], nobj);
        k_gemm<<<TILES, 256, SM_G>>>(Uhi, Ulo, Bf + (4 + l*2)*4096, Bf + (5 + l*2)*4096,
                                     msgb[l], nobj, 1);
    }

    k_zero<<<(B_*C_ + 255)/256, 256>>>();
    k_gemm<<<TILES, 256, SM_G>>>(Thi, Tlo, Bf + 12*4096, (const uint4*)0,
                                 bm0, nobj, 3);
    k_out<<<B_, 128>>>(w20, b20, wmlp, bmlp, (float*)d_out);
}

// round 10
// speedup vs baseline: 4.3349x; 1.1908x over previous
#include <cuda_runtime.h>
#include <cuda_bf16.h>
#include <math.h>
#include <stdint.h>

#define B_  32
#define N_  64
#define S_  9
#define C_  128
#define CS_ 32
#define AVGF 49.0f
#define TILES (B_*32)   // 1024 tiles of 128 rows; tile=(b, i-pair), row=(i&1)*64+j

// ---------------- device scratch ----------------
__device__ __nv_bfloat16 g_Thi[TILES*16384], g_Tlo[TILES*16384];
__device__ __nv_bfloat16 g_Uhi[TILES*16384], g_Ulo[TILES*16384];
__device__ float g_X[B_*N_*384];          // [m=b*64+i][dvec|rvec|cvec]
__device__ uint4 g_Bf[13*4096];           // B fragments: [mat][wx][ks][nt][lane] = {b0h,b1h,b0l,b1l}
__device__ __nv_bfloat16 g_WpHi[4*147456], g_WpLo[4*147456];   // proj weights [l][p][n][384k]
__device__ float g_y012[B_*N_*3*CS_];
__device__ float g_y34[B_*2*CS_];
__device__ float g_Vrow[B_*N_*C_];
__device__ float g_Vcol[B_*N_*C_];
__device__ float g_Dd[B_*N_*C_];
__device__ float g_G[B_*C_];
__device__ float g_E[B_*C_];
__device__ float g_dg[B_*C_];
__device__ float g_tot[B_*C_];

__device__ __forceinline__ float lrelu(float x){ return x >= 0.f ? x : 0.01f*x; }
__device__ __forceinline__ uint32_t smem_u32(const void* p) {
    uint32_t a;
    asm("{ .reg .u64 t; cvta.to.shared.u64 t, %1; cvt.u32.u64 %0, t; }" : "=r"(a) : "l"(p));
    return a;
}
__device__ __forceinline__ void split2(float v, __nv_bfloat16& h, __nv_bfloat16& l) {
    h = __float2bfloat16(v);
    l = __float2bfloat16(v - __bfloat162float(h));
}
__device__ __forceinline__ uint32_t packbf(__nv_bfloat16 a, __nv_bfloat16 b) {
    __nv_bfloat162 p; p.x = a; p.y = b;
    return *(uint32_t*)&p;
}
__device__ __forceinline__ void ldmx4(uint32_t a, uint32_t& r0, uint32_t& r1, uint32_t& r2, uint32_t& r3) {
    asm volatile("ldmatrix.sync.aligned.m8n8.x4.shared.b16 {%0,%1,%2,%3}, [%4];"
                 : "=r"(r0), "=r"(r1), "=r"(r2), "=r"(r3) : "r"(a));
}
__device__ __forceinline__ void mma16816(float* c, const uint32_t* a, uint32_t b0, uint32_t b1) {
    asm volatile("mma.sync.aligned.m16n8k16.row.col.f32.bf16.bf16.f32 "
                 "{%0,%1,%2,%3}, {%4,%5,%6,%7}, {%8,%9}, {%0,%1,%2,%3};"
                 : "+f"(c[0]), "+f"(c[1]), "+f"(c[2]), "+f"(c[3])
                 : "r"(a[0]), "r"(a[1]), "r"(a[2]), "r"(a[3]), "r"(b0), "r"(b1));
}
#define CPA16(dst, src) asm volatile("cp.async.ca.shared.global [%0], [%1], 16;" :: "r"(dst), "l"(src))
#define CPCOMMIT() asm volatile("cp.async.commit_group;" ::: "memory")
#define CPWAIT1()  asm volatile("cp.async.wait_group 1;"  ::: "memory")
#define CPWAIT()   asm volatile("cp.async.wait_group 0;"  ::: "memory")

#define AROW2 136
#define ALO2  34816
#define SM_G  69632
#define APAD 72
#define BPAD 80
#define AH_OFF 0
#define AL_OFF 18432
#define BH_OFF 36864
#define BL_OFF 57344
#define SM_P 77824

// ---------------- B fragment pack: [mat][wx][ks][nt][lane] ----------------
__global__ void k_wsplitF(const float* __restrict__ m0, const float* __restrict__ m1,
                          const float* __restrict__ m2, const float* __restrict__ m3,
                          const float* __restrict__ e0, const float* __restrict__ e1,
                          const float* __restrict__ e2, const float* __restrict__ e3,
                          const float* __restrict__ wfin) {
    int mat = blockIdx.x, tid = threadIdx.x;
    const float* W;
    if (mat < 4)       W = (mat==0)?m0:(mat==1)?m1:(mat==2)?m2:m3;
    else if (mat < 12) {
        int l = (mat-4)>>1, wh = (mat-4)&1;
        const float* E = (l==0)?e0:(l==1)?e1:(l==2)?e2:e3;
        W = E + wh*16384;
    } else W = wfin;
    uint4* dst = g_Bf + mat*4096;
    for (int e = tid; e < 4096; e += 256) {
        int lane = e&31, nt = (e>>5)&7, ks = (e>>8)&7, wx = e>>11;
        int n = wx*64 + nt*8 + (lane>>2);
        int k0 = ks*16 + (lane&3)*2;
        __nv_bfloat16 h00,l00,h01,l01,h10,l10,h11,l11;
        split2(W[k0*128+n],     h00, l00);
        split2(W[(k0+1)*128+n], h01, l01);
        split2(W[(k0+8)*128+n], h10, l10);
        split2(W[(k0+9)*128+n], h11, l11);
        uint4 o;
        o.x = packbf(h00,h01); o.y = packbf(h10,h11);
        o.z = packbf(l00,l01); o.w = packbf(l10,l11);
        dst[e] = o;
    }
}

// proj weights: [l][p][n][384] with k-chunks mapping to eq mats
__global__ void k_wsplit2(const float* __restrict__ e0, const float* __restrict__ e1,
                          const float* __restrict__ e2, const float* __restrict__ e3) {
    int l = blockIdx.x / 3, p = blockIdx.x % 3, tid = threadIdx.x;
    const int tbl[3][3] = {{3,5,7},{4,6,8},{2,9,10}};
    const float* E = (l==0)?e0:(l==1)?e1:(l==2)?e2:e3;
    __nv_bfloat16* Hi = g_WpHi + (size_t)l*147456 + p*49152;
    __nv_bfloat16* Lo = g_WpLo + (size_t)l*147456 + p*49152;
    for (int e = tid; e < 49152; e += 256) {
        int n = e / 384, k = e % 384;
        int mat = tbl[p][k>>7], kk = k&127;
        __nv_bfloat16 h, lo;
        split2(E[(mat*C_ + kk)*C_ + n], h, lo);
        Hi[n*384 + k] = h; Lo[n*384 + k] = lo;
    }
}

// ---------------- main GEMM (masked-tile early exit, pipelined K-half staging) --------
// modes: 0 = U = lrelu(acc+bias)*mask
//        1 = T = lrelu(U@W0 + UT@W1 + Vrow+G+Vcol (+Dd+E diag))*mask
//        3 = final: lrelu(acc+bias)*mask -> trace/total reduction
__global__ void __launch_bounds__(256, 2) k_gemm(const __nv_bfloat16* __restrict__ Ahi,
                                                 const __nv_bfloat16* __restrict__ Alo,
                                                 const uint4* __restrict__ F0,
                                                 const uint4* __restrict__ F1,
                                                 const float* __restrict__ bias,
                                                 const int* __restrict__ nobj, int mode) {
    extern __shared__ unsigned char sm[];
    uint32_t sb = smem_u32(sm);
    int tid = threadIdx.x, wid = tid>>5, lane = tid&31;
    int tile = blockIdx.x;
    int b = tile>>5, i0 = (tile&31)<<1;
    int nb = nobj[b];
    if (i0 >= nb) return;   // whole tile masked: outputs are permanently zero

    int wy = wid&3, wx = wid>>2;
    int rb = wy*32, nb0 = wx*64;
    float c[2][8][4];
    #pragma unroll
    for (int mt = 0; mt < 2; mt++)
        #pragma unroll
        for (int nt = 0; nt < 8; nt++)
            #pragma unroll
            for (int q = 0; q < 4; q++) c[mt][nt][q] = 0.f;

    int lrow = (lane&7) + ((lane>>3)&1)*8;
    int lcolb = ((lane>>4)&1)*16;

    int nsrc = (mode == 1) ? 2 : 1;
    for (int src = 0; src < nsrc; src++) {
        if (src) __syncthreads();
        // issue staging in two K-half commit groups (khalf0 first)
        #pragma unroll
        for (int uu = 0; uu < 16; uu++) {
            int group = uu>>3, comp = (uu>>2)&1, sub = uu&3;
            int f = tid + 256*(comp*8 + group*4 + sub);
            int idx = f & 2047;
            int row = (idx>>3)&127, c8 = idx&7, c16 = group*8 + c8;
            const __nv_bfloat16* basep = comp ? Alo : Ahi;
            size_t goff;
            if (src == 0) {
                goff = (size_t)tile*16384 + row*128 + c16*8;
            } else {
                int jj = row&63, hh = row>>6;
                goff = ((size_t)(b*32 + (jj>>1))*128 + (jj&1)*64 + i0 + hh)*128 + c16*8;
            }
            uint32_t dst = sb + comp*ALO2 + row*272 + c16*16;
            CPA16(dst, basep + goff);
            if (uu == 7) CPCOMMIT();
        }
        CPCOMMIT();
        const uint4* Fw = (src ? F1 : F0) + wx*2048;
        #pragma unroll
        for (int half = 0; half < 2; half++) {
            if (half == 0) CPWAIT1(); else CPWAIT();
            __syncthreads();
            #pragma unroll
            for (int ks = half*4; ks < half*4+4; ks++) {
                uint32_t ah[2][4], al[2][4];
                #pragma unroll
                for (int mt = 0; mt < 2; mt++) {
                    uint32_t adr = sb + (rb + mt*16 + lrow)*272 + ks*32 + lcolb;
                    ldmx4(adr, ah[mt][0], ah[mt][1], ah[mt][2], ah[mt][3]);
                    adr += ALO2;
                    ldmx4(adr, al[mt][0], al[mt][1], al[mt][2], al[mt][3]);
                }
                #pragma unroll
                for (int nt = 0; nt < 8; nt++) {
                    uint4 f4 = Fw[(ks*8 + nt)*32 + lane];
                    #pragma unroll
                    for (int mt = 0; mt < 2; mt++) {
                        mma16816(c[mt][nt], ah[mt], f4.x, f4.y);
                        mma16816(c[mt][nt], ah[mt], f4.z, f4.w);
                        mma16816(c[mt][nt], al[mt], f4.x, f4.y);
                    }
                }
            }
        }
    }

    // ---------------- epilogues ----------------
    int g = lane>>2, t2 = (lane&3)*2;
    if (mode == 0 || mode == 1) {
        __nv_bfloat16* Hi = (mode==0 ? g_Uhi : g_Thi) + (size_t)tile*16384;
        __nv_bfloat16* Lo = (mode==0 ? g_Ulo : g_Tlo) + (size_t)tile*16384;
        #pragma unroll
        for (int mt = 0; mt < 2; mt++) {
            #pragma unroll
            for (int h = 0; h < 2; h++) {
                int row = rb + mt*16 + g + h*8;
                int i = i0 + (row>>6), j = row&63;
                float mask = (i < nb && j < nb) ? 1.f : 0.f;
                bool diag = (i == j);
                const float* vr = g_Vrow + (b*64+i)*C_;
                const float* vc = g_Vcol + (b*64+j)*C_;
                const float* gg = g_G + b*C_;
                const float* dd = g_Dd + (b*64+i)*C_;
                const float* ee = g_E + b*C_;
                #pragma unroll
                for (int nt = 0; nt < 8; nt++) {
                    int col = nb0 + nt*8 + t2;
                    float vx, vy;
                    if (mode == 0) {
                        vx = lrelu(c[mt][nt][h*2+0] + bias[col])   * mask;
                        vy = lrelu(c[mt][nt][h*2+1] + bias[col+1]) * mask;
                    } else {
                        vx = c[mt][nt][h*2+0] + vr[col]   + gg[col]   + vc[col];
                        vy = c[mt][nt][h*2+1] + vr[col+1] + gg[col+1] + vc[col+1];
                        if (diag) { vx += dd[col] + ee[col]; vy += dd[col+1] + ee[col+1]; }
                        vx = lrelu(vx) * mask;
                        vy = lrelu(vy) * mask;
                    }
                    __nv_bfloat16 hx,lx,hy,ly;
                    split2(vx, hx, lx); split2(vy, hy, ly);
                    *(uint32_t*)(Hi + row*128 + col) = packbf(hx, hy);
                    *(uint32_t*)(Lo + row*128 + col) = packbf(lx, ly);
                }
            }
        }
    } else {
        __syncthreads();
        float* Vs = (float*)sm;   // [128][132]
        #pragma unroll
        for (int mt = 0; mt < 2; mt++) {
            #pragma unroll
            for (int h = 0; h < 2; h++) {
                int row = rb + mt*16 + g + h*8;
                int i = i0 + (row>>6), j = row&63;
                float mask = (i < nb && j < nb) ? 1.f : 0.f;
                #pragma unroll
                for (int nt = 0; nt < 8; nt++) {
                    int col = nb0 + nt*8 + t2;
                    float2 v;
                    v.x = lrelu(c[mt][nt][h*2+0] + bias[col])   * mask;
                    v.y = lrelu(c[mt][nt][h*2+1] + bias[col+1]) * mask;
                    *(float2*)(Vs + row*132 + col) = v;
                }
            }
        }
        __syncthreads();
        if (tid < 128) {
            float s = 0.f;
            #pragma unroll 8
            for (int r = 0; r < 128; r++) s += Vs[r*132 + tid];
            atomicAdd(&g_tot[b*C_ + tid], s);
            float dgv = Vs[i0*132 + tid] + Vs[(64 + i0 + 1)*132 + tid];
            atomicAdd(&g_dg[b*C_ + tid], dgv);
        }
    }
}

// ---------------- projection GEMM + fused G/E: blocks 0..47 proj, 48..79 rpg ----------
__global__ void __launch_bounds__(256, 2) k_proj(const __nv_bfloat16* __restrict__ Bhi,
                                                 const __nv_bfloat16* __restrict__ Blo,
                                                 const float* __restrict__ W,
                                                 const float* __restrict__ eqb,
                                                 const float* __restrict__ eqbd,
                                                 const int* __restrict__ nobj) {
    extern __shared__ unsigned char sm[];
    if (blockIdx.x >= 48) {
        // fused r2+pg: totals then G/E projections (first 128 threads)
        int b = blockIdx.x - 48, d = threadIdx.x;
        float* tt = (float*)sm;         // [128]
        float* tg = (float*)sm + 128;   // [128]
        if (d < 128) {
            int nb = nobj[b];
            float t = 0.f, tr = 0.f;
            for (int i = 0; i < nb; i++) {
                size_t m = (size_t)(b*N_+i);
                t  += g_X[m*384 + 128 + d];
                tr += g_X[m*384 + d];
            }
            tt[d] = t / AVGF; tg[d] = tr / AVGF;
        }
        __syncthreads();
        if (d < 128) {
            float g = eqb[d], e = eqbd[d];
            for (int c = 0; c < C_; c++) {
                g += tt[c]*W[(11*C_+c)*C_+d] + tg[c]*W[(13*C_+c)*C_+d];
                e += tt[c]*W[(12*C_+c)*C_+d] + tg[c]*W[(14*C_+c)*C_+d];
            }
            g_G[b*C_+d] = g; g_E[b*C_+d] = e;
        }
        return;
    }
    uint32_t sb = smem_u32(sm);
    int tid = threadIdx.x, wid = tid>>5, lane = tid&31;
    int p = blockIdx.x >> 4, tile = blockIdx.x & 15;

    int wy = wid&3, wx = wid>>2;
    int rb = wy*32, nb0 = wx*64;
    float c[2][8][4];
    #pragma unroll
    for (int mt = 0; mt < 2; mt++)
        #pragma unroll
        for (int nt = 0; nt < 8; nt++)
            #pragma unroll
            for (int q = 0; q < 4; q++) c[mt][nt][q] = 0.f;

    int lrow = (lane&7) + ((lane>>3)&1)*8;
    int lcolb = ((lane>>4)&1)*16;
    int bn = nb0 + (lane>>2);
    int btid4 = (lane&3)*4;
    const uint32_t* bhp = (const uint32_t*)(Bhi + p*49152);
    const uint32_t* blp = (const uint32_t*)(Blo + p*49152);
    const float4* Ag = (const float4*)(g_X + (size_t)tile*128*384);

    for (int ph = 0; ph < 6; ph++) {
        if (ph) __syncthreads();
        #pragma unroll
        for (int u = 0; u < 8; u++) {
            int f = tid + 256*u;
            int row = f>>4, q = f&15, c4 = q*4;
            float4 v = Ag[row*96 + ph*16 + q];
            __nv_bfloat16 h[4], l[4];
            split2(v.x, h[0], l[0]); split2(v.y, h[1], l[1]);
            split2(v.z, h[2], l[2]); split2(v.w, h[3], l[3]);
            *(uint2*)(sm + AH_OFF + (row*APAD + c4)*2) = *(uint2*)h;
            *(uint2*)(sm + AL_OFF + (row*APAD + c4)*2) = *(uint2*)l;
        }
        #pragma unroll
        for (int u = 0; u < 16; u++) {
            int f = tid + 256*u;
            int n = f>>5, kp = f&31;
            int k = kp*2;
            int col = (k & ~15) + (((k>>1)&3)<<2) + (((k>>3)&1)<<1);
            *(uint32_t*)(sm + BH_OFF + (n*BPAD + col)*2) = bhp[n*192 + ph*32 + kp];
            *(uint32_t*)(sm + BL_OFF + (n*BPAD + col)*2) = blp[n*192 + ph*32 + kp];
        }
        __syncthreads();
        #pragma unroll
        for (int ks = 0; ks < 4; ks++) {
            uint32_t ah[2][4], al[2][4];
            #pragma unroll
            for (int mt = 0; mt < 2; mt++) {
                uint32_t adr = sb + AH_OFF + (rb + mt*16 + lrow)*APAD*2 + ks*32 + lcolb;
                ldmx4(adr, ah[mt][0], ah[mt][1], ah[mt][2], ah[mt][3]);
                adr = sb + AL_OFF + (rb + mt*16 + lrow)*APAD*2 + ks*32 + lcolb;
                ldmx4(adr, al[mt][0], al[mt][1], al[mt][2], al[mt][3]);
            }
            #pragma unroll
            for (int nt = 0; nt < 8; nt++) {
                uint32_t bh0, bh1, bl0, bl1;
                uint32_t badr = sb + BH_OFF + ((bn + nt*8)*BPAD + ks*16 + btid4)*2;
                asm volatile("ld.shared.v2.b32 {%0,%1}, [%2];" : "=r"(bh0), "=r"(bh1) : "r"(badr));
                badr = sb + BL_OFF + ((bn + nt*8)*BPAD + ks*16 + btid4)*2;
                asm volatile("ld.shared.v2.b32 {%0,%1}, [%2];" : "=r"(bl0), "=r"(bl1) : "r"(badr));
                #pragma unroll
                for (int mt = 0; mt < 2; mt++) {
                    mma16816(c[mt][nt], ah[mt], bh0, bh1);
                    mma16816(c[mt][nt], ah[mt], bl0, bl1);
                    mma16816(c[mt][nt], al[mt], bh0, bh1);
                }
            }
        }
    }
    float* Out = (p==0) ? g_Vrow : (p==1) ? g_Vcol : g_Dd;
    int g = lane>>2, t2 = (lane&3)*2;
    #pragma unroll
    for (int mt = 0; mt < 2; mt++) {
        #pragma unroll
        for (int h = 0; h < 2; h++) {
            int row = rb + mt*16 + g + h*8;
            int m = tile*128 + row;
            #pragma unroll
            for (int nt = 0; nt < 8; nt++) {
                int col = nb0 + nt*8 + t2;
                float2 v;
                v.x = c[mt][nt][h*2+0];
                v.y = c[mt][nt][h*2+1];
                *(float2*)(Out + (size_t)m*128 + col) = v;
            }
        }
    }
}

// ---------------- eq1to2 prep ----------------
__global__ void k_prep(const float* __restrict__ scalars, const int* __restrict__ nobj,
                       const float* __restrict__ w_in) {
    int b = blockIdx.x;
    __shared__ float xs[N_][S_];
    __shared__ float ssum[S_];
    int nb = nobj[b];
    for (int idx = threadIdx.x; idx < N_*S_; idx += blockDim.x) {
        int n = idx/S_, s = idx%S_;
        xs[n][s] = (n < nb) ? scalars[(b*N_+n)*S_+s] : 0.f;
    }
    __syncthreads();
    if (threadIdx.x < S_) {
        float a = 0.f;
        for (int n = 0; n < N_; n++) a += xs[n][threadIdx.x];
        ssum[threadIdx.x] = a / AVGF;
    }
    __syncthreads();
    for (int idx = threadIdx.x; idx < N_*CS_; idx += blockDim.x) {
        int n = idx/CS_, c = idx%CS_;
        float a0=0, a1=0, a2=0;
        #pragma unroll
        for (int s = 0; s < S_; s++) {
            float xv = xs[n][s];
            a0 += xv*w_in[(0*S_+s)*CS_+c];
            a1 += xv*w_in[(1*S_+s)*CS_+c];
            a2 += xv*w_in[(2*S_+s)*CS_+c];
        }
        g_y012[((b*N_+n)*3+0)*CS_+c] = a0;
        g_y012[((b*N_+n)*3+1)*CS_+c] = a1;
        g_y012[((b*N_+n)*3+2)*CS_+c] = a2;
    }
    if (threadIdx.x < 2*CS_) {
        int k = threadIdx.x/CS_, c = threadIdx.x%CS_;
        float a = 0.f;
        #pragma unroll
        for (int s = 0; s < S_; s++) a += ssum[s]*w_in[((3+k)*S_+s)*CS_+c];
        g_y34[(b*2+k)*CS_+c] = a;
    }
}

// ---------------- initial T (bf16 hi/lo, masked rows skipped, 256 thr) ----------------
__global__ void k_init(const float* __restrict__ momenta, const int* __restrict__ nobj,
                       const float* __restrict__ w_lin, const float* __restrict__ alpha,
                       const float* __restrict__ b_in) {
    int b = blockIdx.x / N_, i = blockIdx.x % N_;
    int nb = nobj[b];
    if (i >= nb) return;   // masked row: stays zero forever
    int tid = threadIdx.x;
    int c = tid & 127, jh = tid >> 7;
    __shared__ float pm[N_][4];
    __shared__ float dij[N_];
    __shared__ float y1s[N_][CS_];
    __shared__ float y0r[CS_], y2r[CS_], y3s[CS_], y4s[CS_];
    if (tid < 256) pm[tid>>2][tid&3] = momenta[(b*N_)*4 + tid];
    for (int idx = tid; idx < N_*CS_; idx += 256) {
        int n = idx/CS_, cs = idx%CS_;
        y1s[n][cs] = g_y012[((b*N_+n)*3+1)*CS_+cs];
    }
    if (tid < CS_) {
        y0r[tid] = g_y012[((b*N_+i)*3+0)*CS_+tid];
        y2r[tid] = g_y012[((b*N_+i)*3+2)*CS_+tid];
    } else if (tid < 2*CS_) {
        y3s[tid-CS_] = g_y34[(b*2+0)*CS_+tid-CS_];
    } else if (tid < 3*CS_) {
        y4s[tid-2*CS_] = g_y34[(b*2+1)*CS_+tid-2*CS_];
    }
    __syncthreads();
    if (tid < N_)
        dij[tid] = pm[i][0]*pm[tid][0] - pm[i][1]*pm[tid][1]
                 - pm[i][2]*pm[tid][2] - pm[i][3]*pm[tid][3];
    __syncthreads();
    float base = 0.f, wl = 0.f, al = 0.f;
    if (c < CS_) base = y0r[c] + y3s[c] + b_in[c];
    else { wl = w_lin[c-CS_]; al = alpha[c-CS_]; }
    size_t rowbase = ((size_t)(b*32 + (i>>1))*128 + (i&1)*64)*128;
    for (int j = jh; j < N_; j += 2) {
        float mask = (j < nb) ? 1.f : 0.f;
        float v;
        if (c < CS_) {
            v = base + y1s[j][c];
            if (j == i) v += y2r[c] + y4s[c];
            v = lrelu(v) * mask;
        } else {
            float r = dij[j] * wl;
            v = al * copysignf(log1pf(fabsf(r)), r) * mask;
        }
        __nv_bfloat16 h, l;
        split2(v, h, l);
        g_Thi[rowbase + j*128 + c] = h;
        g_Tlo[rowbase + j*128 + c] = l;
    }
}

// ---------------- reductions from U (bf16 hi/lo) -> X (masked rows skipped) ----------------
__global__ void k_r1(const int* __restrict__ nobj) {
    int b = blockIdx.x >> 6, i = blockIdx.x & 63;
    if (i >= nobj[b]) return;
    int t = threadIdx.x;
    int g = t&15, jg = t>>4;
    __shared__ float red[8][128];
    float aR[8] = {0,0,0,0,0,0,0,0}, aC[8] = {0,0,0,0,0,0,0,0};
    #pragma unroll
    for (int jj = 0; jj < 8; jj++) {
        int j = jg*8 + jj;
        {
            size_t off = ((size_t)(b*32 + (i>>1))*128 + (i&1)*64 + j)*128 + g*8;
            uint4 h4 = *(const uint4*)(g_Uhi + off);
            uint4 l4 = *(const uint4*)(g_Ulo + off);
            const __nv_bfloat16 *hp = (const __nv_bfloat16*)&h4, *lp = (const __nv_bfloat16*)&l4;
            #pragma unroll
            for (int q = 0; q < 8; q++) aR[q] += __bfloat162float(hp[q]) + __bfloat162float(lp[q]);
        }
        {
            size_t off = ((size_t)(b*32 + (j>>1))*128 + (j&1)*64 + i)*128 + g*8;
            uint4 h4 = *(const uint4*)(g_Uhi + off);
            uint4 l4 = *(const uint4*)(g_Ulo + off);
            const __nv_bfloat16 *hp = (const __nv_bfloat16*)&h4, *lp = (const __nv_bfloat16*)&l4;
            #pragma unroll
            for (int q = 0; q < 8; q++) aC[q] += __bfloat162float(hp[q]) + __bfloat162float(lp[q]);
        }
    }
    size_t m = (size_t)(b*N_+i);
    #pragma unroll
    for (int q = 0; q < 8; q++) red[jg][g*8+q] = aR[q];
    __syncthreads();
    { float s = 0.f; for (int r = 0; r < 8; r++) s += red[r][t]; g_X[m*384 + 128 + t] = s/AVGF; }
    __syncthreads();
    #pragma unroll
    for (int q = 0; q < 8; q++) red[jg][g*8+q] = aC[q];
    __syncthreads();
    { float s = 0.f; for (int r = 0; r < 8; r++) s += red[r][t]; g_X[m*384 + 256 + t] = s/AVGF; }
    if (t < 16) {
        size_t off = ((size_t)(b*32 + (i>>1))*128 + (i&1)*64 + i)*128 + t*8;
        uint4 h4 = *(const uint4*)(g_Uhi + off);
        uint4 l4 = *(const uint4*)(g_Ulo + off);
        const __nv_bfloat16 *hp = (const __nv_bfloat16*)&h4, *lp = (const __nv_bfloat16*)&l4;
        #pragma unroll
        for (int q = 0; q < 8; q++)
            g_X[m*384 + t*8 + q] = __bfloat162float(hp[q]) + __bfloat162float(lp[q]);
    }
}

// ---------------- output head (also resets accumulators for next replay) --------------
__global__ void k_out(const float* __restrict__ w20, const float* __restrict__ b20,
                      const float* __restrict__ wmlp, const float* __restrict__ bmlp,
                      float* __restrict__ out) {
    int b = blockIdx.x, d = threadIdx.x;
    __shared__ float a0[C_], a1[C_], act[C_];
    a0[d] = lrelu(g_dg[b*C_+d] / AVGF);
    a1[d] = lrelu(g_tot[b*C_+d] / (AVGF*AVGF));
    g_dg[b*C_+d] = 0.f;
    g_tot[b*C_+d] = 0.f;
    __syncthreads();
    float a = b20[d];
    for (int c = 0; c < C_; c++) a += a0[c]*w20[c*C_+d] + a1[c]*w20[(C_+c)*C_+d];
    act[d] = a;
    __syncthreads();
    if (d < 2) {
        float o = bmlp[d];
        for (int k = 0; k < C_; k++) o += act[k]*wmlp[k*2+d];
        out[b*2+d] = o;
    }
}

// ---------------- host ----------------
extern "C" void kernel_launch(void* const* d_in, const int* in_sizes, int n_in,
                              void* d_out, int out_size) {
    const float *momenta=0, *scalars=0, *w_lin=0, *alpha=0, *w_in=0, *b_in=0;
    const int* nobj=0;
    const float *msgw[4], *msgb[4], *eqw[4], *eqb[4], *eqbd[4];
    const float *wm0=0, *bm0=0, *w20=0, *b20=0, *wmlp=0, *bmlp=0;

    if (n_in >= 33 && in_sizes[0] == 8192) {
        momenta=(const float*)d_in[0]; scalars=(const float*)d_in[1]; nobj=(const int*)d_in[2];
        w_lin=(const float*)d_in[3]; alpha=(const float*)d_in[4]; w_in=(const float*)d_in[5];
        b_in=(const float*)d_in[6];
        for (int l = 0; l < 4; l++) {
            msgw[l]=(const float*)d_in[7+l];  msgb[l]=(const float*)d_in[11+l];
            eqw[l] =(const float*)d_in[15+l]; eqb[l] =(const float*)d_in[19+l];
            eqbd[l]=(const float*)d_in[23+l];
        }
        wm0=(const float*)d_in[27]; bm0=(const float*)d_in[28]; w20=(const float*)d_in[29];
        b20=(const float*)d_in[30]; wmlp=(const float*)d_in[31]; bmlp=(const float*)d_in[32];
    } else if (n_in >= 33) {
        alpha=(const float*)d_in[0]; b20=(const float*)d_in[1]; b_in=(const float*)d_in[2];
        bm0=(const float*)d_in[3]; bmlp=(const float*)d_in[4];
        for (int l = 0; l < 4; l++) {
            eqb[l] =(const float*)d_in[5+l];  eqbd[l]=(const float*)d_in[9+l];
            eqw[l] =(const float*)d_in[13+l]; msgb[l]=(const float*)d_in[18+l];
            msgw[l]=(const float*)d_in[22+l];
        }
        momenta=(const float*)d_in[17]; nobj=(const int*)d_in[26]; scalars=(const float*)d_in[27];
        w20=(const float*)d_in[28]; w_in=(const float*)d_in[29]; w_lin=(const float*)d_in[30];
        wm0=(const float*)d_in[31]; wmlp=(const float*)d_in[32];
    } else {
        momenta=(const float*)d_in[0]; scalars=(const float*)d_in[1]; nobj=(const int*)d_in[2];
        w_lin=(const float*)d_in[3]; alpha=(const float*)d_in[4]; w_in=(const float*)d_in[5];
        b_in=(const float*)d_in[6];
        for (int l = 0; l < 4; l++) {
            msgw[l]=(const float*)d_in[7]+(size_t)l*C_*C_;     msgb[l]=(const float*)d_in[8]+(size_t)l*C_;
            eqw[l] =(const float*)d_in[9]+(size_t)l*15*C_*C_;  eqb[l] =(const float*)d_in[10]+(size_t)l*C_;
            eqbd[l]=(const float*)d_in[11]+(size_t)l*C_;
        }
        wm0=(const float*)d_in[12]; bm0=(const float*)d_in[13]; w20=(const float*)d_in[14];
        b20=(const float*)d_in[15]; wmlp=(const float*)d_in[16]; bmlp=(const float*)d_in[17];
    }

    cudaFuncSetAttribute(k_gemm, cudaFuncAttributeMaxDynamicSharedMemorySize, SM_G);
    cudaFuncSetAttribute(k_proj, cudaFuncAttributeMaxDynamicSharedMemorySize, SM_P);

    __nv_bfloat16 *Thi=0, *Tlo=0, *Uhi=0, *Ulo=0, *WpH=0, *WpL=0;
    uint4* Bf=0;
    cudaGetSymbolAddress((void**)&Thi, g_Thi);
    cudaGetSymbolAddress((void**)&Tlo, g_Tlo);
    cudaGetSymbolAddress((void**)&Uhi, g_Uhi);
    cudaGetSymbolAddress((void**)&Ulo, g_Ulo);
    cudaGetSymbolAddress((void**)&Bf,  g_Bf);
    cudaGetSymbolAddress((void**)&WpH, g_WpHi);
    cudaGetSymbolAddress((void**)&WpL, g_WpLo);

    k_wsplitF<<<13, 256>>>(msgw[0], msgw[1], msgw[2], msgw[3],
                           eqw[0], eqw[1], eqw[2], eqw[3], wm0);
    k_wsplit2<<<12, 256>>>(eqw[0], eqw[1], eqw[2], eqw[3]);
    k_prep<<<B_, 256>>>(scalars, nobj, w_in);
    k_init<<<B_*N_, 256>>>(momenta, nobj, w_lin, alpha, b_in);

    for (int l = 0; l < 4; l++) {
        k_gemm<<<TILES, 256, SM_G>>>(Thi, Tlo, Bf + l*4096, (const uint4*)0,
                                     msgb[l], nobj, 0);
        k_r1<<<B_*N_, 128>>>(nobj);
        k_proj<<<80, 256, SM_P>>>(WpH + (size_t)l*147456, WpL + (size_t)l*147456,
                                  eqw[l], eqb[l], eqbd[l], nobj);
        k_gemm<<<TILES, 256, SM_G>>>(Uhi, Ulo, Bf + (4 + l*2)*4096, Bf + (5 + l*2)*4096,
                                     msgb[l], nobj, 1);
    }

    k_gemm<<<TILES, 256, SM_G>>>(Thi, Tlo, Bf + 12*4096, (const uint4*)0,
                                 bm0, nobj, 3);
    k_out<<<B_, 128>>>(w20, b20, wmlp, bmlp, (float*)d_out);
}

// round 11
// speedup vs baseline: 4.7229x; 1.0895x over previous
#include <cuda_runtime.h>
#include <cuda_bf16.h>
#include <math.h>
#include <stdint.h>

#define B_  32
#define N_  64
#define S_  9
#define C_  128
#define CS_ 32
#define AVGF 49.0f
#define TILES (B_*32)   // 1024 tiles of 128 rows; tile=(b, i-pair), row=(i&1)*64+j

// ---------------- device scratch ----------------
__device__ __nv_bfloat16 g_Thi[TILES*16384], g_Tlo[TILES*16384];
__device__ __nv_bfloat16 g_Uhi[TILES*16384], g_Ulo[TILES*16384];
__device__ float g_X[B_*N_*384];          // [m=b*64+i][dvec|rvec|cvec]
__device__ uint4 g_Bf[13*4096];           // B fragments: [mat][wx][ks][nt][lane]
__device__ __nv_bfloat16 g_WpHi[4*147456], g_WpLo[4*147456];   // proj weights [l][p][n][384k]
__device__ float g_y012[B_*N_*3*CS_];
__device__ float g_y34[B_*2*CS_];
__device__ float g_Vrow[B_*N_*C_];
__device__ float g_Vcol[B_*N_*C_];
__device__ float g_Dd[B_*N_*C_];
__device__ float g_G[B_*C_];
__device__ float g_E[B_*C_];
__device__ float g_dg[B_*C_];
__device__ float g_tot[B_*C_];

__device__ __forceinline__ float lrelu(float x){ return x >= 0.f ? x : 0.01f*x; }
__device__ __forceinline__ uint32_t smem_u32(const void* p) {
    uint32_t a;
    asm("{ .reg .u64 t; cvta.to.shared.u64 t, %1; cvt.u32.u64 %0, t; }" : "=r"(a) : "l"(p));
    return a;
}
__device__ __forceinline__ void split2(float v, __nv_bfloat16& h, __nv_bfloat16& l) {
    h = __float2bfloat16(v);
    l = __float2bfloat16(v - __bfloat162float(h));
}
__device__ __forceinline__ uint32_t packbf(__nv_bfloat16 a, __nv_bfloat16 b) {
    __nv_bfloat162 p; p.x = a; p.y = b;
    return *(uint32_t*)&p;
}
__device__ __forceinline__ void ldmx4(uint32_t a, uint32_t& r0, uint32_t& r1, uint32_t& r2, uint32_t& r3) {
    asm volatile("ldmatrix.sync.aligned.m8n8.x4.shared.b16 {%0,%1,%2,%3}, [%4];"
                 : "=r"(r0), "=r"(r1), "=r"(r2), "=r"(r3) : "r"(a));
}
__device__ __forceinline__ void mma16816(float* c, const uint32_t* a, uint32_t b0, uint32_t b1) {
    asm volatile("mma.sync.aligned.m16n8k16.row.col.f32.bf16.bf16.f32 "
                 "{%0,%1,%2,%3}, {%4,%5,%6,%7}, {%8,%9}, {%0,%1,%2,%3};"
                 : "+f"(c[0]), "+f"(c[1]), "+f"(c[2]), "+f"(c[3])
                 : "r"(a[0]), "r"(a[1]), "r"(a[2]), "r"(a[3]), "r"(b0), "r"(b1));
}
#define CPA16(dst, src) asm volatile("cp.async.ca.shared.global [%0], [%1], 16;" :: "r"(dst), "l"(src))
#define CPCOMMIT() asm volatile("cp.async.commit_group;" ::: "memory")
#define CPWAIT1()  asm volatile("cp.async.wait_group 1;"  ::: "memory")
#define CPWAIT()   asm volatile("cp.async.wait_group 0;"  ::: "memory")

#define AROW2 136
#define ALO2  34816
#define SM_G  69632
#define APAD 72
#define BPAD 80
#define AH_OFF 0
#define AL_OFF 18432
#define BH_OFF 36864
#define BL_OFF 57344
#define SM_P 77824

// ---------------- one-time setup: fragment pack + proj weights + eq1to2 prep ----------
__global__ void k_setup(const float* __restrict__ m0, const float* __restrict__ m1,
                        const float* __restrict__ m2, const float* __restrict__ m3,
                        const float* __restrict__ e0, const float* __restrict__ e1,
                        const float* __restrict__ e2, const float* __restrict__ e3,
                        const float* __restrict__ wfin,
                        const float* __restrict__ scalars, const int* __restrict__ nobj,
                        const float* __restrict__ w_in) {
    int blk = blockIdx.x, tid = threadIdx.x;
    if (blk < 52) {
        // B fragment pack: mat = blk/4, quarter = blk%4
        int mat = blk >> 2, quar = blk & 3;
        const float* W;
        if (mat < 4)       W = (mat==0)?m0:(mat==1)?m1:(mat==2)?m2:m3;
        else if (mat < 12) {
            int l = (mat-4)>>1, wh = (mat-4)&1;
            const float* E = (l==0)?e0:(l==1)?e1:(l==2)?e2:e3;
            W = E + wh*16384;
        } else W = wfin;
        uint4* dst = g_Bf + mat*4096;
        for (int e = quar*1024 + tid; e < quar*1024 + 1024; e += 256) {
            int lane = e&31, nt = (e>>5)&7, ks = (e>>8)&7, wx = e>>11;
            int n = wx*64 + nt*8 + (lane>>2);
            int k0 = ks*16 + (lane&3)*2;
            __nv_bfloat16 h00,l00,h01,l01,h10,l10,h11,l11;
            split2(W[k0*128+n],     h00, l00);
            split2(W[(k0+1)*128+n], h01, l01);
            split2(W[(k0+8)*128+n], h10, l10);
            split2(W[(k0+9)*128+n], h11, l11);
            uint4 o;
            o.x = packbf(h00,h01); o.y = packbf(h10,h11);
            o.z = packbf(l00,l01); o.w = packbf(l10,l11);
            dst[e] = o;
        }
    } else if (blk < 100) {
        // proj weights: idx = blk-52; unit = idx/4 -> (l,p), quarter = idx%4
        int idx = blk - 52;
        int unit = idx >> 2, quar = idx & 3;
        int l = unit / 3, p = unit % 3;
        const int tbl[3][3] = {{3,5,7},{4,6,8},{2,9,10}};
        const float* E = (l==0)?e0:(l==1)?e1:(l==2)?e2:e3;
        __nv_bfloat16* Hi = g_WpHi + (size_t)l*147456 + p*49152;
        __nv_bfloat16* Lo = g_WpLo + (size_t)l*147456 + p*49152;
        for (int e = quar*12288 + tid; e < quar*12288 + 12288; e += 256) {
            int n = e / 384, k = e % 384;
            int mat = tbl[p][k>>7], kk = k&127;
            __nv_bfloat16 h, lo;
            split2(E[(mat*C_ + kk)*C_ + n], h, lo);
            Hi[n*384 + k] = h; Lo[n*384 + k] = lo;
        }
    } else {
        // eq1to2 prep: b = blk-100
        int b = blk - 100;
        __shared__ float xs[N_][S_];
        __shared__ float ssum[S_];
        int nb = nobj[b];
        for (int idx = tid; idx < N_*S_; idx += 256) {
            int n = idx/S_, s = idx%S_;
            xs[n][s] = (n < nb) ? scalars[(b*N_+n)*S_+s] : 0.f;
        }
        __syncthreads();
        if (tid < S_) {
            float a = 0.f;
            for (int n = 0; n < N_; n++) a += xs[n][tid];
            ssum[tid] = a / AVGF;
        }
        __syncthreads();
        for (int idx = tid; idx < N_*CS_; idx += 256) {
            int n = idx/CS_, c = idx%CS_;
            float a0=0, a1=0, a2=0;
            #pragma unroll
            for (int s = 0; s < S_; s++) {
                float xv = xs[n][s];
                a0 += xv*w_in[(0*S_+s)*CS_+c];
                a1 += xv*w_in[(1*S_+s)*CS_+c];
                a2 += xv*w_in[(2*S_+s)*CS_+c];
            }
            g_y012[((b*N_+n)*3+0)*CS_+c] = a0;
            g_y012[((b*N_+n)*3+1)*CS_+c] = a1;
            g_y012[((b*N_+n)*3+2)*CS_+c] = a2;
        }
        if (tid < 2*CS_) {
            int k = tid/CS_, c = tid%CS_;
            float a = 0.f;
            #pragma unroll
            for (int s = 0; s < S_; s++) a += ssum[s]*w_in[((3+k)*S_+s)*CS_+c];
            g_y34[(b*2+k)*CS_+c] = a;
        }
    }
}

// ---------------- main GEMM (masked-tile early exit, pipelined staging, B prefetch) ---
// modes: 0 = U = lrelu(acc+bias)*mask
//        1 = T = lrelu(U@W0 + UT@W1 + Vrow+G+Vcol (+Dd+E diag))*mask
//        3 = final: lrelu(acc+bias)*mask -> trace/total reduction
__global__ void __launch_bounds__(256, 2) k_gemm(const __nv_bfloat16* __restrict__ Ahi,
                                                 const __nv_bfloat16* __restrict__ Alo,
                                                 const uint4* __restrict__ F0,
                                                 const uint4* __restrict__ F1,
                                                 const float* __restrict__ bias,
                                                 const int* __restrict__ nobj, int mode) {
    extern __shared__ unsigned char sm[];
    uint32_t sb = smem_u32(sm);
    int tid = threadIdx.x, wid = tid>>5, lane = tid&31;
    int tile = blockIdx.x;
    int b = tile>>5, i0 = (tile&31)<<1;
    int nb = nobj[b];
    if (i0 >= nb) return;

    int wy = wid&3, wx = wid>>2;
    int rb = wy*32, nb0 = wx*64;
    float c[2][8][4];
    #pragma unroll
    for (int mt = 0; mt < 2; mt++)
        #pragma unroll
        for (int nt = 0; nt < 8; nt++)
            #pragma unroll
            for (int q = 0; q < 4; q++) c[mt][nt][q] = 0.f;

    int lrow = (lane&7) + ((lane>>3)&1)*8;
    int lcolb = ((lane>>4)&1)*16;

    int nsrc = (mode == 1) ? 2 : 1;
    for (int src = 0; src < nsrc; src++) {
        if (src) __syncthreads();
        #pragma unroll
        for (int uu = 0; uu < 16; uu++) {
            int group = uu>>3, comp = (uu>>2)&1, sub = uu&3;
            int f = tid + 256*(comp*8 + group*4 + sub);
            int idx = f & 2047;
            int row = (idx>>3)&127, c8 = idx&7, c16 = group*8 + c8;
            const __nv_bfloat16* basep = comp ? Alo : Ahi;
            size_t goff;
            if (src == 0) {
                goff = (size_t)tile*16384 + row*128 + c16*8;
            } else {
                int jj = row&63, hh = row>>6;
                goff = ((size_t)(b*32 + (jj>>1))*128 + (jj&1)*64 + i0 + hh)*128 + c16*8;
            }
            uint32_t dst = sb + comp*ALO2 + row*272 + c16*16;
            CPA16(dst, basep + goff);
            if (uu == 7) CPCOMMIT();
        }
        CPCOMMIT();
        const uint4* Fw = (src ? F1 : F0) + wx*2048;
        #pragma unroll
        for (int half = 0; half < 2; half++) {
            if (half == 0) CPWAIT1(); else CPWAIT();
            __syncthreads();
            #pragma unroll
            for (int ks = half*4; ks < half*4+4; ks++) {
                uint32_t ah[2][4], al[2][4];
                #pragma unroll
                for (int mt = 0; mt < 2; mt++) {
                    uint32_t adr = sb + (rb + mt*16 + lrow)*272 + ks*32 + lcolb;
                    ldmx4(adr, ah[mt][0], ah[mt][1], ah[mt][2], ah[mt][3]);
                    adr += ALO2;
                    ldmx4(adr, al[mt][0], al[mt][1], al[mt][2], al[mt][3]);
                }
                uint4 f4 = Fw[(ks*8)*32 + lane];
                #pragma unroll
                for (int nt = 0; nt < 8; nt++) {
                    uint4 cur = f4;
                    if (nt < 7) f4 = Fw[(ks*8 + nt + 1)*32 + lane];
                    #pragma unroll
                    for (int mt = 0; mt < 2; mt++) {
                        mma16816(c[mt][nt], ah[mt], cur.x, cur.y);
                        mma16816(c[mt][nt], ah[mt], cur.z, cur.w);
                        mma16816(c[mt][nt], al[mt], cur.x, cur.y);
                    }
                }
            }
        }
    }

    // ---------------- epilogues ----------------
    int g = lane>>2, t2 = (lane&3)*2;
    if (mode == 0 || mode == 1) {
        __nv_bfloat16* Hi = (mode==0 ? g_Uhi : g_Thi) + (size_t)tile*16384;
        __nv_bfloat16* Lo = (mode==0 ? g_Ulo : g_Tlo) + (size_t)tile*16384;
        #pragma unroll
        for (int mt = 0; mt < 2; mt++) {
            #pragma unroll
            for (int h = 0; h < 2; h++) {
                int row = rb + mt*16 + g + h*8;
                int i = i0 + (row>>6), j = row&63;
                float mask = (i < nb && j < nb) ? 1.f : 0.f;
                bool diag = (i == j);
                const float* vr = g_Vrow + (b*64+i)*C_;
                const float* vc = g_Vcol + (b*64+j)*C_;
                const float* gg = g_G + b*C_;
                const float* dd = g_Dd + (b*64+i)*C_;
                const float* ee = g_E + b*C_;
                #pragma unroll
                for (int nt = 0; nt < 8; nt++) {
                    int col = nb0 + nt*8 + t2;
                    float vx, vy;
                    if (mode == 0) {
                        vx = lrelu(c[mt][nt][h*2+0] + bias[col])   * mask;
                        vy = lrelu(c[mt][nt][h*2+1] + bias[col+1]) * mask;
                    } else {
                        vx = c[mt][nt][h*2+0] + vr[col]   + gg[col]   + vc[col];
                        vy = c[mt][nt][h*2+1] + vr[col+1] + gg[col+1] + vc[col+1];
                        if (diag) { vx += dd[col] + ee[col]; vy += dd[col+1] + ee[col+1]; }
                        vx = lrelu(vx) * mask;
                        vy = lrelu(vy) * mask;
                    }
                    __nv_bfloat16 hx,lx,hy,ly;
                    split2(vx, hx, lx); split2(vy, hy, ly);
                    *(uint32_t*)(Hi + row*128 + col) = packbf(hx, hy);
                    *(uint32_t*)(Lo + row*128 + col) = packbf(lx, ly);
                }
            }
        }
    } else {
        __syncthreads();
        float* Vs = (float*)sm;   // [128][132]
        #pragma unroll
        for (int mt = 0; mt < 2; mt++) {
            #pragma unroll
            for (int h = 0; h < 2; h++) {
                int row = rb + mt*16 + g + h*8;
                int i = i0 + (row>>6), j = row&63;
                float mask = (i < nb && j < nb) ? 1.f : 0.f;
                #pragma unroll
                for (int nt = 0; nt < 8; nt++) {
                    int col = nb0 + nt*8 + t2;
                    float2 v;
                    v.x = lrelu(c[mt][nt][h*2+0] + bias[col])   * mask;
                    v.y = lrelu(c[mt][nt][h*2+1] + bias[col+1]) * mask;
                    *(float2*)(Vs + row*132 + col) = v;
                }
            }
        }
        __syncthreads();
        if (tid < 128) {
            float s = 0.f;
            #pragma unroll 8
            for (int r = 0; r < 128; r++) s += Vs[r*132 + tid];
            atomicAdd(&g_tot[b*C_ + tid], s);
            float dgv = Vs[i0*132 + tid] + Vs[(64 + i0 + 1)*132 + tid];
            atomicAdd(&g_dg[b*C_ + tid], dgv);
        }
    }
}

// ---------------- projection GEMM + fused G/E: blocks 0..47 proj, 48..79 rpg ----------
__global__ void __launch_bounds__(256, 2) k_proj(const __nv_bfloat16* __restrict__ Bhi,
                                                 const __nv_bfloat16* __restrict__ Blo,
                                                 const float* __restrict__ W,
                                                 const float* __restrict__ eqb,
                                                 const float* __restrict__ eqbd,
                                                 const int* __restrict__ nobj) {
    extern __shared__ unsigned char sm[];
    if (blockIdx.x >= 48) {
        int b = blockIdx.x - 48, d = threadIdx.x;
        float* tt = (float*)sm;
        float* tg = (float*)sm + 128;
        if (d < 128) {
            int nb = nobj[b];
            float t = 0.f, tr = 0.f;
            for (int i = 0; i < nb; i++) {
                size_t m = (size_t)(b*N_+i);
                t  += g_X[m*384 + 128 + d];
                tr += g_X[m*384 + d];
            }
            tt[d] = t / AVGF; tg[d] = tr / AVGF;
        }
        __syncthreads();
        if (d < 128) {
            float g = eqb[d], e = eqbd[d];
            for (int c = 0; c < C_; c++) {
                g += tt[c]*W[(11*C_+c)*C_+d] + tg[c]*W[(13*C_+c)*C_+d];
                e += tt[c]*W[(12*C_+c)*C_+d] + tg[c]*W[(14*C_+c)*C_+d];
            }
            g_G[b*C_+d] = g; g_E[b*C_+d] = e;
        }
        return;
    }
    uint32_t sb = smem_u32(sm);
    int tid = threadIdx.x, wid = tid>>5, lane = tid&31;
    int p = blockIdx.x >> 4, tile = blockIdx.x & 15;

    int wy = wid&3, wx = wid>>2;
    int rb = wy*32, nb0 = wx*64;
    float c[2][8][4];
    #pragma unroll
    for (int mt = 0; mt < 2; mt++)
        #pragma unroll
        for (int nt = 0; nt < 8; nt++)
            #pragma unroll
            for (int q = 0; q < 4; q++) c[mt][nt][q] = 0.f;

    int lrow = (lane&7) + ((lane>>3)&1)*8;
    int lcolb = ((lane>>4)&1)*16;
    int bn = nb0 + (lane>>2);
    int btid4 = (lane&3)*4;
    const uint32_t* bhp = (const uint32_t*)(Bhi + p*49152);
    const uint32_t* blp = (const uint32_t*)(Blo + p*49152);
    const float4* Ag = (const float4*)(g_X + (size_t)tile*128*384);

    for (int ph = 0; ph < 6; ph++) {
        if (ph) __syncthreads();
        #pragma unroll
        for (int u = 0; u < 8; u++) {
            int f = tid + 256*u;
            int row = f>>4, q = f&15, c4 = q*4;
            float4 v = Ag[row*96 + ph*16 + q];
            __nv_bfloat16 h[4], l[4];
            split2(v.x, h[0], l[0]); split2(v.y, h[1], l[1]);
            split2(v.z, h[2], l[2]); split2(v.w, h[3], l[3]);
            *(uint2*)(sm + AH_OFF + (row*APAD + c4)*2) = *(uint2*)h;
            *(uint2*)(sm + AL_OFF + (row*APAD + c4)*2) = *(uint2*)l;
        }
        #pragma unroll
        for (int u = 0; u < 16; u++) {
            int f = tid + 256*u;
            int n = f>>5, kp = f&31;
            int k = kp*2;
            int col = (k & ~15) + (((k>>1)&3)<<2) + (((k>>3)&1)<<1);
            *(uint32_t*)(sm + BH_OFF + (n*BPAD + col)*2) = bhp[n*192 + ph*32 + kp];
            *(uint32_t*)(sm + BL_OFF + (n*BPAD + col)*2) = blp[n*192 + ph*32 + kp];
        }
        __syncthreads();
        #pragma unroll
        for (int ks = 0; ks < 4; ks++) {
            uint32_t ah[2][4], al[2][4];
            #pragma unroll
            for (int mt = 0; mt < 2; mt++) {
                uint32_t adr = sb + AH_OFF + (rb + mt*16 + lrow)*APAD*2 + ks*32 + lcolb;
                ldmx4(adr, ah[mt][0], ah[mt][1], ah[mt][2], ah[mt][3]);
                adr = sb + AL_OFF + (rb + mt*16 + lrow)*APAD*2 + ks*32 + lcolb;
                ldmx4(adr, al[mt][0], al[mt][1], al[mt][2], al[mt][3]);
            }
            #pragma unroll
            for (int nt = 0; nt < 8; nt++) {
                uint32_t bh0, bh1, bl0, bl1;
                uint32_t badr = sb + BH_OFF + ((bn + nt*8)*BPAD + ks*16 + btid4)*2;
                asm volatile("ld.shared.v2.b32 {%0,%1}, [%2];" : "=r"(bh0), "=r"(bh1) : "r"(badr));
                badr = sb + BL_OFF + ((bn + nt*8)*BPAD + ks*16 + btid4)*2;
                asm volatile("ld.shared.v2.b32 {%0,%1}, [%2];" : "=r"(bl0), "=r"(bl1) : "r"(badr));
                #pragma unroll
                for (int mt = 0; mt < 2; mt++) {
                    mma16816(c[mt][nt], ah[mt], bh0, bh1);
                    mma16816(c[mt][nt], ah[mt], bl0, bl1);
                    mma16816(c[mt][nt], al[mt], bh0, bh1);
                }
            }
        }
    }
    float* Out = (p==0) ? g_Vrow : (p==1) ? g_Vcol : g_Dd;
    int g = lane>>2, t2 = (lane&3)*2;
    #pragma unroll
    for (int mt = 0; mt < 2; mt++) {
        #pragma unroll
        for (int h = 0; h < 2; h++) {
            int row = rb + mt*16 + g + h*8;
            int m = tile*128 + row;
            #pragma unroll
            for (int nt = 0; nt < 8; nt++) {
                int col = nb0 + nt*8 + t2;
                float2 v;
                v.x = c[mt][nt][h*2+0];
                v.y = c[mt][nt][h*2+1];
                *(float2*)(Out + (size_t)m*128 + col) = v;
            }
        }
    }
}

// ---------------- initial T (bf16 hi/lo, masked rows skipped, 256 thr) ----------------
__global__ void k_init(const float* __restrict__ momenta, const int* __restrict__ nobj,
                       const float* __restrict__ w_lin, const float* __restrict__ alpha,
                       const float* __restrict__ b_in) {
    int b = blockIdx.x / N_, i = blockIdx.x % N_;
    int nb = nobj[b];
    if (i >= nb) return;
    int tid = threadIdx.x;
    int c = tid & 127, jh = tid >> 7;
    __shared__ float pm[N_][4];
    __shared__ float dij[N_];
    __shared__ float y1s[N_][CS_];
    __shared__ float y0r[CS_], y2r[CS_], y3s[CS_], y4s[CS_];
    if (tid < 256) pm[tid>>2][tid&3] = momenta[(b*N_)*4 + tid];
    for (int idx = tid; idx < N_*CS_; idx += 256) {
        int n = idx/CS_, cs = idx%CS_;
        y1s[n][cs] = g_y012[((b*N_+n)*3+1)*CS_+cs];
    }
    if (tid < CS_) {
        y0r[tid] = g_y012[((b*N_+i)*3+0)*CS_+tid];
        y2r[tid] = g_y012[((b*N_+i)*3+2)*CS_+tid];
    } else if (tid < 2*CS_) {
        y3s[tid-CS_] = g_y34[(b*2+0)*CS_+tid-CS_];
    } else if (tid < 3*CS_) {
        y4s[tid-2*CS_] = g_y34[(b*2+1)*CS_+tid-2*CS_];
    }
    __syncthreads();
    if (tid < N_)
        dij[tid] = pm[i][0]*pm[tid][0] - pm[i][1]*pm[tid][1]
                 - pm[i][2]*pm[tid][2] - pm[i][3]*pm[tid][3];
    __syncthreads();
    float base = 0.f, wl = 0.f, al = 0.f;
    if (c < CS_) base = y0r[c] + y3s[c] + b_in[c];
    else { wl = w_lin[c-CS_]; al = alpha[c-CS_]; }
    size_t rowbase = ((size_t)(b*32 + (i>>1))*128 + (i&1)*64)*128;
    for (int j = jh; j < N_; j += 2) {
        float mask = (j < nb) ? 1.f : 0.f;
        float v;
        if (c < CS_) {
            v = base + y1s[j][c];
            if (j == i) v += y2r[c] + y4s[c];
            v = lrelu(v) * mask;
        } else {
            float r = dij[j] * wl;
            v = al * copysignf(log1pf(fabsf(r)), r) * mask;
        }
        __nv_bfloat16 h, l;
        split2(v, h, l);
        g_Thi[rowbase + j*128 + c] = h;
        g_Tlo[rowbase + j*128 + c] = l;
    }
}

// ---------------- reductions from U -> X (256 threads, single sync) ----------------
__global__ void k_r1(const int* __restrict__ nobj) {
    int b = blockIdx.x >> 6, i = blockIdx.x & 63;
    if (i >= nobj[b]) return;
    int t = threadIdx.x;
    int g = t & 15, jg = t >> 4;    // 16 col-granules x 16 j-groups of 4
    __shared__ float redR[16][128], redC[16][128];
    float aR[8] = {0,0,0,0,0,0,0,0}, aC[8] = {0,0,0,0,0,0,0,0};
    #pragma unroll
    for (int jj = 0; jj < 4; jj++) {
        int j = jg*4 + jj;
        {
            size_t off = ((size_t)(b*32 + (i>>1))*128 + (i&1)*64 + j)*128 + g*8;
            uint4 h4 = *(const uint4*)(g_Uhi + off);
            uint4 l4 = *(const uint4*)(g_Ulo + off);
            const __nv_bfloat16 *hp = (const __nv_bfloat16*)&h4, *lp = (const __nv_bfloat16*)&l4;
            #pragma unroll
            for (int q = 0; q < 8; q++) aR[q] += __bfloat162float(hp[q]) + __bfloat162float(lp[q]);
        }
        {
            size_t off = ((size_t)(b*32 + (j>>1))*128 + (j&1)*64 + i)*128 + g*8;
            uint4 h4 = *(const uint4*)(g_Uhi + off);
            uint4 l4 = *(const uint4*)(g_Ulo + off);
            const __nv_bfloat16 *hp = (const __nv_bfloat16*)&h4, *lp = (const __nv_bfloat16*)&l4;
            #pragma unroll
            for (int q = 0; q < 8; q++) aC[q] += __bfloat162float(hp[q]) + __bfloat162float(lp[q]);
        }
    }
    #pragma unroll
    for (int q = 0; q < 8; q++) { redR[jg][g*8+q] = aR[q]; redC[jg][g*8+q] = aC[q]; }
    __syncthreads();
    size_t m = (size_t)(b*N_+i);
    if (t < 128) {
        float s = 0.f;
        #pragma unroll
        for (int r = 0; r < 16; r++) s += redR[r][t];
        g_X[m*384 + 128 + t] = s / AVGF;
    } else {
        int d = t - 128;
        float s = 0.f;
        #pragma unroll
        for (int r = 0; r < 16; r++) s += redC[r][d];
        g_X[m*384 + 256 + d] = s / AVGF;
    }
    if (t < 16) {
        size_t off = ((size_t)(b*32 + (i>>1))*128 + (i&1)*64 + i)*128 + t*8;
        uint4 h4 = *(const uint4*)(g_Uhi + off);
        uint4 l4 = *(const uint4*)(g_Ulo + off);
        const __nv_bfloat16 *hp = (const __nv_bfloat16*)&h4, *lp = (const __nv_bfloat16*)&l4;
        #pragma unroll
        for (int q = 0; q < 8; q++)
            g_X[m*384 + t*8 + q] = __bfloat162float(hp[q]) + __bfloat162float(lp[q]);
    }
}

// ---------------- output head (also resets accumulators for next replay) --------------
__global__ void k_out(const float* __restrict__ w20, const float* __restrict__ b20,
                      const float* __restrict__ wmlp, const float* __restrict__ bmlp,
                      float* __restrict__ out) {
    int b = blockIdx.x, d = threadIdx.x;
    __shared__ float a0[C_], a1[C_], act[C_];
    a0[d] = lrelu(g_dg[b*C_+d] / AVGF);
    a1[d] = lrelu(g_tot[b*C_+d] / (AVGF*AVGF));
    g_dg[b*C_+d] = 0.f;
    g_tot[b*C_+d] = 0.f;
    __syncthreads();
    float a = b20[d];
    for (int c = 0; c < C_; c++) a += a0[c]*w20[c*C_+d] + a1[c]*w20[(C_+c)*C_+d];
    act[d] = a;
    __syncthreads();
    if (d < 2) {
        float o = bmlp[d];
        for (int k = 0; k < C_; k++) o += act[k]*wmlp[k*2+d];
        out[b*2+d] = o;
    }
}

// ---------------- host ----------------
extern "C" void kernel_launch(void* const* d_in, const int* in_sizes, int n_in,
                              void* d_out, int out_size) {
    const float *momenta=0, *scalars=0, *w_lin=0, *alpha=0, *w_in=0, *b_in=0;
    const int* nobj=0;
    const float *msgw[4], *msgb[4], *eqw[4], *eqb[4], *eqbd[4];
    const float *wm0=0, *bm0=0, *w20=0, *b20=0, *wmlp=0, *bmlp=0;

    if (n_in >= 33 && in_sizes[0] == 8192) {
        momenta=(const float*)d_in[0]; scalars=(const float*)d_in[1]; nobj=(const int*)d_in[2];
        w_lin=(const float*)d_in[3]; alpha=(const float*)d_in[4]; w_in=(const float*)d_in[5];
        b_in=(const float*)d_in[6];
        for (int l = 0; l < 4; l++) {
            msgw[l]=(const float*)d_in[7+l];  msgb[l]=(const float*)d_in[11+l];
            eqw[l] =(const float*)d_in[15+l]; eqb[l] =(const float*)d_in[19+l];
            eqbd[l]=(const float*)d_in[23+l];
        }
        wm0=(const float*)d_in[27]; bm0=(const float*)d_in[28]; w20=(const float*)d_in[29];
        b20=(const float*)d_in[30]; wmlp=(const float*)d_in[31]; bmlp=(const float*)d_in[32];
    } else if (n_in >= 33) {
        alpha=(const float*)d_in[0]; b20=(const float*)d_in[1]; b_in=(const float*)d_in[2];
        bm0=(const float*)d_in[3]; bmlp=(const float*)d_in[4];
        for (int l = 0; l < 4; l++) {
            eqb[l] =(const float*)d_in[5+l];  eqbd[l]=(const float*)d_in[9+l];
            eqw[l] =(const float*)d_in[13+l]; msgb[l]=(const float*)d_in[18+l];
            msgw[l]=(const float*)d_in[22+l];
        }
        momenta=(const float*)d_in[17]; nobj=(const int*)d_in[26]; scalars=(const float*)d_in[27];
        w20=(const float*)d_in[28]; w_in=(const float*)d_in[29]; w_lin=(const float*)d_in[30];
        wm0=(const float*)d_in[31]; wmlp=(const float*)d_in[32];
    } else {
        momenta=(const float*)d_in[0]; scalars=(const float*)d_in[1]; nobj=(const int*)d_in[2];
        w_lin=(const float*)d_in[3]; alpha=(const float*)d_in[4]; w_in=(const float*)d_in[5];
        b_in=(const float*)d_in[6];
        for (int l = 0; l < 4; l++) {
            msgw[l]=(const float*)d_in[7]+(size_t)l*C_*C_;     msgb[l]=(const float*)d_in[8]+(size_t)l*C_;
            eqw[l] =(const float*)d_in[9]+(size_t)l*15*C_*C_;  eqb[l] =(const float*)d_in[10]+(size_t)l*C_;
            eqbd[l]=(const float*)d_in[11]+(size_t)l*C_;
        }
        wm0=(const float*)d_in[12]; bm0=(const float*)d_in[13]; w20=(const float*)d_in[14];
        b20=(const float*)d_in[15]; wmlp=(const float*)d_in[16]; bmlp=(const float*)d_in[17];
    }

    cudaFuncSetAttribute(k_gemm, cudaFuncAttributeMaxDynamicSharedMemorySize, SM_G);
    cudaFuncSetAttribute(k_proj, cudaFuncAttributeMaxDynamicSharedMemorySize, SM_P);

    __nv_bfloat16 *Thi=0, *Tlo=0, *Uhi=0, *Ulo=0, *WpH=0, *WpL=0;
    uint4* Bf=0;
    cudaGetSymbolAddress((void**)&Thi, g_Thi);
    cudaGetSymbolAddress((void**)&Tlo, g_Tlo);
    cudaGetSymbolAddress((void**)&Uhi, g_Uhi);
    cudaGetSymbolAddress((void**)&Ulo, g_Ulo);
    cudaGetSymbolAddress((void**)&Bf,  g_Bf);
    cudaGetSymbolAddress((void**)&WpH, g_WpHi);
    cudaGetSymbolAddress((void**)&WpL, g_WpLo);

    k_setup<<<132, 256>>>(msgw[0], msgw[1], msgw[2], msgw[3],
                          eqw[0], eqw[1], eqw[2], eqw[3], wm0,
                          scalars, nobj, w_in);
    k_init<<<B_*N_, 256>>>(momenta, nobj, w_lin, alpha, b_in);

    for (int l = 0; l < 4; l++) {
        k_gemm<<<TILES, 256, SM_G>>>(Thi, Tlo, Bf + l*4096, (const uint4*)0,
                                     msgb[l], nobj, 0);
        k_r1<<<B_*N_, 256>>>(nobj);
        k_proj<<<80, 256, SM_P>>>(WpH + (size_t)l*147456, WpL + (size_t)l*147456,
                                  eqw[l], eqb[l], eqbd[l], nobj);
        k_gemm<<<TILES, 256, SM_G>>>(Uhi, Ulo, Bf + (4 + l*2)*4096, Bf + (5 + l*2)*4096,
                                     msgb[l], nobj, 1);
    }

    k_gemm<<<TILES, 256, SM_G>>>(Thi, Tlo, Bf + 12*4096, (const uint4*)0,
                                 bm0, nobj, 3);
    k_out<<<B_, 128>>>(w20, b20, wmlp, bmlp, (float*)d_out);
}

// round 12
// speedup vs baseline: 5.5236x; 1.1695x over previous
#include <cuda_runtime.h>
#include <cuda_bf16.h>
#include <math.h>
#include <stdint.h>

#define B_  32
#define N_  64
#define S_  9
#define C_  128
#define CS_ 32
#define AVGF 49.0f
#define TILES (B_*32)

// ---------------- device scratch ----------------
__device__ __nv_bfloat16 g_Ahi[TILES*16384], g_Alo[TILES*16384];   // U buffer A (also T-init)
__device__ __nv_bfloat16 g_Bhi[TILES*16384], g_Blo[TILES*16384];   // U buffer B
__device__ float g_X[B_*N_*384];
__device__ uint4 g_Bf[13*4096];
__device__ __nv_bfloat16 g_WpHi[4*147456], g_WpLo[4*147456];
__device__ float g_y012[B_*N_*3*CS_];
__device__ float g_y34[B_*2*CS_];
__device__ float g_Vrow[B_*N_*C_];
__device__ float g_Vcol[B_*N_*C_];
__device__ float g_Dd[B_*N_*C_];
__device__ float g_G[B_*C_];
__device__ float g_E[B_*C_];
__device__ float g_dg[B_*C_];
__device__ float g_tot[B_*C_];

__device__ __forceinline__ float lrelu(float x){ return x >= 0.f ? x : 0.01f*x; }
__device__ __forceinline__ uint32_t smem_u32(const void* p) {
    uint32_t a;
    asm("{ .reg .u64 t; cvta.to.shared.u64 t, %1; cvt.u32.u64 %0, t; }" : "=r"(a) : "l"(p));
    return a;
}
__device__ __forceinline__ void split2(float v, __nv_bfloat16& h, __nv_bfloat16& l) {
    h = __float2bfloat16(v);
    l = __float2bfloat16(v - __bfloat162float(h));
}
__device__ __forceinline__ uint32_t packbf(__nv_bfloat16 a, __nv_bfloat16 b) {
    __nv_bfloat162 p; p.x = a; p.y = b;
    return *(uint32_t*)&p;
}
__device__ __forceinline__ void ldmx4(uint32_t a, uint32_t& r0, uint32_t& r1, uint32_t& r2, uint32_t& r3) {
    asm volatile("ldmatrix.sync.aligned.m8n8.x4.shared.b16 {%0,%1,%2,%3}, [%4];"
                 : "=r"(r0), "=r"(r1), "=r"(r2), "=r"(r3) : "r"(a));
}
__device__ __forceinline__ void mma16816(float* c, const uint32_t* a, uint32_t b0, uint32_t b1) {
    asm volatile("mma.sync.aligned.m16n8k16.row.col.f32.bf16.bf16.f32 "
                 "{%0,%1,%2,%3}, {%4,%5,%6,%7}, {%8,%9}, {%0,%1,%2,%3};"
                 : "+f"(c[0]), "+f"(c[1]), "+f"(c[2]), "+f"(c[3])
                 : "r"(a[0]), "r"(a[1]), "r"(a[2]), "r"(a[3]), "r"(b0), "r"(b1));
}
#define CPA16(dst, src) asm volatile("cp.async.ca.shared.global [%0], [%1], 16;" :: "r"(dst), "l"(src))
#define CPCOMMIT() asm volatile("cp.async.commit_group;" ::: "memory")
#define CPWAIT1()  asm volatile("cp.async.wait_group 1;"  ::: "memory")
#define CPWAIT()   asm volatile("cp.async.wait_group 0;"  ::: "memory")

#define ALO2  34816
#define SM_G  69632
#define APAD 72
#define BPAD 80
#define AH_OFF 0
#define AL_OFF 18432
#define BH_OFF 36864
#define BL_OFF 57344
#define SM_P 77824

// ---------------- one-time setup ----------------
__global__ void k_setup(const float* __restrict__ m0, const float* __restrict__ m1,
                        const float* __restrict__ m2, const float* __restrict__ m3,
                        const float* __restrict__ e0, const float* __restrict__ e1,
                        const float* __restrict__ e2, const float* __restrict__ e3,
                        const float* __restrict__ wfin,
                        const float* __restrict__ scalars, const int* __restrict__ nobj,
                        const float* __restrict__ w_in) {
    int blk = blockIdx.x, tid = threadIdx.x;
    if (blk < 52) {
        int mat = blk >> 2, quar = blk & 3;
        const float* W;
        if (mat < 4)       W = (mat==0)?m0:(mat==1)?m1:(mat==2)?m2:m3;
        else if (mat < 12) {
            int l = (mat-4)>>1, wh = (mat-4)&1;
            const float* E = (l==0)?e0:(l==1)?e1:(l==2)?e2:e3;
            W = E + wh*16384;
        } else W = wfin;
        uint4* dst = g_Bf + mat*4096;
        for (int e = quar*1024 + tid; e < quar*1024 + 1024; e += 256) {
            int lane = e&31, nt = (e>>5)&7, ks = (e>>8)&7, wx = e>>11;
            int n = wx*64 + nt*8 + (lane>>2);
            int k0 = ks*16 + (lane&3)*2;
            __nv_bfloat16 h00,l00,h01,l01,h10,l10,h11,l11;
            split2(W[k0*128+n],     h00, l00);
            split2(W[(k0+1)*128+n], h01, l01);
            split2(W[(k0+8)*128+n], h10, l10);
            split2(W[(k0+9)*128+n], h11, l11);
            uint4 o;
            o.x = packbf(h00,h01); o.y = packbf(h10,h11);
            o.z = packbf(l00,l01); o.w = packbf(l10,l11);
            dst[e] = o;
        }
    } else if (blk < 100) {
        int idx = blk - 52;
        int unit = idx >> 2, quar = idx & 3;
        int l = unit / 3, p = unit % 3;
        const int tbl[3][3] = {{3,5,7},{4,6,8},{2,9,10}};
        const float* E = (l==0)?e0:(l==1)?e1:(l==2)?e2:e3;
        __nv_bfloat16* Hi = g_WpHi + (size_t)l*147456 + p*49152;
        __nv_bfloat16* Lo = g_WpLo + (size_t)l*147456 + p*49152;
        for (int e = quar*12288 + tid; e < quar*12288 + 12288; e += 256) {
            int n = e / 384, k = e % 384;
            int mat = tbl[p][k>>7], kk = k&127;
            __nv_bfloat16 h, lo;
            split2(E[(mat*C_ + kk)*C_ + n], h, lo);
            Hi[n*384 + k] = h; Lo[n*384 + k] = lo;
        }
    } else {
        int b = blk - 100;
        __shared__ float xs[N_][S_];
        __shared__ float ssum[S_];
        int nb = nobj[b];
        for (int idx = tid; idx < N_*S_; idx += 256) {
            int n = idx/S_, s = idx%S_;
            xs[n][s] = (n < nb) ? scalars[(b*N_+n)*S_+s] : 0.f;
        }
        __syncthreads();
        if (tid < S_) {
            float a = 0.f;
            for (int n = 0; n < N_; n++) a += xs[n][tid];
            ssum[tid] = a / AVGF;
        }
        __syncthreads();
        for (int idx = tid; idx < N_*CS_; idx += 256) {
            int n = idx/CS_, c = idx%CS_;
            float a0=0, a1=0, a2=0;
            #pragma unroll
            for (int s = 0; s < S_; s++) {
                float xv = xs[n][s];
                a0 += xv*w_in[(0*S_+s)*CS_+c];
                a1 += xv*w_in[(1*S_+s)*CS_+c];
                a2 += xv*w_in[(2*S_+s)*CS_+c];
            }
            g_y012[((b*N_+n)*3+0)*CS_+c] = a0;
            g_y012[((b*N_+n)*3+1)*CS_+c] = a1;
            g_y012[((b*N_+n)*3+2)*CS_+c] = a2;
        }
        if (tid < 2*CS_) {
            int k = tid/CS_, c = tid%CS_;
            float a = 0.f;
            #pragma unroll
            for (int s = 0; s < S_; s++) a += ssum[s]*w_in[((3+k)*S_+s)*CS_+c];
            g_y34[(b*2+k)*CS_+c] = a;
        }
    }
}

// ---------------- helpers shared by GEMM kernels ----------------
struct GemmCtx {
    uint32_t sb;
    int tid, wid, lane, tile, b, i0, nb;
    int wy, wx, rb, nb0, lrow, lcolb, g, t2;
};
__device__ __forceinline__ void stage_src(const GemmCtx& X, const __nv_bfloat16* Ahi,
                                          const __nv_bfloat16* Alo, bool transp) {
    #pragma unroll
    for (int uu = 0; uu < 16; uu++) {
        int group = uu>>3, comp = (uu>>2)&1, sub = uu&3;
        int f = X.tid + 256*(comp*8 + group*4 + sub);
        int idx = f & 2047;
        int row = (idx>>3)&127, c8 = idx&7, c16 = group*8 + c8;
        const __nv_bfloat16* basep = comp ? Alo : Ahi;
        size_t goff;
        if (!transp) {
            goff = (size_t)X.tile*16384 + row*128 + c16*8;
        } else {
            int jj = row&63, hh = row>>6;
            goff = ((size_t)(X.b*32 + (jj>>1))*128 + (jj&1)*64 + X.i0 + hh)*128 + c16*8;
        }
        uint32_t dst = X.sb + comp*ALO2 + row*272 + c16*16;
        CPA16(dst, basep + goff);
        if (uu == 7) CPCOMMIT();
    }
    CPCOMMIT();
}
__device__ __forceinline__ void compute_pass(const GemmCtx& X, const uint4* Fw,
                                             float c[2][8][4], bool staged) {
    #pragma unroll
    for (int half = 0; half < 2; half++) {
        if (staged) { if (half == 0) CPWAIT1(); else CPWAIT(); __syncthreads(); }
        #pragma unroll
        for (int ks = half*4; ks < half*4+4; ks++) {
            uint32_t ah[2][4], al[2][4];
            #pragma unroll
            for (int mt = 0; mt < 2; mt++) {
                uint32_t adr = X.sb + (X.rb + mt*16 + X.lrow)*272 + ks*32 + X.lcolb;
                ldmx4(adr, ah[mt][0], ah[mt][1], ah[mt][2], ah[mt][3]);
                adr += ALO2;
                ldmx4(adr, al[mt][0], al[mt][1], al[mt][2], al[mt][3]);
            }
            uint4 f4 = Fw[(ks*8)*32 + X.lane];
            #pragma unroll
            for (int nt = 0; nt < 8; nt++) {
                uint4 cur = f4;
                if (nt < 7) f4 = Fw[(ks*8 + nt + 1)*32 + X.lane];
                #pragma unroll
                for (int mt = 0; mt < 2; mt++) {
                    mma16816(c[mt][nt], ah[mt], cur.x, cur.y);
                    mma16816(c[mt][nt], ah[mt], cur.z, cur.w);
                    mma16816(c[mt][nt], al[mt], cur.x, cur.y);
                }
            }
        }
    }
}
__device__ __forceinline__ void init_ctx(GemmCtx& X, unsigned char* sm) {
    X.sb = smem_u32(sm);
    X.tid = threadIdx.x; X.wid = X.tid>>5; X.lane = X.tid&31;
    X.tile = blockIdx.x; X.b = X.tile>>5; X.i0 = (X.tile&31)<<1;
    X.wy = X.wid&3; X.wx = X.wid>>2;
    X.rb = X.wy*32; X.nb0 = X.wx*64;
    X.lrow = (X.lane&7) + ((X.lane>>3)&1)*8;
    X.lcolb = ((X.lane>>4)&1)*16;
    X.g = X.lane>>2; X.t2 = (X.lane&3)*2;
}
#define ZEROC(c) { _Pragma("unroll") for (int mt=0;mt<2;mt++) _Pragma("unroll") for (int nt=0;nt<8;nt++) _Pragma("unroll") for (int q=0;q<4;q++) c[mt][nt][q]=0.f; }

// ---------------- standalone mode-0 GEMM: U = lrelu(A@W + b)*mask ----------------
__global__ void __launch_bounds__(256, 2) k_gemm0(const __nv_bfloat16* __restrict__ Ahi,
                                                  const __nv_bfloat16* __restrict__ Alo,
                                                  const uint4* __restrict__ F,
                                                  const float* __restrict__ bias,
                                                  const int* __restrict__ nobj,
                                                  __nv_bfloat16* __restrict__ OutHi,
                                                  __nv_bfloat16* __restrict__ OutLo) {
    extern __shared__ unsigned char sm[];
    GemmCtx X; init_ctx(X, sm);
    X.nb = nobj[X.b];
    if (X.i0 >= X.nb) return;
    float c[2][8][4]; ZEROC(c);
    stage_src(X, Ahi, Alo, false);
    compute_pass(X, F + X.wx*2048, c, true);
    __nv_bfloat16* Hi = OutHi + (size_t)X.tile*16384;
    __nv_bfloat16* Lo = OutLo + (size_t)X.tile*16384;
    #pragma unroll
    for (int mt = 0; mt < 2; mt++)
        #pragma unroll
        for (int h = 0; h < 2; h++) {
            int row = X.rb + mt*16 + X.g + h*8;
            int i = X.i0 + (row>>6), j = row&63;
            float mask = (i < X.nb && j < X.nb) ? 1.f : 0.f;
            #pragma unroll
            for (int nt = 0; nt < 8; nt++) {
                int col = X.nb0 + nt*8 + X.t2;
                float vx = lrelu(c[mt][nt][h*2+0] + bias[col])   * mask;
                float vy = lrelu(c[mt][nt][h*2+1] + bias[col+1]) * mask;
                __nv_bfloat16 hx,lx,hy,ly;
                split2(vx, hx, lx); split2(vy, hy, ly);
                *(uint32_t*)(Hi + row*128 + col) = packbf(hx, hy);
                *(uint32_t*)(Lo + row*128 + col) = packbf(lx, ly);
            }
        }
}

// ---------------- fused GEMM: Eq2to2 dual (U@W0 + UT@W1 + combine) -> T (smem) ->
//                  next GEMM (T@F2): mode2=0 writes U_next, mode2=3 final reduce ------
__global__ void __launch_bounds__(256, 2) k_gemm2(const __nv_bfloat16* __restrict__ Uhi,
                                                  const __nv_bfloat16* __restrict__ Ulo,
                                                  const uint4* __restrict__ F0,
                                                  const uint4* __restrict__ F1,
                                                  const uint4* __restrict__ F2,
                                                  const float* __restrict__ bias2,
                                                  const int* __restrict__ nobj, int mode2,
                                                  __nv_bfloat16* __restrict__ OutHi,
                                                  __nv_bfloat16* __restrict__ OutLo) {
    extern __shared__ unsigned char sm[];
    GemmCtx X; init_ctx(X, sm);
    X.nb = nobj[X.b];
    if (X.i0 >= X.nb) return;
    float c[2][8][4]; ZEROC(c);
    // pass 1: U @ W0
    stage_src(X, Uhi, Ulo, false);
    compute_pass(X, F0 + X.wx*2048, c, true);
    // pass 2: UT @ W1
    __syncthreads();
    stage_src(X, Uhi, Ulo, true);
    compute_pass(X, F1 + X.wx*2048, c, true);
    // Eq2to2 combine -> T in smem A buffers
    __syncthreads();
    #pragma unroll
    for (int mt = 0; mt < 2; mt++)
        #pragma unroll
        for (int h = 0; h < 2; h++) {
            int row = X.rb + mt*16 + X.g + h*8;
            int i = X.i0 + (row>>6), j = row&63;
            float mask = (i < X.nb && j < X.nb) ? 1.f : 0.f;
            bool diag = (i == j);
            const float* vr = g_Vrow + (X.b*64+i)*C_;
            const float* vc = g_Vcol + (X.b*64+j)*C_;
            const float* gg = g_G + X.b*C_;
            const float* dd = g_Dd + (X.b*64+i)*C_;
            const float* ee = g_E + X.b*C_;
            #pragma unroll
            for (int nt = 0; nt < 8; nt++) {
                int col = X.nb0 + nt*8 + X.t2;
                float vx = c[mt][nt][h*2+0] + vr[col]   + gg[col]   + vc[col];
                float vy = c[mt][nt][h*2+1] + vr[col+1] + gg[col+1] + vc[col+1];
                if (diag) { vx += dd[col] + ee[col]; vy += dd[col+1] + ee[col+1]; }
                vx = lrelu(vx) * mask;
                vy = lrelu(vy) * mask;
                __nv_bfloat16 hx,lx,hy,ly;
                split2(vx, hx, lx); split2(vy, hy, ly);
                *(uint32_t*)(sm + row*272 + col*2)        = packbf(hx, hy);
                *(uint32_t*)(sm + ALO2 + row*272 + col*2) = packbf(lx, ly);
            }
        }
    __syncthreads();
    // pass 3: T @ F2 (no staging, T already in smem)
    ZEROC(c);
    compute_pass(X, F2 + X.wx*2048, c, false);
    if (mode2 == 0) {
        __nv_bfloat16* Hi = OutHi + (size_t)X.tile*16384;
        __nv_bfloat16* Lo = OutLo + (size_t)X.tile*16384;
        #pragma unroll
        for (int mt = 0; mt < 2; mt++)
            #pragma unroll
            for (int h = 0; h < 2; h++) {
                int row = X.rb + mt*16 + X.g + h*8;
                int i = X.i0 + (row>>6), j = row&63;
                float mask = (i < X.nb && j < X.nb) ? 1.f : 0.f;
                #pragma unroll
                for (int nt = 0; nt < 8; nt++) {
                    int col = X.nb0 + nt*8 + X.t2;
                    float vx = lrelu(c[mt][nt][h*2+0] + bias2[col])   * mask;
                    float vy = lrelu(c[mt][nt][h*2+1] + bias2[col+1]) * mask;
                    __nv_bfloat16 hx,lx,hy,ly;
                    split2(vx, hx, lx); split2(vy, hy, ly);
                    *(uint32_t*)(Hi + row*128 + col) = packbf(hx, hy);
                    *(uint32_t*)(Lo + row*128 + col) = packbf(lx, ly);
                }
            }
    } else {
        __syncthreads();
        float* Vs = (float*)sm;   // [128][132]
        #pragma unroll
        for (int mt = 0; mt < 2; mt++)
            #pragma unroll
            for (int h = 0; h < 2; h++) {
                int row = X.rb + mt*16 + X.g + h*8;
                int i = X.i0 + (row>>6), j = row&63;
                float mask = (i < X.nb && j < X.nb) ? 1.f : 0.f;
                #pragma unroll
                for (int nt = 0; nt < 8; nt++) {
                    int col = X.nb0 + nt*8 + X.t2;
                    float2 v;
                    v.x = lrelu(c[mt][nt][h*2+0] + bias2[col])   * mask;
                    v.y = lrelu(c[mt][nt][h*2+1] + bias2[col+1]) * mask;
                    *(float2*)(Vs + row*132 + col) = v;
                }
            }
        __syncthreads();
        if (X.tid < 128) {
            float s = 0.f;
            #pragma unroll 8
            for (int r = 0; r < 128; r++) s += Vs[r*132 + X.tid];
            atomicAdd(&g_tot[X.b*C_ + X.tid], s);
            float dgv = Vs[X.i0*132 + X.tid] + Vs[(64 + X.i0 + 1)*132 + X.tid];
            atomicAdd(&g_dg[X.b*C_ + X.tid], dgv);
        }
    }
}

// ---------------- projection GEMM + fused G/E ----------------
__global__ void __launch_bounds__(256, 2) k_proj(const __nv_bfloat16* __restrict__ Bhi,
                                                 const __nv_bfloat16* __restrict__ Blo,
                                                 const float* __restrict__ W,
                                                 const float* __restrict__ eqb,
                                                 const float* __restrict__ eqbd,
                                                 const int* __restrict__ nobj) {
    extern __shared__ unsigned char sm[];
    if (blockIdx.x >= 48) {
        int b = blockIdx.x - 48, d = threadIdx.x;
        float* tt = (float*)sm;
        float* tg = (float*)sm + 128;
        if (d < 128) {
            int nb = nobj[b];
            float t = 0.f, tr = 0.f;
            for (int i = 0; i < nb; i++) {
                size_t m = (size_t)(b*N_+i);
                t  += g_X[m*384 + 128 + d];
                tr += g_X[m*384 + d];
            }
            tt[d] = t / AVGF; tg[d] = tr / AVGF;
        }
        __syncthreads();
        if (d < 128) {
            float g = eqb[d], e = eqbd[d];
            for (int c = 0; c < C_; c++) {
                g += tt[c]*W[(11*C_+c)*C_+d] + tg[c]*W[(13*C_+c)*C_+d];
                e += tt[c]*W[(12*C_+c)*C_+d] + tg[c]*W[(14*C_+c)*C_+d];
            }
            g_G[b*C_+d] = g; g_E[b*C_+d] = e;
        }
        return;
    }
    uint32_t sb = smem_u32(sm);
    int tid = threadIdx.x, wid = tid>>5, lane = tid&31;
    int p = blockIdx.x >> 4, tile = blockIdx.x & 15;
    int wy = wid&3, wx = wid>>2;
    int rb = wy*32, nb0 = wx*64;
    float c[2][8][4]; ZEROC(c);
    int lrow = (lane&7) + ((lane>>3)&1)*8;
    int lcolb = ((lane>>4)&1)*16;
    int bn = nb0 + (lane>>2);
    int btid4 = (lane&3)*4;
    const uint32_t* bhp = (const uint32_t*)(Bhi + p*49152);
    const uint32_t* blp = (const uint32_t*)(Blo + p*49152);
    const float4* Ag = (const float4*)(g_X + (size_t)tile*128*384);
    for (int ph = 0; ph < 6; ph++) {
        if (ph) __syncthreads();
        #pragma unroll
        for (int u = 0; u < 8; u++) {
            int f = tid + 256*u;
            int row = f>>4, q = f&15, c4 = q*4;
            float4 v = Ag[row*96 + ph*16 + q];
            __nv_bfloat16 h[4], l[4];
            split2(v.x, h[0], l[0]); split2(v.y, h[1], l[1]);
            split2(v.z, h[2], l[2]); split2(v.w, h[3], l[3]);
            *(uint2*)(sm + AH_OFF + (row*APAD + c4)*2) = *(uint2*)h;
            *(uint2*)(sm + AL_OFF + (row*APAD + c4)*2) = *(uint2*)l;
        }
        #pragma unroll
        for (int u = 0; u < 16; u++) {
            int f = tid + 256*u;
            int n = f>>5, kp = f&31;
            int k = kp*2;
            int col = (k & ~15) + (((k>>1)&3)<<2) + (((k>>3)&1)<<1);
            *(uint32_t*)(sm + BH_OFF + (n*BPAD + col)*2) = bhp[n*192 + ph*32 + kp];
            *(uint32_t*)(sm + BL_OFF + (n*BPAD + col)*2) = blp[n*192 + ph*32 + kp];
        }
        __syncthreads();
        #pragma unroll
        for (int ks = 0; ks < 4; ks++) {
            uint32_t ah[2][4], al[2][4];
            #pragma unroll
            for (int mt = 0; mt < 2; mt++) {
                uint32_t adr = sb + AH_OFF + (rb + mt*16 + lrow)*APAD*2 + ks*32 + lcolb;
                ldmx4(adr, ah[mt][0], ah[mt][1], ah[mt][2], ah[mt][3]);
                adr = sb + AL_OFF + (rb + mt*16 + lrow)*APAD*2 + ks*32 + lcolb;
                ldmx4(adr, al[mt][0], al[mt][1], al[mt][2], al[mt][3]);
            }
            #pragma unroll
            for (int nt = 0; nt < 8; nt++) {
                uint32_t bh0, bh1, bl0, bl1;
                uint32_t badr = sb + BH_OFF + ((bn + nt*8)*BPAD + ks*16 + btid4)*2;
                asm volatile("ld.shared.v2.b32 {%0,%1}, [%2];" : "=r"(bh0), "=r"(bh1) : "r"(badr));
                badr = sb + BL_OFF + ((bn + nt*8)*BPAD + ks*16 + btid4)*2;
                asm volatile("ld.shared.v2.b32 {%0,%1}, [%2];" : "=r"(bl0), "=r"(bl1) : "r"(badr));
                #pragma unroll
                for (int mt = 0; mt < 2; mt++) {
                    mma16816(c[mt][nt], ah[mt], bh0, bh1);
                    mma16816(c[mt][nt], ah[mt], bl0, bl1);
                    mma16816(c[mt][nt], al[mt], bh0, bh1);
                }
            }
        }
    }
    float* Out = (p==0) ? g_Vrow : (p==1) ? g_Vcol : g_Dd;
    int g = lane>>2, t2 = (lane&3)*2;
    #pragma unroll
    for (int mt = 0; mt < 2; mt++)
        #pragma unroll
        for (int h = 0; h < 2; h++) {
            int row = rb + mt*16 + g + h*8;
            int m = tile*128 + row;
            #pragma unroll
            for (int nt = 0; nt < 8; nt++) {
                int col = nb0 + nt*8 + t2;
                float2 v;
                v.x = c[mt][nt][h*2+0];
                v.y = c[mt][nt][h*2+1];
                *(float2*)(Out + (size_t)m*128 + col) = v;
            }
        }
}

// ---------------- initial T ----------------
__global__ void k_init(const float* __restrict__ momenta, const int* __restrict__ nobj,
                       const float* __restrict__ w_lin, const float* __restrict__ alpha,
                       const float* __restrict__ b_in) {
    int b = blockIdx.x / N_, i = blockIdx.x % N_;
    int nb = nobj[b];
    if (i >= nb) return;
    int tid = threadIdx.x;
    int c = tid & 127, jh = tid >> 7;
    __shared__ float pm[N_][4];
    __shared__ float dij[N_];
    __shared__ float y1s[N_][CS_];
    __shared__ float y0r[CS_], y2r[CS_], y3s[CS_], y4s[CS_];
    if (tid < 256) pm[tid>>2][tid&3] = momenta[(b*N_)*4 + tid];
    for (int idx = tid; idx < N_*CS_; idx += 256) {
        int n = idx/CS_, cs = idx%CS_;
        y1s[n][cs] = g_y012[((b*N_+n)*3+1)*CS_+cs];
    }
    if (tid < CS_) {
        y0r[tid] = g_y012[((b*N_+i)*3+0)*CS_+tid];
        y2r[tid] = g_y012[((b*N_+i)*3+2)*CS_+tid];
    } else if (tid < 2*CS_) {
        y3s[tid-CS_] = g_y34[(b*2+0)*CS_+tid-CS_];
    } else if (tid < 3*CS_) {
        y4s[tid-2*CS_] = g_y34[(b*2+1)*CS_+tid-2*CS_];
    }
    __syncthreads();
    if (tid < N_)
        dij[tid] = pm[i][0]*pm[tid][0] - pm[i][1]*pm[tid][1]
                 - pm[i][2]*pm[tid][2] - pm[i][3]*pm[tid][3];
    __syncthreads();
    float base = 0.f, wl = 0.f, al = 0.f;
    if (c < CS_) base = y0r[c] + y3s[c] + b_in[c];
    else { wl = w_lin[c-CS_]; al = alpha[c-CS_]; }
    size_t rowbase = ((size_t)(b*32 + (i>>1))*128 + (i&1)*64)*128;
    for (int j = jh; j < N_; j += 2) {
        float mask = (j < nb) ? 1.f : 0.f;
        float v;
        if (c < CS_) {
            v = base + y1s[j][c];
            if (j == i) v += y2r[c] + y4s[c];
            v = lrelu(v) * mask;
        } else {
            float r = dij[j] * wl;
            v = al * copysignf(log1pf(fabsf(r)), r) * mask;
        }
        __nv_bfloat16 h, l;
        split2(v, h, l);
        g_Ahi[rowbase + j*128 + c] = h;
        g_Alo[rowbase + j*128 + c] = l;
    }
}

// ---------------- reductions: U -> X ----------------
__global__ void k_r1(const __nv_bfloat16* __restrict__ Uhi,
                     const __nv_bfloat16* __restrict__ Ulo,
                     const int* __restrict__ nobj) {
    int b = blockIdx.x >> 6, i = blockIdx.x & 63;
    if (i >= nobj[b]) return;
    int t = threadIdx.x;
    int g = t & 15, jg = t >> 4;
    __shared__ float redR[16][128], redC[16][128];
    float aR[8] = {0,0,0,0,0,0,0,0}, aC[8] = {0,0,0,0,0,0,0,0};
    #pragma unroll
    for (int jj = 0; jj < 4; jj++) {
        int j = jg*4 + jj;
        {
            size_t off = ((size_t)(b*32 + (i>>1))*128 + (i&1)*64 + j)*128 + g*8;
            uint4 h4 = *(const uint4*)(Uhi + off);
            uint4 l4 = *(const uint4*)(Ulo + off);
            const __nv_bfloat16 *hp = (const __nv_bfloat16*)&h4, *lp = (const __nv_bfloat16*)&l4;
            #pragma unroll
            for (int q = 0; q < 8; q++) aR[q] += __bfloat162float(hp[q]) + __bfloat162float(lp[q]);
        }
        {
            size_t off = ((size_t)(b*32 + (j>>1))*128 + (j&1)*64 + i)*128 + g*8;
            uint4 h4 = *(const uint4*)(Uhi + off);
            uint4 l4 = *(const uint4*)(Ulo + off);
            const __nv_bfloat16 *hp = (const __nv_bfloat16*)&h4, *lp = (const __nv_bfloat16*)&l4;
            #pragma unroll
            for (int q = 0; q < 8; q++) aC[q] += __bfloat162float(hp[q]) + __bfloat162float(lp[q]);
        }
    }
    #pragma unroll
    for (int q = 0; q < 8; q++) { redR[jg][g*8+q] = aR[q]; redC[jg][g*8+q] = aC[q]; }
    __syncthreads();
    size_t m = (size_t)(b*N_+i);
    if (t < 128) {
        float s = 0.f;
        #pragma unroll
        for (int r = 0; r < 16; r++) s += redR[r][t];
        g_X[m*384 + 128 + t] = s / AVGF;
    } else {
        int d = t - 128;
        float s = 0.f;
        #pragma unroll
        for (int r = 0; r < 16; r++) s += redC[r][d];
        g_X[m*384 + 256 + d] = s / AVGF;
    }
    if (t < 16) {
        size_t off = ((size_t)(b*32 + (i>>1))*128 + (i&1)*64 + i)*128 + t*8;
        uint4 h4 = *(const uint4*)(Uhi + off);
        uint4 l4 = *(const uint4*)(Ulo + off);
        const __nv_bfloat16 *hp = (const __nv_bfloat16*)&h4, *lp = (const __nv_bfloat16*)&l4;
        #pragma unroll
        for (int q = 0; q < 8; q++)
            g_X[m*384 + t*8 + q] = __bfloat162float(hp[q]) + __bfloat162float(lp[q]);
    }
}

// ---------------- output head (resets accumulators) ----------------
__global__ void k_out(const float* __restrict__ w20, const float* __restrict__ b20,
                      const float* __restrict__ wmlp, const float* __restrict__ bmlp,
                      float* __restrict__ out) {
    int b = blockIdx.x, d = threadIdx.x;
    __shared__ float a0[C_], a1[C_], act[C_];
    a0[d] = lrelu(g_dg[b*C_+d] / AVGF);
    a1[d] = lrelu(g_tot[b*C_+d] / (AVGF*AVGF));
    g_dg[b*C_+d] = 0.f;
    g_tot[b*C_+d] = 0.f;
    __syncthreads();
    float a = b20[d];
    for (int c = 0; c < C_; c++) a += a0[c]*w20[c*C_+d] + a1[c]*w20[(C_+c)*C_+d];
    act[d] = a;
    __syncthreads();
    if (d < 2) {
        float o = bmlp[d];
        for (int k = 0; k < C_; k++) o += act[k]*wmlp[k*2+d];
        out[b*2+d] = o;
    }
}

// ---------------- host ----------------
extern "C" void kernel_launch(void* const* d_in, const int* in_sizes, int n_in,
                              void* d_out, int out_size) {
    const float *momenta=0, *scalars=0, *w_lin=0, *alpha=0, *w_in=0, *b_in=0;
    const int* nobj=0;
    const float *msgw[4], *msgb[4], *eqw[4], *eqb[4], *eqbd[4];
    const float *wm0=0, *bm0=0, *w20=0, *b20=0, *wmlp=0, *bmlp=0;

    if (n_in >= 33 && in_sizes[0] == 8192) {
        momenta=(const float*)d_in[0]; scalars=(const float*)d_in[1]; nobj=(const int*)d_in[2];
        w_lin=(const float*)d_in[3]; alpha=(const float*)d_in[4]; w_in=(const float*)d_in[5];
        b_in=(const float*)d_in[6];
        for (int l = 0; l < 4; l++) {
            msgw[l]=(const float*)d_in[7+l];  msgb[l]=(const float*)d_in[11+l];
            eqw[l] =(const float*)d_in[15+l]; eqb[l] =(const float*)d_in[19+l];
            eqbd[l]=(const float*)d_in[23+l];
        }
        wm0=(const float*)d_in[27]; bm0=(const float*)d_in[28]; w20=(const float*)d_in[29];
        b20=(const float*)d_in[30]; wmlp=(const float*)d_in[31]; bmlp=(const float*)d_in[32];
    } else if (n_in >= 33) {
        alpha=(const float*)d_in[0]; b20=(const float*)d_in[1]; b_in=(const float*)d_in[2];
        bm0=(const float*)d_in[3]; bmlp=(const float*)d_in[4];
        for (int l = 0; l < 4; l++) {
            eqb[l] =(const float*)d_in[5+l];  eqbd[l]=(const float*)d_in[9+l];
            eqw[l] =(const float*)d_in[13+l]; msgb[l]=(const float*)d_in[18+l];
            msgw[l]=(const float*)d_in[22+l];
        }
        momenta=(const float*)d_in[17]; nobj=(const int*)d_in[26]; scalars=(const float*)d_in[27];
        w20=(const float*)d_in[28]; w_in=(const float*)d_in[29]; w_lin=(const float*)d_in[30];
        wm0=(const float*)d_in[31]; wmlp=(const float*)d_in[32];
    } else {
        momenta=(const float*)d_in[0]; scalars=(const float*)d_in[1]; nobj=(const int*)d_in[2];
        w_lin=(const float*)d_in[3]; alpha=(const float*)d_in[4]; w_in=(const float*)d_in[5];
        b_in=(const float*)d_in[6];
        for (int l = 0; l < 4; l++) {
            msgw[l]=(const float*)d_in[7]+(size_t)l*C_*C_;     msgb[l]=(const float*)d_in[8]+(size_t)l*C_;
            eqw[l] =(const float*)d_in[9]+(size_t)l*15*C_*C_;  eqb[l] =(const float*)d_in[10]+(size_t)l*C_;
            eqbd[l]=(const float*)d_in[11]+(size_t)l*C_;
        }
        wm0=(const float*)d_in[12]; bm0=(const float*)d_in[13]; w20=(const float*)d_in[14];
        b20=(const float*)d_in[15]; wmlp=(const float*)d_in[16]; bmlp=(const float*)d_in[17];
    }

    cudaFuncSetAttribute(k_gemm0, cudaFuncAttributeMaxDynamicSharedMemorySize, SM_G);
    cudaFuncSetAttribute(k_gemm2, cudaFuncAttributeMaxDynamicSharedMemorySize, SM_G);
    cudaFuncSetAttribute(k_proj,  cudaFuncAttributeMaxDynamicSharedMemorySize, SM_P);

    __nv_bfloat16 *Ahi=0, *Alo=0, *Bhi=0, *Blo=0, *WpH=0, *WpL=0;
    uint4* Bf=0;
    cudaGetSymbolAddress((void**)&Ahi, g_Ahi);
    cudaGetSymbolAddress((void**)&Alo, g_Alo);
    cudaGetSymbolAddress((void**)&Bhi, g_Bhi);
    cudaGetSymbolAddress((void**)&Blo, g_Blo);
    cudaGetSymbolAddress((void**)&Bf,  g_Bf);
    cudaGetSymbolAddress((void**)&WpH, g_WpHi);
    cudaGetSymbolAddress((void**)&WpL, g_WpLo);

    k_setup<<<132, 256>>>(msgw[0], msgw[1], msgw[2], msgw[3],
                          eqw[0], eqw[1], eqw[2], eqw[3], wm0,
                          scalars, nobj, w_in);
    k_init<<<B_*N_, 256>>>(momenta, nobj, w_lin, alpha, b_in);

    // T-init lives in A buffer; first MessageNet writes U0 into B buffer.
    k_gemm0<<<TILES, 256, SM_G>>>(Ahi, Alo, Bf + 0*4096, msgb[0], nobj, Bhi, Blo);

    // ping-pong: layer l reads cur, fused kernel writes next layer's U into other buffer
    __nv_bfloat16 *curHi = Bhi, *curLo = Blo, *nxtHi = Ahi, *nxtLo = Alo;
    for (int l = 0; l < 4; l++) {
        k_r1<<<B_*N_, 256>>>(curHi, curLo, nobj);
        k_proj<<<80, 256, SM_P>>>(WpH + (size_t)l*147456, WpL + (size_t)l*147456,
                                  eqw[l], eqb[l], eqbd[l], nobj);
        if (l < 3) {
            k_gemm2<<<TILES, 256, SM_G>>>(curHi, curLo,
                                          Bf + (4 + l*2)*4096, Bf + (5 + l*2)*4096,
                                          Bf + (l+1)*4096, msgb[l+1], nobj, 0,
                                          nxtHi, nxtLo);
            __nv_bfloat16* th = curHi; curHi = nxtHi; nxtHi = th;
            __nv_bfloat16* tl = curLo; curLo = nxtLo; nxtLo = tl;
        } else {
            k_gemm2<<<TILES, 256, SM_G>>>(curHi, curLo,
                                          Bf + (4 + l*2)*4096, Bf + (5 + l*2)*4096,
                                          Bf + 12*4096, bm0, nobj, 3,
                                          (__nv_bfloat16*)0, (__nv_bfloat16*)0);
        }
    }

    k_out<<<B_, 128>>>(w20, b20, wmlp, bmlp, (float*)d_out);
}